// round 2
// baseline (speedup 1.0000x reference)
#include <cuda_runtime.h>
#include <cuda_bf16.h>

// Problem constants
#define B_    4
#define T_    2048
#define D_    1024
#define H_    8
#define DH    128
#define TE_   2048
#define D2    2048            // 2*D
#define NROWS (B_*T_)         // 8192

// GEMM tiling
#define BM 128
#define BN 128
#define BK 8

#define SPLITS 16             // att split-K over T
#define KTS    8              // k-softmax split over T
#define FKS    8              // film GEMM split over K

// ---------------- scratch (device globals; no allocation allowed) ----------
__device__ __align__(128) float g_xn  [NROWS*D_];
__device__ __align__(128) float g_q   [NROWS*D_];
__device__ __align__(128) float g_k   [NROWS*D_];
__device__ __align__(128) float g_v   [NROWS*D_];
__device__ __align__(128) float g_y   [NROWS*D_];
__device__ __align__(128) float g_hh  [NROWS*D_];
__device__ __align__(128) float g_attp[SPLITS*B_*H_*DH*DH];
__device__ __align__(128) float g_att [B_*H_*DH*DH];
__device__ __align__(128) float g_filmp[FKS*B_*D2];
__device__ __align__(128) float g_film[B_*D2];
__device__ __align__(128) float g_gm  [KTS*B_*D_];
__device__ __align__(128) float g_gs  [KTS*B_*D_];
__device__ __align__(128) float g_cm  [B_*D_];
__device__ __align__(128) float g_cs  [B_*D_];

// ---------------- helpers ----------------
__device__ __forceinline__ void blockReduce2(float& a, float& b) {
    __shared__ float sa[8], sb[8];
    #pragma unroll
    for (int o = 16; o > 0; o >>= 1) {
        a += __shfl_xor_sync(0xffffffffu, a, o);
        b += __shfl_xor_sync(0xffffffffu, b, o);
    }
    int w = threadIdx.x >> 5, l = threadIdx.x & 31;
    if (l == 0) { sa[w] = a; sb[w] = b; }
    __syncthreads();
    if (threadIdx.x < 32) {
        a = (l < 8) ? sa[l] : 0.f;
        b = (l < 8) ? sb[l] : 0.f;
        #pragma unroll
        for (int o = 4; o > 0; o >>= 1) {
            a += __shfl_xor_sync(0xffffffffu, a, o);
            b += __shfl_xor_sync(0xffffffffu, b, o);
        }
        if (l == 0) { sa[0] = a; sb[0] = b; }
    }
    __syncthreads();
    a = sa[0]; b = sb[0];
}

__device__ __forceinline__ float silu_f(float x) {
    return x / (1.f + __expf(-x));
}

// ---------------- LayerNorm (pre-norm) ----------------
__global__ void ln_k(const float* __restrict__ x, const float* __restrict__ w,
                     const float* __restrict__ bb, float* __restrict__ o)
{
    long base = (long)blockIdx.x * D_;
    int t = threadIdx.x;                 // 256 threads, float4 each
    float4 v = *(const float4*)&x[base + t*4];
    float s  = v.x + v.y + v.z + v.w;
    float ss = v.x*v.x + v.y*v.y + v.z*v.z + v.w*v.w;
    blockReduce2(s, ss);
    float mean = s * (1.f/D_);
    float var  = ss * (1.f/D_) - mean*mean;
    float rs   = rsqrtf(var + 1e-5f);
    float4 w4 = *(const float4*)&w[t*4];
    float4 b4 = *(const float4*)&bb[t*4];
    float4 r;
    r.x = (v.x-mean)*rs*w4.x + b4.x;
    r.y = (v.y-mean)*rs*w4.y + b4.y;
    r.z = (v.z-mean)*rs*w4.z + b4.z;
    r.w = (v.w-mean)*rs*w4.w + b4.w;
    *(float4*)&o[base + t*4] = r;
}

// ---------------- LayerNorm2 + FiLM + SiLU ----------------
__global__ void ln2film_k(const float* __restrict__ y, const float* __restrict__ w,
                          const float* __restrict__ bb, const float* __restrict__ film,
                          float* __restrict__ o)
{
    long base = (long)blockIdx.x * D_;
    int b = blockIdx.x >> 11;            // row / T_
    int t = threadIdx.x;
    float4 v = *(const float4*)&y[base + t*4];
    float s  = v.x + v.y + v.z + v.w;
    float ss = v.x*v.x + v.y*v.y + v.z*v.z + v.w*v.w;
    blockReduce2(s, ss);
    float mean = s * (1.f/D_);
    float var  = ss * (1.f/D_) - mean*mean;
    float rs   = rsqrtf(var + 1e-5f);
    float4 w4 = *(const float4*)&w[t*4];
    float4 b4 = *(const float4*)&bb[t*4];
    float4 sc = *(const float4*)&film[(long)b*D2 + t*4];
    float4 sf = *(const float4*)&film[(long)b*D2 + D_ + t*4];
    float4 r; float h;
    h = ((v.x-mean)*rs*w4.x + b4.x)*(1.f+sc.x) + sf.x; r.x = silu_f(h);
    h = ((v.y-mean)*rs*w4.y + b4.y)*(1.f+sc.y) + sf.y; r.y = silu_f(h);
    h = ((v.z-mean)*rs*w4.z + b4.z)*(1.f+sc.z) + sf.z; r.z = silu_f(h);
    h = ((v.w-mean)*rs*w4.w + b4.w)*(1.f+sc.w) + sf.w; r.w = silu_f(h);
    *(float4*)&o[base + t*4] = r;
}

// ---------------- generic SGEMM with epilogues ----------------
// C[M,N] = A[M,K] @ B[K,N]; 128x128 tile, 8x8 per thread, double-buffered smem.
// blockIdx.z decomposed into (zb, zh) for per-(batch,head) GEMMs via strides.
static const int EPI_NONE  = 0;
static const int EPI_BIAS  = 1;
static const int EPI_KMASK = 2;
static const int EPI_VMASK = 3;
static const int EPI_RESID = 4;

template<int EPI>
__global__ void __launch_bounds__(256, 2)
sgemm_k(const float* __restrict__ A0, int lda, long sAb, long sAh,
        const float* __restrict__ B0, int ldb, long sBb, long sBh,
        float* __restrict__ C0, int ldc, long sCb, long sCh,
        int K, int zH,
        const float* __restrict__ bias,
        const float* __restrict__ msk,
        const float* __restrict__ resid, int ldr)
{
    __shared__ float As[2][BK][BM+4];
    __shared__ float Bs[2][BK][BN+4];

    int tid = threadIdx.x;
    int bz = blockIdx.z;
    int zb = bz / zH, zh = bz - zb*zH;

    const float* A  = A0 + (long)zb*sAb + (long)zh*sAh + (long)blockIdx.y*BM*lda;
    const float* Bp = B0 + (long)zb*sBb + (long)zh*sBh + blockIdx.x*BN;
    float*       C  = C0 + (long)zb*sCb + (long)zh*sCh + (long)blockIdx.y*BM*ldc + blockIdx.x*BN;

    int arow = tid >> 1;
    int acol = (tid & 1) * 4;
    int brow = tid >> 5;
    int bcol = (tid & 31) * 4;
    int tx = tid & 15;
    int ty = tid >> 4;

    float acc[8][8];
    #pragma unroll
    for (int i = 0; i < 8; i++)
        #pragma unroll
        for (int j = 0; j < 8; j++) acc[i][j] = 0.f;

    // prologue: load tile 0
    float4 a4 = *(const float4*)&A[(long)arow*lda + acol];
    float4 b4 = *(const float4*)&Bp[(long)brow*ldb + bcol];
    As[0][acol+0][arow] = a4.x; As[0][acol+1][arow] = a4.y;
    As[0][acol+2][arow] = a4.z; As[0][acol+3][arow] = a4.w;
    *(float4*)&Bs[0][brow][bcol] = b4;
    __syncthreads();

    int nk = K / BK;
    for (int kt = 0; kt < nk; kt++) {
        int buf = kt & 1;
        float4 na, nb;
        if (kt + 1 < nk) {
            na = *(const float4*)&A[(long)arow*lda + (kt+1)*BK + acol];
            nb = *(const float4*)&Bp[(long)((kt+1)*BK + brow)*ldb + bcol];
        }
        #pragma unroll
        for (int kk = 0; kk < BK; kk++) {
            float ar[8], br[8];
            *(float4*)&ar[0] = *(const float4*)&As[buf][kk][ty*4];
            *(float4*)&ar[4] = *(const float4*)&As[buf][kk][64 + ty*4];
            *(float4*)&br[0] = *(const float4*)&Bs[buf][kk][tx*4];
            *(float4*)&br[4] = *(const float4*)&Bs[buf][kk][64 + tx*4];
            #pragma unroll
            for (int i = 0; i < 8; i++)
                #pragma unroll
                for (int j = 0; j < 8; j++)
                    acc[i][j] += ar[i]*br[j];
        }
        if (kt + 1 < nk) {
            int nbuf = buf ^ 1;
            As[nbuf][acol+0][arow] = na.x; As[nbuf][acol+1][arow] = na.y;
            As[nbuf][acol+2][arow] = na.z; As[nbuf][acol+3][arow] = na.w;
            *(float4*)&Bs[nbuf][brow][bcol] = nb;
            __syncthreads();
        }
    }

    int m0 = blockIdx.y * BM;
    int n0 = blockIdx.x * BN;
    #pragma unroll
    for (int i = 0; i < 8; i++) {
        int ml = (i < 4) ? (ty*4 + i) : (64 + ty*4 + i - 4);
        int mg = m0 + ml;
        float rowk = 0.f, rowv = 1.f;
        if (EPI == EPI_KMASK) rowk = (1.0f - msk[mg]) * -1000000.0f;
        if (EPI == EPI_VMASK) rowv = msk[mg];
        #pragma unroll
        for (int j = 0; j < 8; j++) {
            int nl = (j < 4) ? (tx*4 + j) : (64 + tx*4 + j - 4);
            int ng = n0 + nl;
            float val = acc[i][j];
            if (EPI != EPI_NONE) val += bias[ng];
            if (EPI == EPI_KMASK) val += rowk;
            if (EPI == EPI_VMASK) val *= rowv;
            if (EPI == EPI_RESID) val += resid[(long)mg*ldr + ng];
            C[(long)ml*ldc + nl] = val;
        }
    }
}

// ---------------- q softmax over d_head (contiguous 128) ----------------
__global__ void qsoftmax_k(float* __restrict__ q)
{
    long base = (long)blockIdx.x * DH;
    int t = threadIdx.x;                 // 128 threads
    float v = q[base + t];
    __shared__ float sh[4];
    float m = v;
    #pragma unroll
    for (int o = 16; o > 0; o >>= 1) m = fmaxf(m, __shfl_xor_sync(0xffffffffu, m, o));
    if ((t & 31) == 0) sh[t >> 5] = m;
    __syncthreads();
    m = fmaxf(fmaxf(sh[0], sh[1]), fmaxf(sh[2], sh[3]));
    float e = __expf(v - m);
    float s = e;
    #pragma unroll
    for (int o = 16; o > 0; o >>= 1) s += __shfl_xor_sync(0xffffffffu, s, o);
    __syncthreads();
    if ((t & 31) == 0) sh[t >> 5] = s;
    __syncthreads();
    s = sh[0] + sh[1] + sh[2] + sh[3];
    q[base + t] = e / s;
}

// ---------------- k softmax over time (axis=1), split in 3 passes ----------
__global__ void ksm_pass1(const float* __restrict__ kq, float* __restrict__ gm,
                          float* __restrict__ gs)
{
    int d = blockIdx.x*256 + threadIdx.x;     // 0..1023
    int b = blockIdx.y;
    int sp = blockIdx.z;
    const float* p = kq + (long)b*T_*D_ + (long)sp*(T_/KTS)*D_ + d;
    float m = -1e30f, s = 0.f;
    for (int t = 0; t < T_/KTS; t++) {
        float vv = p[(long)t*D_];
        float nm = fmaxf(m, vv);
        s = s*__expf(m - nm) + __expf(vv - nm);
        m = nm;
    }
    int idx = (sp*B_ + b)*D_ + d;
    gm[idx] = m; gs[idx] = s;
}

__global__ void ksm_pass2(const float* __restrict__ gm, const float* __restrict__ gs,
                          float* __restrict__ cm, float* __restrict__ cs)
{
    int i = blockIdx.x*256 + threadIdx.x;     // b*D + d, total 4096
    float M = -1e30f;
    #pragma unroll
    for (int sp = 0; sp < KTS; sp++) M = fmaxf(M, gm[sp*B_*D_ + i]);
    float S = 0.f;
    #pragma unroll
    for (int sp = 0; sp < KTS; sp++) S += gs[sp*B_*D_ + i]*__expf(gm[sp*B_*D_ + i] - M);
    cm[i] = M; cs[i] = 1.f/S;
}

__global__ void ksm_pass3(float* __restrict__ kq, const float* __restrict__ cm,
                          const float* __restrict__ cs)
{
    int d = blockIdx.x*256 + threadIdx.x;
    int b = blockIdx.y, sp = blockIdx.z;
    float M = cm[b*D_ + d], inv = cs[b*D_ + d];
    float* p = kq + (long)b*T_*D_ + (long)sp*(T_/KTS)*D_ + d;
    for (int t = 0; t < T_/KTS; t++)
        p[(long)t*D_] = __expf(p[(long)t*D_] - M) * inv;
}

// ---------------- att = K^T V per (b,h), split over T with partials --------
__global__ void __launch_bounds__(256)
attpart_k(const float* __restrict__ kq, const float* __restrict__ vq,
          float* __restrict__ part)
{
    int s  = blockIdx.x;                  // split 0..SPLITS-1
    int bh = blockIdx.y;                  // 0..31
    int b = bh >> 3, h = bh & 7;
    int tid = threadIdx.x;
    long base = (long)b*T_*D_ + h*DH;
    int t0 = s * (T_/SPLITS);

    __shared__ float Ks[BK][DH+4];
    __shared__ float Vs[BK][DH+4];

    int r = tid >> 5, c = (tid & 31)*4;
    int tx = tid & 15, ty = tid >> 4;
    float acc[8][8];
    #pragma unroll
    for (int i = 0; i < 8; i++)
        #pragma unroll
        for (int j = 0; j < 8; j++) acc[i][j] = 0.f;

    for (int tt = t0; tt < t0 + T_/SPLITS; tt += BK) {
        float4 k4 = *(const float4*)&kq[base + (long)(tt + r)*D_ + c];
        float4 v4 = *(const float4*)&vq[base + (long)(tt + r)*D_ + c];
        __syncthreads();
        *(float4*)&Ks[r][c] = k4;
        *(float4*)&Vs[r][c] = v4;
        __syncthreads();
        #pragma unroll
        for (int kk = 0; kk < BK; kk++) {
            float ar[8], br[8];
            *(float4*)&ar[0] = *(const float4*)&Ks[kk][ty*4];
            *(float4*)&ar[4] = *(const float4*)&Ks[kk][64 + ty*4];
            *(float4*)&br[0] = *(const float4*)&Vs[kk][tx*4];
            *(float4*)&br[4] = *(const float4*)&Vs[kk][64 + tx*4];
            #pragma unroll
            for (int i = 0; i < 8; i++)
                #pragma unroll
                for (int j = 0; j < 8; j++)
                    acc[i][j] += ar[i]*br[j];
        }
    }
    float* P = part + ((long)s*(B_*H_) + bh)*(DH*DH);
    #pragma unroll
    for (int i = 0; i < 8; i++) {
        int ml = (i < 4) ? (ty*4 + i) : (64 + ty*4 + i - 4);
        #pragma unroll
        for (int j = 0; j < 8; j++) {
            int nl = (j < 4) ? (tx*4 + j) : (64 + tx*4 + j - 4);
            P[ml*DH + nl] = acc[i][j];
        }
    }
}

__global__ void attreduce_k(const float* __restrict__ part, float* __restrict__ att)
{
    int i = blockIdx.x*256 + threadIdx.x;   // 0 .. 32*16384-1
    float s = 0.f;
    #pragma unroll
    for (int sp = 0; sp < SPLITS; sp++)
        s += part[(long)sp*(B_*H_*DH*DH) + i];
    att[i] = s;
}

// ---------------- FiLM: silu(emb) @ W_emb + b_emb ----------------
__global__ void filmpart_k(const float* __restrict__ emb, const float* __restrict__ W,
                           float* __restrict__ part)
{
    int b = blockIdx.x;                  // 0..3
    int colBase = blockIdx.y*256;        // 8 chunks of 256 cols
    int kz = blockIdx.z;                 // 0..FKS-1
    __shared__ float se[256];
    int tid = threadIdx.x;
    float e = emb[(long)b*TE_ + kz*256 + tid];
    se[tid] = silu_f(e);
    __syncthreads();
    int col = colBase + tid;
    float acc = 0.f;
    const float* wp = W + (long)(kz*256)*D2 + col;
    #pragma unroll 8
    for (int k = 0; k < 256; k++) acc += se[k]*wp[(long)k*D2];
    part[((long)kz*B_ + b)*D2 + col] = acc;
}

__global__ void filmreduce_k(const float* __restrict__ part,
                             const float* __restrict__ b_emb,
                             float* __restrict__ film)
{
    int i = blockIdx.x*256 + threadIdx.x;  // b*2048+col, total 8192
    int col = i & (D2-1);
    int b = i >> 11;
    float s = b_emb[col];
    #pragma unroll
    for (int kz = 0; kz < FKS; kz++)
        s += part[((long)kz*B_ + b)*D2 + col];
    film[i] = s;
}

// ---------------- launch ----------------
extern "C" void kernel_launch(void* const* d_in, const int* in_sizes, int n_in,
                              void* d_out, int out_size)
{
    const float* x     = (const float*)d_in[0];
    const float* emb   = (const float*)d_in[1];
    const float* mask  = (const float*)d_in[2];
    // d_in[3] = num_head (int), fixed H_=8
    const float* ln_w  = (const float*)d_in[4];
    const float* ln_b  = (const float*)d_in[5];
    const float* Wq    = (const float*)d_in[6];
    const float* bq    = (const float*)d_in[7];
    const float* Wk    = (const float*)d_in[8];
    const float* bk    = (const float*)d_in[9];
    const float* Wv    = (const float*)d_in[10];
    const float* bv    = (const float*)d_in[11];
    const float* W_emb = (const float*)d_in[12];
    const float* b_emb = (const float*)d_in[13];
    const float* ln2_w = (const float*)d_in[14];
    const float* ln2_b = (const float*)d_in[15];
    const float* W_out = (const float*)d_in[16];
    const float* b_out = (const float*)d_in[17];
    float* out = (float*)d_out;

    float *xn, *q, *k, *v, *y, *hh, *attp, *att, *filmp, *film, *gm, *gs, *cm, *cs;
    cudaGetSymbolAddress((void**)&xn,   g_xn);
    cudaGetSymbolAddress((void**)&q,    g_q);
    cudaGetSymbolAddress((void**)&k,    g_k);
    cudaGetSymbolAddress((void**)&v,    g_v);
    cudaGetSymbolAddress((void**)&y,    g_y);
    cudaGetSymbolAddress((void**)&hh,   g_hh);
    cudaGetSymbolAddress((void**)&attp, g_attp);
    cudaGetSymbolAddress((void**)&att,  g_att);
    cudaGetSymbolAddress((void**)&filmp,g_filmp);
    cudaGetSymbolAddress((void**)&film, g_film);
    cudaGetSymbolAddress((void**)&gm,   g_gm);
    cudaGetSymbolAddress((void**)&gs,   g_gs);
    cudaGetSymbolAddress((void**)&cm,   g_cm);
    cudaGetSymbolAddress((void**)&cs,   g_cs);

    // 1) pre-norm
    ln_k<<<NROWS, 256>>>(x, ln_w, ln_b, xn);

    // 2) Q/K/V projections with fused epilogues
    dim3 g1(D_/BN, NROWS/BM, 1);
    sgemm_k<EPI_BIAS><<<g1, 256>>>(xn, D_, 0,0, Wq, D_, 0,0, q, D_, 0,0,
                                   D_, 1, bq, nullptr, nullptr, 0);
    sgemm_k<EPI_KMASK><<<g1, 256>>>(xn, D_, 0,0, Wk, D_, 0,0, k, D_, 0,0,
                                    D_, 1, bk, mask, nullptr, 0);
    sgemm_k<EPI_VMASK><<<g1, 256>>>(xn, D_, 0,0, Wv, D_, 0,0, v, D_, 0,0,
                                    D_, 1, bv, mask, nullptr, 0);

    // 3) feature-map softmaxes
    qsoftmax_k<<<NROWS*H_, 128>>>(q);
    ksm_pass1<<<dim3(D_/256, B_, KTS), 256>>>(k, gm, gs);
    ksm_pass2<<<(B_*D_)/256, 256>>>(gm, gs, cm, cs);
    ksm_pass3<<<dim3(D_/256, B_, KTS), 256>>>(k, cm, cs);

    // 4) att = K^T V per (b,h)  (split-K partials, deterministic reduce)
    attpart_k<<<dim3(SPLITS, B_*H_), 256>>>(k, v, attp);
    attreduce_k<<<(B_*H_*DH*DH)/256, 256>>>(attp, att);

    // 5) y = Q @ att per (b,h)
    sgemm_k<EPI_NONE><<<dim3(1, T_/BM, B_*H_), 256>>>(
        q, D_, (long)T_*D_, (long)DH,
        att, DH, (long)H_*DH*DH, (long)DH*DH,
        y, D_, (long)T_*D_, (long)DH,
        DH, H_, nullptr, nullptr, nullptr, 0);

    // 6) FiLM params from emb
    filmpart_k<<<dim3(B_, D2/256, FKS), 256>>>(emb, W_emb, filmp);
    filmreduce_k<<<(B_*D2)/256, 256>>>(filmp, b_emb, film);

    // 7) LN2 + FiLM + SiLU
    ln2film_k<<<NROWS, 256>>>(y, ln2_w, ln2_b, film, hh);

    // 8) out = x + hh @ W_out + b_out
    sgemm_k<EPI_RESID><<<g1, 256>>>(hh, D_, 0,0, W_out, D_, 0,0, out, D_, 0,0,
                                    D_, 1, b_out, nullptr, x, D_);
}

// round 5
// speedup vs baseline: 1.8118x; 1.8118x over previous
#include <cuda_runtime.h>
#include <cuda_bf16.h>
#include <cstdint>

// Problem constants
#define B_    4
#define T_    2048
#define D_    1024
#define H_    8
#define DH    128
#define TE_   2048
#define D2    2048
#define NROWS (B_*T_)         // 8192

// SIMT GEMM tiling (step 5 only)
#define BM 128
#define BN 128
#define BK 8

#define SPLITS 16
#define KTS    8
#define FKS    8

// HMMA GEMM config
#define KC    32              // bf16 K per chunk
#define ROWB  80              // padded smem row bytes (32*2 padded to 80; 5x16B -> conflict-free)
#define MATB  (128*ROWB)      // 10240 per matrix per stage
#define STGB  (4*MATB)        // Ah,Al,Bh,Bl
#define SMEM_HGEMM (2*STGB)   // double buffer: 81920

// ---------------- scratch (device globals) ----------------
__device__ __align__(128) float g_q   [NROWS*D_];
__device__ __align__(128) float g_k   [NROWS*D_];
__device__ __align__(128) float g_v   [NROWS*D_];
__device__ __align__(128) float g_y   [NROWS*D_];
__device__ __align__(128) __nv_bfloat16 g_xh[NROWS*D_];
__device__ __align__(128) __nv_bfloat16 g_xl[NROWS*D_];
__device__ __align__(128) __nv_bfloat16 g_wh[D_*D_];
__device__ __align__(128) __nv_bfloat16 g_wl[D_*D_];
__device__ __align__(128) float g_attp[SPLITS*B_*H_*DH*DH];
__device__ __align__(128) float g_att [B_*H_*DH*DH];
__device__ __align__(128) float g_filmp[FKS*B_*D2];
__device__ __align__(128) float g_film[B_*D2];
__device__ __align__(128) float g_gm  [KTS*B_*D_];
__device__ __align__(128) float g_gs  [KTS*B_*D_];
__device__ __align__(128) float g_cm  [B_*D_];
__device__ __align__(128) float g_cs  [B_*D_];

// ---------------- PTX helpers (base-ISA only) ----------------
__device__ __forceinline__ uint32_t smem_u32(const void* p) {
    uint32_t a;
    asm("{ .reg .u64 t; cvta.to.shared.u64 t, %1; cvt.u32.u64 %0, t; }" : "=r"(a) : "l"(p));
    return a;
}
__device__ __forceinline__ void cp16(uint32_t sa, const void* g) {
    asm volatile("cp.async.cg.shared.global [%0], [%1], 16;" :: "r"(sa), "l"(__cvta_generic_to_global(g)));
}
__device__ __forceinline__ void cp_commit() { asm volatile("cp.async.commit_group;" ::: "memory"); }
template<int N> __device__ __forceinline__ void cp_wait() { asm volatile("cp.async.wait_group %0;" :: "n"(N) : "memory"); }

__device__ __forceinline__ void lds_x4(uint32_t a[4], uint32_t addr) {
    asm volatile("ldmatrix.sync.aligned.m8n8.x4.shared.b16 {%0,%1,%2,%3}, [%4];"
        : "=r"(a[0]), "=r"(a[1]), "=r"(a[2]), "=r"(a[3]) : "r"(addr));
}
__device__ __forceinline__ void lds_x2(uint32_t b[2], uint32_t addr) {
    asm volatile("ldmatrix.sync.aligned.m8n8.x2.shared.b16 {%0,%1}, [%2];"
        : "=r"(b[0]), "=r"(b[1]) : "r"(addr));
}
__device__ __forceinline__ void mma16816(float d[4], const uint32_t a[4], const uint32_t b[2]) {
    asm volatile("mma.sync.aligned.m16n8k16.row.col.f32.bf16.bf16.f32 "
        "{%0,%1,%2,%3}, {%4,%5,%6,%7}, {%8,%9}, {%0,%1,%2,%3};"
        : "+f"(d[0]), "+f"(d[1]), "+f"(d[2]), "+f"(d[3])
        : "r"(a[0]), "r"(a[1]), "r"(a[2]), "r"(a[3]), "r"(b[0]), "r"(b[1]));
}

// ---------------- misc helpers ----------------
__device__ __forceinline__ void blockReduce2(float& a, float& b) {
    __shared__ float sa[8], sb[8];
    #pragma unroll
    for (int o = 16; o > 0; o >>= 1) {
        a += __shfl_xor_sync(0xffffffffu, a, o);
        b += __shfl_xor_sync(0xffffffffu, b, o);
    }
    int w = threadIdx.x >> 5, l = threadIdx.x & 31;
    if (l == 0) { sa[w] = a; sb[w] = b; }
    __syncthreads();
    if (threadIdx.x < 32) {
        a = (l < 8) ? sa[l] : 0.f;
        b = (l < 8) ? sb[l] : 0.f;
        #pragma unroll
        for (int o = 4; o > 0; o >>= 1) {
            a += __shfl_xor_sync(0xffffffffu, a, o);
            b += __shfl_xor_sync(0xffffffffu, b, o);
        }
        if (l == 0) { sa[0] = a; sb[0] = b; }
    }
    __syncthreads();
    a = sa[0]; b = sb[0];
}
__device__ __forceinline__ float silu_f(float x) { return x / (1.f + __expf(-x)); }

__device__ __forceinline__ void split_store(float v, __nv_bfloat16* h, __nv_bfloat16* l) {
    __nv_bfloat16 hv = __float2bfloat16(v);
    *h = hv;
    *l = __float2bfloat16(v - __bfloat162float(hv));
}

// ---------------- LayerNorm (pre-norm) -> bf16 hi/lo ----------------
__global__ void ln_k(const float* __restrict__ x, const float* __restrict__ w,
                     const float* __restrict__ bb,
                     __nv_bfloat16* __restrict__ oh, __nv_bfloat16* __restrict__ ol)
{
    long base = (long)blockIdx.x * D_;
    int t = threadIdx.x;
    float4 v = *(const float4*)&x[base + t*4];
    float s  = v.x + v.y + v.z + v.w;
    float ss = v.x*v.x + v.y*v.y + v.z*v.z + v.w*v.w;
    blockReduce2(s, ss);
    float mean = s * (1.f/D_);
    float var  = ss * (1.f/D_) - mean*mean;
    float rs   = rsqrtf(var + 1e-5f);
    float4 w4 = *(const float4*)&w[t*4];
    float4 b4 = *(const float4*)&bb[t*4];
    float r0 = (v.x-mean)*rs*w4.x + b4.x;
    float r1 = (v.y-mean)*rs*w4.y + b4.y;
    float r2 = (v.z-mean)*rs*w4.z + b4.z;
    float r3 = (v.w-mean)*rs*w4.w + b4.w;
    long o = base + t*4;
    split_store(r0, &oh[o+0], &ol[o+0]);
    split_store(r1, &oh[o+1], &ol[o+1]);
    split_store(r2, &oh[o+2], &ol[o+2]);
    split_store(r3, &oh[o+3], &ol[o+3]);
}

// ---------------- LayerNorm2 + FiLM + SiLU -> bf16 hi/lo ----------------
__global__ void ln2film_k(const float* __restrict__ y, const float* __restrict__ w,
                          const float* __restrict__ bb, const float* __restrict__ film,
                          __nv_bfloat16* __restrict__ oh, __nv_bfloat16* __restrict__ ol)
{
    long base = (long)blockIdx.x * D_;
    int b = blockIdx.x >> 11;
    int t = threadIdx.x;
    float4 v = *(const float4*)&y[base + t*4];
    float s  = v.x + v.y + v.z + v.w;
    float ss = v.x*v.x + v.y*v.y + v.z*v.z + v.w*v.w;
    blockReduce2(s, ss);
    float mean = s * (1.f/D_);
    float var  = ss * (1.f/D_) - mean*mean;
    float rs   = rsqrtf(var + 1e-5f);
    float4 w4 = *(const float4*)&w[t*4];
    float4 b4 = *(const float4*)&bb[t*4];
    float4 sc = *(const float4*)&film[(long)b*D2 + t*4];
    float4 sf = *(const float4*)&film[(long)b*D2 + D_ + t*4];
    float h0 = silu_f(((v.x-mean)*rs*w4.x + b4.x)*(1.f+sc.x) + sf.x);
    float h1 = silu_f(((v.y-mean)*rs*w4.y + b4.y)*(1.f+sc.y) + sf.y);
    float h2 = silu_f(((v.z-mean)*rs*w4.z + b4.z)*(1.f+sc.z) + sf.z);
    float h3 = silu_f(((v.w-mean)*rs*w4.w + b4.w)*(1.f+sc.w) + sf.w);
    long o = base + t*4;
    split_store(h0, &oh[o+0], &ol[o+0]);
    split_store(h1, &oh[o+1], &ol[o+1]);
    split_store(h2, &oh[o+2], &ol[o+2]);
    split_store(h3, &oh[o+3], &ol[o+3]);
}

// ---------------- weight transpose + bf16 split: W[K,N] -> Wt[N,K] ---------
__global__ void wconv_k(const float* __restrict__ W,
                        __nv_bfloat16* __restrict__ th, __nv_bfloat16* __restrict__ tl)
{
    __shared__ float tile[32][33];
    int n0 = blockIdx.x*32, k0 = blockIdx.y*32;
    int tx = threadIdx.x, ty0 = threadIdx.y;   // 32 x 8
    #pragma unroll
    for (int i = 0; i < 4; i++) {
        int ty = ty0 + i*8;
        tile[ty][tx] = W[(long)(k0+ty)*D_ + n0+tx];
    }
    __syncthreads();
    #pragma unroll
    for (int i = 0; i < 4; i++) {
        int ty = ty0 + i*8;
        float v = tile[tx][ty];                // = W[k0+tx][n0+ty]
        long o = (long)(n0+ty)*D_ + k0+tx;
        split_store(v, &th[o], &tl[o]);
    }
}

// ---------------- HMMA bf16x3 GEMM: C[M,N] = A[M,K] @ B^T ------------------
// A (hi/lo): [M,K] row-major bf16. B (hi/lo): [N,K] row-major bf16.
static constexpr int EPI_NONE  = 0;
static constexpr int EPI_BIAS  = 1;
static constexpr int EPI_KMASK = 2;
static constexpr int EPI_VMASK = 3;
static constexpr int EPI_RESID = 4;

template<int EPI>
__global__ void __launch_bounds__(256, 2)
hgemm_k(const __nv_bfloat16* __restrict__ Ah, const __nv_bfloat16* __restrict__ Al,
        const __nv_bfloat16* __restrict__ Bh, const __nv_bfloat16* __restrict__ Bl,
        float* __restrict__ C,
        const float* __restrict__ bias, const float* __restrict__ msk,
        const float* __restrict__ resid)
{
    extern __shared__ char smem[];
    uint32_t sb = smem_u32(smem);
    int tid = threadIdx.x, lane = tid & 31, wid = tid >> 5;
    int m0 = blockIdx.y * 128, n0 = blockIdx.x * 128;
    int wm0 = (wid >> 2) * 64;        // 2 warp-rows of 64
    int wn0 = (wid & 3) * 32;         // 4 warp-cols of 32
    const long Kd = D_;

    float acc[4][4][4];
    #pragma unroll
    for (int i = 0; i < 4; i++)
        #pragma unroll
        for (int j = 0; j < 4; j++)
            #pragma unroll
            for (int r = 0; r < 4; r++) acc[i][j][r] = 0.f;

    auto load_stage = [&](int s, int kc) {
        uint32_t st = sb + s * STGB;
        const __nv_bfloat16* gp[4] = {
            Ah + (long)m0 * Kd + kc, Al + (long)m0 * Kd + kc,
            Bh + (long)n0 * Kd + kc, Bl + (long)n0 * Kd + kc };
        #pragma unroll
        for (int t = 0; t < 4; t++) {
            #pragma unroll
            for (int i = 0; i < 2; i++) {
                int g = tid + i * 256;
                int r = g >> 2, c = g & 3;
                cp16(st + t*MATB + r*ROWB + c*16,
                     (const char*)gp[t] + (long)r * Kd * 2 + c*16);
            }
        }
        cp_commit();
    };

    load_stage(0, 0);
    load_stage(1, KC);
    int nk = Kd / KC;                 // 32

    for (int ch = 0; ch < nk; ch++) {
        if (ch == nk - 1) cp_wait<0>(); else cp_wait<1>();
        __syncthreads();
        uint32_t st = sb + (ch & 1) * STGB;

        #pragma unroll
        for (int ks = 0; ks < 2; ks++) {
            uint32_t bh[4][2], bl[4][2];
            #pragma unroll
            for (int ni = 0; ni < 4; ni++) {
                int rB = wn0 + ni*8 + (lane & 7);
                int cB = ks*16 + ((lane >> 3) & 1) * 8;
                uint32_t off = (uint32_t)(rB*ROWB + cB*2);
                lds_x2(bh[ni], st + 2*MATB + off);
                lds_x2(bl[ni], st + 3*MATB + off);
            }
            #pragma unroll
            for (int mi = 0; mi < 4; mi++) {
                int rA = wm0 + mi*16 + (lane & 15);
                int cA = ks*16 + (lane >> 4) * 8;
                uint32_t off = (uint32_t)(rA*ROWB + cA*2);
                uint32_t ah[4], al[4];
                lds_x4(ah, st + off);
                lds_x4(al, st + MATB + off);
                #pragma unroll
                for (int ni = 0; ni < 4; ni++) {
                    mma16816(acc[mi][ni], ah, bh[ni]);
                    mma16816(acc[mi][ni], ah, bl[ni]);
                    mma16816(acc[mi][ni], al, bh[ni]);
                }
            }
        }
        __syncthreads();
        if (ch + 2 < nk) load_stage(ch & 1, (ch + 2) * KC);
    }

    // epilogue: d0 (r,c) (r, c+1) (r+8, c) (r+8, c+1); r = lane/4, c = (lane%4)*2
    int gq = lane >> 2, tq = lane & 3;
    #pragma unroll
    for (int mi = 0; mi < 4; mi++) {
        #pragma unroll
        for (int half = 0; half < 2; half++) {
            int mg = m0 + wm0 + mi*16 + gq + half*8;
            float kadd = 0.f, vmul = 1.f;
            if (EPI == EPI_KMASK) kadd = (1.0f - msk[mg]) * -1000000.0f;
            if (EPI == EPI_VMASK) vmul = msk[mg];
            #pragma unroll
            for (int ni = 0; ni < 4; ni++) {
                int ng = n0 + wn0 + ni*8 + tq*2;
                #pragma unroll
                for (int e = 0; e < 2; e++) {
                    float val = acc[mi][ni][half*2 + e];
                    int ngc = ng + e;
                    if (EPI != EPI_NONE) val += bias[ngc];
                    if (EPI == EPI_KMASK) val += kadd;
                    if (EPI == EPI_VMASK) val *= vmul;
                    if (EPI == EPI_RESID) val += resid[(long)mg*D_ + ngc];
                    C[(long)mg*D_ + ngc] = val;
                }
            }
        }
    }
}

// ---------------- SIMT SGEMM (step 5: y = Q @ att) ----------------
template<int EPI>
__global__ void __launch_bounds__(256, 2)
sgemm_k(const float* __restrict__ A0, int lda, long sAb, long sAh,
        const float* __restrict__ B0, int ldb, long sBb, long sBh,
        float* __restrict__ C0, int ldc, long sCb, long sCh,
        int K, int zH,
        const float* __restrict__ bias,
        const float* __restrict__ msk,
        const float* __restrict__ resid, int ldr)
{
    __shared__ float As[2][BK][BM+4];
    __shared__ float Bs[2][BK][BN+4];

    int tid = threadIdx.x;
    int bz = blockIdx.z;
    int zb = bz / zH, zh = bz - zb*zH;

    const float* A  = A0 + (long)zb*sAb + (long)zh*sAh + (long)blockIdx.y*BM*lda;
    const float* Bp = B0 + (long)zb*sBb + (long)zh*sBh + blockIdx.x*BN;
    float*       C  = C0 + (long)zb*sCb + (long)zh*sCh + (long)blockIdx.y*BM*ldc + blockIdx.x*BN;

    int arow = tid >> 1;
    int acol = (tid & 1) * 4;
    int brow = tid >> 5;
    int bcol = (tid & 31) * 4;
    int tx = tid & 15;
    int ty = tid >> 4;

    float acc[8][8];
    #pragma unroll
    for (int i = 0; i < 8; i++)
        #pragma unroll
        for (int j = 0; j < 8; j++) acc[i][j] = 0.f;

    float4 a4 = *(const float4*)&A[(long)arow*lda + acol];
    float4 b4 = *(const float4*)&Bp[(long)brow*ldb + bcol];
    As[0][acol+0][arow] = a4.x; As[0][acol+1][arow] = a4.y;
    As[0][acol+2][arow] = a4.z; As[0][acol+3][arow] = a4.w;
    *(float4*)&Bs[0][brow][bcol] = b4;
    __syncthreads();

    int nk = K / BK;
    for (int kt = 0; kt < nk; kt++) {
        int buf = kt & 1;
        float4 na, nb;
        if (kt + 1 < nk) {
            na = *(const float4*)&A[(long)arow*lda + (kt+1)*BK + acol];
            nb = *(const float4*)&Bp[(long)((kt+1)*BK + brow)*ldb + bcol];
        }
        #pragma unroll
        for (int kk = 0; kk < BK; kk++) {
            float ar[8], br[8];
            *(float4*)&ar[0] = *(const float4*)&As[buf][kk][ty*4];
            *(float4*)&ar[4] = *(const float4*)&As[buf][kk][64 + ty*4];
            *(float4*)&br[0] = *(const float4*)&Bs[buf][kk][tx*4];
            *(float4*)&br[4] = *(const float4*)&Bs[buf][kk][64 + tx*4];
            #pragma unroll
            for (int i = 0; i < 8; i++)
                #pragma unroll
                for (int j = 0; j < 8; j++)
                    acc[i][j] += ar[i]*br[j];
        }
        if (kt + 1 < nk) {
            int nbuf = buf ^ 1;
            As[nbuf][acol+0][arow] = na.x; As[nbuf][acol+1][arow] = na.y;
            As[nbuf][acol+2][arow] = na.z; As[nbuf][acol+3][arow] = na.w;
            *(float4*)&Bs[nbuf][brow][bcol] = nb;
            __syncthreads();
        }
    }

    int m0 = blockIdx.y * BM;
    int n0 = blockIdx.x * BN;
    #pragma unroll
    for (int i = 0; i < 8; i++) {
        int ml = (i < 4) ? (ty*4 + i) : (64 + ty*4 + i - 4);
        int mg = m0 + ml;
        float rowk = 0.f, rowv = 1.f;
        if (EPI == EPI_KMASK) rowk = (1.0f - msk[mg]) * -1000000.0f;
        if (EPI == EPI_VMASK) rowv = msk[mg];
        #pragma unroll
        for (int j = 0; j < 8; j++) {
            int nl = (j < 4) ? (tx*4 + j) : (64 + tx*4 + j - 4);
            int ng = n0 + nl;
            float val = acc[i][j];
            if (EPI != EPI_NONE) val += bias[ng];
            if (EPI == EPI_KMASK) val += rowk;
            if (EPI == EPI_VMASK) val *= rowv;
            if (EPI == EPI_RESID) val += resid[(long)mg*ldr + ng];
            C[(long)ml*ldc + nl] = val;
        }
    }
}

// ---------------- q softmax over d_head ----------------
__global__ void qsoftmax_k(float* __restrict__ q)
{
    long base = (long)blockIdx.x * DH;
    int t = threadIdx.x;
    float v = q[base + t];
    __shared__ float sh[4];
    float m = v;
    #pragma unroll
    for (int o = 16; o > 0; o >>= 1) m = fmaxf(m, __shfl_xor_sync(0xffffffffu, m, o));
    if ((t & 31) == 0) sh[t >> 5] = m;
    __syncthreads();
    m = fmaxf(fmaxf(sh[0], sh[1]), fmaxf(sh[2], sh[3]));
    float e = __expf(v - m);
    float s = e;
    #pragma unroll
    for (int o = 16; o > 0; o >>= 1) s += __shfl_xor_sync(0xffffffffu, s, o);
    __syncthreads();
    if ((t & 31) == 0) sh[t >> 5] = s;
    __syncthreads();
    s = sh[0] + sh[1] + sh[2] + sh[3];
    q[base + t] = e / s;
}

// ---------------- k softmax over time ----------------
__global__ void ksm_pass1(const float* __restrict__ kq, float* __restrict__ gm,
                          float* __restrict__ gs)
{
    int d = blockIdx.x*256 + threadIdx.x;
    int b = blockIdx.y;
    int sp = blockIdx.z;
    const float* p = kq + (long)b*T_*D_ + (long)sp*(T_/KTS)*D_ + d;
    float m = -1e30f, s = 0.f;
    for (int t = 0; t < T_/KTS; t++) {
        float vv = p[(long)t*D_];
        float nm = fmaxf(m, vv);
        s = s*__expf(m - nm) + __expf(vv - nm);
        m = nm;
    }
    int idx = (sp*B_ + b)*D_ + d;
    gm[idx] = m; gs[idx] = s;
}

__global__ void ksm_pass2(const float* __restrict__ gm, const float* __restrict__ gs,
                          float* __restrict__ cm, float* __restrict__ cs)
{
    int i = blockIdx.x*256 + threadIdx.x;
    float M = -1e30f;
    #pragma unroll
    for (int sp = 0; sp < KTS; sp++) M = fmaxf(M, gm[sp*B_*D_ + i]);
    float S = 0.f;
    #pragma unroll
    for (int sp = 0; sp < KTS; sp++) S += gs[sp*B_*D_ + i]*__expf(gm[sp*B_*D_ + i] - M);
    cm[i] = M; cs[i] = 1.f/S;
}

__global__ void ksm_pass3(float* __restrict__ kq, const float* __restrict__ cm,
                          const float* __restrict__ cs)
{
    int d = blockIdx.x*256 + threadIdx.x;
    int b = blockIdx.y, sp = blockIdx.z;
    float M = cm[b*D_ + d], inv = cs[b*D_ + d];
    float* p = kq + (long)b*T_*D_ + (long)sp*(T_/KTS)*D_ + d;
    for (int t = 0; t < T_/KTS; t++)
        p[(long)t*D_] = __expf(p[(long)t*D_] - M) * inv;
}

// ---------------- att = K^T V per (b,h) ----------------
__global__ void __launch_bounds__(256)
attpart_k(const float* __restrict__ kq, const float* __restrict__ vq,
          float* __restrict__ part)
{
    int s  = blockIdx.x;
    int bh = blockIdx.y;
    int b = bh >> 3, h = bh & 7;
    int tid = threadIdx.x;
    long base = (long)b*T_*D_ + h*DH;
    int t0 = s * (T_/SPLITS);

    __shared__ float Ks[BK][DH+4];
    __shared__ float Vs[BK][DH+4];

    int r = tid >> 5, c = (tid & 31)*4;
    int tx = tid & 15, ty = tid >> 4;
    float acc[8][8];
    #pragma unroll
    for (int i = 0; i < 8; i++)
        #pragma unroll
        for (int j = 0; j < 8; j++) acc[i][j] = 0.f;

    for (int tt = t0; tt < t0 + T_/SPLITS; tt += BK) {
        float4 k4 = *(const float4*)&kq[base + (long)(tt + r)*D_ + c];
        float4 v4 = *(const float4*)&vq[base + (long)(tt + r)*D_ + c];
        __syncthreads();
        *(float4*)&Ks[r][c] = k4;
        *(float4*)&Vs[r][c] = v4;
        __syncthreads();
        #pragma unroll
        for (int kk = 0; kk < BK; kk++) {
            float ar[8], br[8];
            *(float4*)&ar[0] = *(const float4*)&Ks[kk][ty*4];
            *(float4*)&ar[4] = *(const float4*)&Ks[kk][64 + ty*4];
            *(float4*)&br[0] = *(const float4*)&Vs[kk][tx*4];
            *(float4*)&br[4] = *(const float4*)&Vs[kk][64 + tx*4];
            #pragma unroll
            for (int i = 0; i < 8; i++)
                #pragma unroll
                for (int j = 0; j < 8; j++)
                    acc[i][j] += ar[i]*br[j];
        }
    }
    float* P = part + ((long)s*(B_*H_) + bh)*(DH*DH);
    #pragma unroll
    for (int i = 0; i < 8; i++) {
        int ml = (i < 4) ? (ty*4 + i) : (64 + ty*4 + i - 4);
        #pragma unroll
        for (int j = 0; j < 8; j++) {
            int nl = (j < 4) ? (tx*4 + j) : (64 + tx*4 + j - 4);
            P[ml*DH + nl] = acc[i][j];
        }
    }
}

__global__ void attreduce_k(const float* __restrict__ part, float* __restrict__ att)
{
    int i = blockIdx.x*256 + threadIdx.x;
    float s = 0.f;
    #pragma unroll
    for (int sp = 0; sp < SPLITS; sp++)
        s += part[(long)sp*(B_*H_*DH*DH) + i];
    att[i] = s;
}

// ---------------- FiLM ----------------
__global__ void filmpart_k(const float* __restrict__ emb, const float* __restrict__ W,
                           float* __restrict__ part)
{
    int b = blockIdx.x;
    int colBase = blockIdx.y*256;
    int kz = blockIdx.z;
    __shared__ float se[256];
    int tid = threadIdx.x;
    float e = emb[(long)b*TE_ + kz*256 + tid];
    se[tid] = silu_f(e);
    __syncthreads();
    int col = colBase + tid;
    float acc = 0.f;
    const float* wp = W + (long)(kz*256)*D2 + col;
    #pragma unroll 8
    for (int k = 0; k < 256; k++) acc += se[k]*wp[(long)k*D2];
    part[((long)kz*B_ + b)*D2 + col] = acc;
}

__global__ void filmreduce_k(const float* __restrict__ part,
                             const float* __restrict__ b_emb,
                             float* __restrict__ film)
{
    int i = blockIdx.x*256 + threadIdx.x;
    int col = i & (D2-1);
    int b = i >> 11;
    float s = b_emb[col];
    #pragma unroll
    for (int kz = 0; kz < FKS; kz++)
        s += part[((long)kz*B_ + b)*D2 + col];
    film[i] = s;
}

// ---------------- launch ----------------
extern "C" void kernel_launch(void* const* d_in, const int* in_sizes, int n_in,
                              void* d_out, int out_size)
{
    const float* x     = (const float*)d_in[0];
    const float* emb   = (const float*)d_in[1];
    const float* mask  = (const float*)d_in[2];
    const float* ln_w  = (const float*)d_in[4];
    const float* ln_b  = (const float*)d_in[5];
    const float* Wq    = (const float*)d_in[6];
    const float* bq    = (const float*)d_in[7];
    const float* Wk    = (const float*)d_in[8];
    const float* bk    = (const float*)d_in[9];
    const float* Wv    = (const float*)d_in[10];
    const float* bv    = (const float*)d_in[11];
    const float* W_emb = (const float*)d_in[12];
    const float* b_emb = (const float*)d_in[13];
    const float* ln2_w = (const float*)d_in[14];
    const float* ln2_b = (const float*)d_in[15];
    const float* W_out = (const float*)d_in[16];
    const float* b_out = (const float*)d_in[17];
    float* out = (float*)d_out;

    float *q, *k, *v, *y, *attp, *att, *filmp, *film, *gm, *gs, *cm, *cs;
    __nv_bfloat16 *xh, *xl, *wh, *wl;
    cudaGetSymbolAddress((void**)&q,    g_q);
    cudaGetSymbolAddress((void**)&k,    g_k);
    cudaGetSymbolAddress((void**)&v,    g_v);
    cudaGetSymbolAddress((void**)&y,    g_y);
    cudaGetSymbolAddress((void**)&xh,   g_xh);
    cudaGetSymbolAddress((void**)&xl,   g_xl);
    cudaGetSymbolAddress((void**)&wh,   g_wh);
    cudaGetSymbolAddress((void**)&wl,   g_wl);
    cudaGetSymbolAddress((void**)&attp, g_attp);
    cudaGetSymbolAddress((void**)&att,  g_att);
    cudaGetSymbolAddress((void**)&filmp,g_filmp);
    cudaGetSymbolAddress((void**)&film, g_film);
    cudaGetSymbolAddress((void**)&gm,   g_gm);
    cudaGetSymbolAddress((void**)&gs,   g_gs);
    cudaGetSymbolAddress((void**)&cm,   g_cm);
    cudaGetSymbolAddress((void**)&cs,   g_cs);

    cudaFuncSetAttribute(hgemm_k<EPI_BIAS>,  cudaFuncAttributeMaxDynamicSharedMemorySize, SMEM_HGEMM);
    cudaFuncSetAttribute(hgemm_k<EPI_KMASK>, cudaFuncAttributeMaxDynamicSharedMemorySize, SMEM_HGEMM);
    cudaFuncSetAttribute(hgemm_k<EPI_VMASK>, cudaFuncAttributeMaxDynamicSharedMemorySize, SMEM_HGEMM);
    cudaFuncSetAttribute(hgemm_k<EPI_RESID>, cudaFuncAttributeMaxDynamicSharedMemorySize, SMEM_HGEMM);

    dim3 wgrid(32, 32), wblk(32, 8);
    dim3 tgrid(D_/128, NROWS/128);   // (8, 64)

    // 1) pre-norm -> bf16 hi/lo
    ln_k<<<NROWS, 256>>>(x, ln_w, ln_b, xh, xl);

    // 2) Q/K/V projections on HMMA tensor cores (bf16x3 split)
    wconv_k<<<wgrid, wblk>>>(Wq, wh, wl);
    hgemm_k<EPI_BIAS><<<tgrid, 256, SMEM_HGEMM>>>(xh, xl, wh, wl, q, bq, nullptr, nullptr);
    wconv_k<<<wgrid, wblk>>>(Wk, wh, wl);
    hgemm_k<EPI_KMASK><<<tgrid, 256, SMEM_HGEMM>>>(xh, xl, wh, wl, k, bk, mask, nullptr);
    wconv_k<<<wgrid, wblk>>>(Wv, wh, wl);
    hgemm_k<EPI_VMASK><<<tgrid, 256, SMEM_HGEMM>>>(xh, xl, wh, wl, v, bv, mask, nullptr);

    // 3) feature-map softmaxes
    qsoftmax_k<<<NROWS*H_, 128>>>(q);
    ksm_pass1<<<dim3(D_/256, B_, KTS), 256>>>(k, gm, gs);
    ksm_pass2<<<(B_*D_)/256, 256>>>(gm, gs, cm, cs);
    ksm_pass3<<<dim3(D_/256, B_, KTS), 256>>>(k, cm, cs);

    // 4) att = K^T V per (b,h)
    attpart_k<<<dim3(SPLITS, B_*H_), 256>>>(k, v, attp);
    attreduce_k<<<(B_*H_*DH*DH)/256, 256>>>(attp, att);

    // 5) y = Q @ att per (b,h) (SIMT; small)
    sgemm_k<EPI_NONE><<<dim3(1, T_/BM, B_*H_), 256>>>(
        q, D_, (long)T_*D_, (long)DH,
        att, DH, (long)H_*DH*DH, (long)DH*DH,
        y, D_, (long)T_*D_, (long)DH,
        DH, H_, nullptr, nullptr, nullptr, 0);

    // 6) FiLM params
    filmpart_k<<<dim3(B_, D2/256, FKS), 256>>>(emb, W_emb, filmp);
    filmreduce_k<<<(B_*D2)/256, 256>>>(filmp, b_emb, film);

    // 7) LN2 + FiLM + SiLU -> bf16 hi/lo (reuse xh/xl)
    ln2film_k<<<NROWS, 256>>>(y, ln2_w, ln2_b, film, xh, xl);

    // 8) out = x + hh @ W_out + b_out  (HMMA)
    wconv_k<<<wgrid, wblk>>>(W_out, wh, wl);
    hgemm_k<EPI_RESID><<<tgrid, 256, SMEM_HGEMM>>>(xh, xl, wh, wl, out, b_out, nullptr, x);
}

// round 6
// speedup vs baseline: 2.4311x; 1.3418x over previous
#include <cuda_runtime.h>
#include <cuda_bf16.h>
#include <cuda_fp16.h>
#include <cstdint>

// Problem constants
#define B_    4
#define T_    2048
#define D_    1024
#define H_    8
#define DH    128
#define TE_   2048
#define D2    2048
#define NROWS (B_*T_)         // 8192

// SIMT GEMM tiling (step 5 only)
#define BM 128
#define BN 128
#define BK 8

#define SPLITS 16
#define KTS    8
#define FKS    8

// HMMA GEMM config (fp16, weight-split 2-term)
#define KC    32              // fp16 K per chunk
#define ROWB  80              // padded smem row bytes (64B data + pad; 5x16B -> conflict-free)
#define MATB  (128*ROWB)      // 10240 per matrix per stage
#define STGB  (3*MATB)        // A, Bh, Bl
#define SMEM_HGEMM (2*STGB)   // double buffer: 61440

// ---------------- scratch (device globals) ----------------
__device__ __align__(128) float g_q   [NROWS*D_];
__device__ __align__(128) float g_k   [NROWS*D_];
__device__ __align__(128) float g_v   [NROWS*D_];
__device__ __align__(128) float g_y   [NROWS*D_];
__device__ __align__(128) __half g_xh[NROWS*D_];
__device__ __align__(128) __half g_wh[3*D_*D_];
__device__ __align__(128) __half g_wl[3*D_*D_];
__device__ __align__(128) float g_attp[SPLITS*B_*H_*DH*DH];
__device__ __align__(128) float g_att [B_*H_*DH*DH];
__device__ __align__(128) float g_filmp[FKS*B_*D2];
__device__ __align__(128) float g_film[B_*D2];
__device__ __align__(128) float g_gm  [KTS*B_*D_];
__device__ __align__(128) float g_gs  [KTS*B_*D_];
__device__ __align__(128) float g_cm  [B_*D_];
__device__ __align__(128) float g_cs  [B_*D_];

// ---------------- PTX helpers (base-ISA only) ----------------
__device__ __forceinline__ uint32_t smem_u32(const void* p) {
    uint32_t a;
    asm("{ .reg .u64 t; cvta.to.shared.u64 t, %1; cvt.u32.u64 %0, t; }" : "=r"(a) : "l"(p));
    return a;
}
__device__ __forceinline__ void cp16(uint32_t sa, const void* g) {
    asm volatile("cp.async.cg.shared.global [%0], [%1], 16;" :: "r"(sa), "l"(__cvta_generic_to_global(g)));
}
__device__ __forceinline__ void cp_commit() { asm volatile("cp.async.commit_group;" ::: "memory"); }
template<int N> __device__ __forceinline__ void cp_wait() { asm volatile("cp.async.wait_group %0;" :: "n"(N) : "memory"); }

__device__ __forceinline__ void lds_x4(uint32_t a[4], uint32_t addr) {
    asm volatile("ldmatrix.sync.aligned.m8n8.x4.shared.b16 {%0,%1,%2,%3}, [%4];"
        : "=r"(a[0]), "=r"(a[1]), "=r"(a[2]), "=r"(a[3]) : "r"(addr));
}
__device__ __forceinline__ void lds_x2(uint32_t b[2], uint32_t addr) {
    asm volatile("ldmatrix.sync.aligned.m8n8.x2.shared.b16 {%0,%1}, [%2];"
        : "=r"(b[0]), "=r"(b[1]) : "r"(addr));
}
__device__ __forceinline__ void mma16816(float d[4], const uint32_t a[4], const uint32_t b[2]) {
    asm volatile("mma.sync.aligned.m16n8k16.row.col.f32.f16.f16.f32 "
        "{%0,%1,%2,%3}, {%4,%5,%6,%7}, {%8,%9}, {%0,%1,%2,%3};"
        : "+f"(d[0]), "+f"(d[1]), "+f"(d[2]), "+f"(d[3])
        : "r"(a[0]), "r"(a[1]), "r"(a[2]), "r"(a[3]), "r"(b[0]), "r"(b[1]));
}

// ---------------- misc helpers ----------------
__device__ __forceinline__ void blockReduce2(float& a, float& b) {
    __shared__ float sa[8], sb[8];
    #pragma unroll
    for (int o = 16; o > 0; o >>= 1) {
        a += __shfl_xor_sync(0xffffffffu, a, o);
        b += __shfl_xor_sync(0xffffffffu, b, o);
    }
    int w = threadIdx.x >> 5, l = threadIdx.x & 31;
    if (l == 0) { sa[w] = a; sb[w] = b; }
    __syncthreads();
    if (threadIdx.x < 32) {
        a = (l < 8) ? sa[l] : 0.f;
        b = (l < 8) ? sb[l] : 0.f;
        #pragma unroll
        for (int o = 4; o > 0; o >>= 1) {
            a += __shfl_xor_sync(0xffffffffu, a, o);
            b += __shfl_xor_sync(0xffffffffu, b, o);
        }
        if (l == 0) { sa[0] = a; sb[0] = b; }
    }
    __syncthreads();
    a = sa[0]; b = sb[0];
}
__device__ __forceinline__ float silu_f(float x) { return x / (1.f + __expf(-x)); }

__device__ __forceinline__ void split_store_h(float v, __half* h, __half* l) {
    __half hv = __float2half(v);
    *h = hv;
    *l = __float2half(v - __half2float(hv));
}

// ---------------- LayerNorm (pre-norm) -> fp16 ----------------
__global__ void ln_k(const float* __restrict__ x, const float* __restrict__ w,
                     const float* __restrict__ bb, __half* __restrict__ oh)
{
    long base = (long)blockIdx.x * D_;
    int t = threadIdx.x;
    float4 v = *(const float4*)&x[base + t*4];
    float s  = v.x + v.y + v.z + v.w;
    float ss = v.x*v.x + v.y*v.y + v.z*v.z + v.w*v.w;
    blockReduce2(s, ss);
    float mean = s * (1.f/D_);
    float var  = ss * (1.f/D_) - mean*mean;
    float rs   = rsqrtf(var + 1e-5f);
    float4 w4 = *(const float4*)&w[t*4];
    float4 b4 = *(const float4*)&bb[t*4];
    long o = base + t*4;
    oh[o+0] = __float2half((v.x-mean)*rs*w4.x + b4.x);
    oh[o+1] = __float2half((v.y-mean)*rs*w4.y + b4.y);
    oh[o+2] = __float2half((v.z-mean)*rs*w4.z + b4.z);
    oh[o+3] = __float2half((v.w-mean)*rs*w4.w + b4.w);
}

// ---------------- LayerNorm2 + FiLM + SiLU -> fp16 ----------------
__global__ void ln2film_k(const float* __restrict__ y, const float* __restrict__ w,
                          const float* __restrict__ bb, const float* __restrict__ film,
                          __half* __restrict__ oh)
{
    long base = (long)blockIdx.x * D_;
    int b = blockIdx.x >> 11;
    int t = threadIdx.x;
    float4 v = *(const float4*)&y[base + t*4];
    float s  = v.x + v.y + v.z + v.w;
    float ss = v.x*v.x + v.y*v.y + v.z*v.z + v.w*v.w;
    blockReduce2(s, ss);
    float mean = s * (1.f/D_);
    float var  = ss * (1.f/D_) - mean*mean;
    float rs   = rsqrtf(var + 1e-5f);
    float4 w4 = *(const float4*)&w[t*4];
    float4 b4 = *(const float4*)&bb[t*4];
    float4 sc = *(const float4*)&film[(long)b*D2 + t*4];
    float4 sf = *(const float4*)&film[(long)b*D2 + D_ + t*4];
    long o = base + t*4;
    oh[o+0] = __float2half(silu_f(((v.x-mean)*rs*w4.x + b4.x)*(1.f+sc.x) + sf.x));
    oh[o+1] = __float2half(silu_f(((v.y-mean)*rs*w4.y + b4.y)*(1.f+sc.y) + sf.y));
    oh[o+2] = __float2half(silu_f(((v.z-mean)*rs*w4.z + b4.z)*(1.f+sc.z) + sf.z));
    oh[o+3] = __float2half(silu_f(((v.w-mean)*rs*w4.w + b4.w)*(1.f+sc.w) + sf.w));
}

// ---------------- weight transpose + fp16 split: W[K,N] -> Wt[N,K] ---------
__global__ void wconv_k(const float* __restrict__ W,
                        __half* __restrict__ th, __half* __restrict__ tl)
{
    __shared__ float tile[32][33];
    int n0 = blockIdx.x*32, k0 = blockIdx.y*32;
    int tx = threadIdx.x, ty0 = threadIdx.y;   // 32 x 8
    #pragma unroll
    for (int i = 0; i < 4; i++) {
        int ty = ty0 + i*8;
        tile[ty][tx] = W[(long)(k0+ty)*D_ + n0+tx];
    }
    __syncthreads();
    #pragma unroll
    for (int i = 0; i < 4; i++) {
        int ty = ty0 + i*8;
        float v = tile[tx][ty];                // = W[k0+tx][n0+ty]
        long o = (long)(n0+ty)*D_ + k0+tx;
        split_store_h(v, &th[o], &tl[o]);
    }
}

// ---------------- HMMA fp16 2-term GEMM: C = A @ (Bh+Bl)^T ------------------
// A: [M,K] fp16 row-major. Bh/Bl: [N,K] fp16 row-major (N up to 3072).
static constexpr int EPI_QKV   = 0;   // grid.x=24: sel 0=bias, 1=bias+kmask, 2=(..+bias)*mask
static constexpr int EPI_RESID = 1;   // grid.x=8:  + bias + residual
static constexpr int EPI_NONE  = 2;

template<int EPI>
__global__ void __launch_bounds__(256, 2)
hgemm_k(const __half* __restrict__ A, const __half* __restrict__ Bh,
        const __half* __restrict__ Bl,
        float* __restrict__ C0, float* __restrict__ C1, float* __restrict__ C2,
        const float* __restrict__ b0, const float* __restrict__ b1,
        const float* __restrict__ b2,
        const float* __restrict__ msk, const float* __restrict__ resid)
{
    extern __shared__ char smem[];
    uint32_t sb = smem_u32(smem);
    int tid = threadIdx.x, lane = tid & 31, wid = tid >> 5;
    int m0 = blockIdx.y * 128;
    int nblk = blockIdx.x;
    int n0g = nblk * 128;              // row offset into B (global N)
    int n0  = (nblk & 7) * 128;        // column offset into the selected C
    int sel = nblk >> 3;
    int wm0 = (wid >> 2) * 64;
    int wn0 = (wid & 3) * 32;
    const long Kd = D_;

    float acc[4][4][4];
    #pragma unroll
    for (int i = 0; i < 4; i++)
        #pragma unroll
        for (int j = 0; j < 4; j++)
            #pragma unroll
            for (int r = 0; r < 4; r++) acc[i][j][r] = 0.f;

    auto load_stage = [&](int s, int kc) {
        uint32_t st = sb + s * STGB;
        const __half* gp[3] = {
            A  + (long)m0  * Kd + kc,
            Bh + (long)n0g * Kd + kc,
            Bl + (long)n0g * Kd + kc };
        #pragma unroll
        for (int t = 0; t < 3; t++) {
            #pragma unroll
            for (int i = 0; i < 2; i++) {
                int g = tid + i * 256;
                int r = g >> 2, c = g & 3;
                cp16(st + t*MATB + r*ROWB + c*16,
                     (const char*)gp[t] + (long)r * Kd * 2 + c*16);
            }
        }
        cp_commit();
    };

    load_stage(0, 0);
    load_stage(1, KC);
    int nk = Kd / KC;                  // 32

    for (int ch = 0; ch < nk; ch++) {
        if (ch == nk - 1) cp_wait<0>(); else cp_wait<1>();
        __syncthreads();
        uint32_t st = sb + (ch & 1) * STGB;

        #pragma unroll
        for (int ks = 0; ks < 2; ks++) {
            uint32_t bh[4][2], bl[4][2];
            #pragma unroll
            for (int ni = 0; ni < 4; ni++) {
                int rB = wn0 + ni*8 + (lane & 7);
                int cB = ks*16 + ((lane >> 3) & 1) * 8;
                uint32_t off = (uint32_t)(rB*ROWB + cB*2);
                lds_x2(bh[ni], st + MATB   + off);
                lds_x2(bl[ni], st + 2*MATB + off);
            }
            #pragma unroll
            for (int mi = 0; mi < 4; mi++) {
                int rA = wm0 + mi*16 + (lane & 15);
                int cA = ks*16 + (lane >> 4) * 8;
                uint32_t ah[4];
                lds_x4(ah, st + (uint32_t)(rA*ROWB + cA*2));
                #pragma unroll
                for (int ni = 0; ni < 4; ni++) {
                    mma16816(acc[mi][ni], ah, bh[ni]);
                    mma16816(acc[mi][ni], ah, bl[ni]);
                }
            }
        }
        __syncthreads();
        if (ch + 2 < nk) load_stage(ch & 1, (ch + 2) * KC);
    }

    float* C = C0; const float* bias = b0;
    if (EPI == EPI_QKV) {
        if (sel == 1) { C = C1; bias = b1; }
        else if (sel == 2) { C = C2; bias = b2; }
    }
    bool do_kadd = (EPI == EPI_QKV) && (sel == 1);
    bool do_vmul = (EPI == EPI_QKV) && (sel == 2);

    int gq = lane >> 2, tq = lane & 3;
    #pragma unroll
    for (int mi = 0; mi < 4; mi++) {
        #pragma unroll
        for (int half = 0; half < 2; half++) {
            int mg = m0 + wm0 + mi*16 + gq + half*8;
            float kadd = 0.f, vmul = 1.f;
            if (do_kadd) kadd = (1.0f - msk[mg]) * -1000000.0f;
            if (do_vmul) vmul = msk[mg];
            #pragma unroll
            for (int ni = 0; ni < 4; ni++) {
                int ng = n0 + wn0 + ni*8 + tq*2;
                #pragma unroll
                for (int e = 0; e < 2; e++) {
                    float val = acc[mi][ni][half*2 + e];
                    int ngc = ng + e;
                    if (EPI != EPI_NONE) val += bias[ngc];
                    if (do_kadd) val += kadd;
                    if (do_vmul) val *= vmul;
                    if (EPI == EPI_RESID) val += resid[(long)mg*D_ + ngc];
                    C[(long)mg*D_ + ngc] = val;
                }
            }
        }
    }
}

// ---------------- SIMT SGEMM (step 5: y = Q @ att) ----------------
__global__ void __launch_bounds__(256, 2)
sgemm_k(const float* __restrict__ A0, int lda, long sAb, long sAh,
        const float* __restrict__ B0, int ldb, long sBb, long sBh,
        float* __restrict__ C0, int ldc, long sCb, long sCh,
        int K, int zH)
{
    __shared__ float As[2][BK][BM+4];
    __shared__ float Bs[2][BK][BN+4];

    int tid = threadIdx.x;
    int bz = blockIdx.z;
    int zb = bz / zH, zh = bz - zb*zH;

    const float* A  = A0 + (long)zb*sAb + (long)zh*sAh + (long)blockIdx.y*BM*lda;
    const float* Bp = B0 + (long)zb*sBb + (long)zh*sBh + blockIdx.x*BN;
    float*       C  = C0 + (long)zb*sCb + (long)zh*sCh + (long)blockIdx.y*BM*ldc + blockIdx.x*BN;

    int arow = tid >> 1;
    int acol = (tid & 1) * 4;
    int brow = tid >> 5;
    int bcol = (tid & 31) * 4;
    int tx = tid & 15;
    int ty = tid >> 4;

    float acc[8][8];
    #pragma unroll
    for (int i = 0; i < 8; i++)
        #pragma unroll
        for (int j = 0; j < 8; j++) acc[i][j] = 0.f;

    float4 a4 = *(const float4*)&A[(long)arow*lda + acol];
    float4 b4 = *(const float4*)&Bp[(long)brow*ldb + bcol];
    As[0][acol+0][arow] = a4.x; As[0][acol+1][arow] = a4.y;
    As[0][acol+2][arow] = a4.z; As[0][acol+3][arow] = a4.w;
    *(float4*)&Bs[0][brow][bcol] = b4;
    __syncthreads();

    int nk = K / BK;
    for (int kt = 0; kt < nk; kt++) {
        int buf = kt & 1;
        float4 na, nb;
        if (kt + 1 < nk) {
            na = *(const float4*)&A[(long)arow*lda + (kt+1)*BK + acol];
            nb = *(const float4*)&Bp[(long)((kt+1)*BK + brow)*ldb + bcol];
        }
        #pragma unroll
        for (int kk = 0; kk < BK; kk++) {
            float ar[8], br[8];
            *(float4*)&ar[0] = *(const float4*)&As[buf][kk][ty*4];
            *(float4*)&ar[4] = *(const float4*)&As[buf][kk][64 + ty*4];
            *(float4*)&br[0] = *(const float4*)&Bs[buf][kk][tx*4];
            *(float4*)&br[4] = *(const float4*)&Bs[buf][kk][64 + tx*4];
            #pragma unroll
            for (int i = 0; i < 8; i++)
                #pragma unroll
                for (int j = 0; j < 8; j++)
                    acc[i][j] += ar[i]*br[j];
        }
        if (kt + 1 < nk) {
            int nbuf = buf ^ 1;
            As[nbuf][acol+0][arow] = na.x; As[nbuf][acol+1][arow] = na.y;
            As[nbuf][acol+2][arow] = na.z; As[nbuf][acol+3][arow] = na.w;
            *(float4*)&Bs[nbuf][brow][bcol] = nb;
            __syncthreads();
        }
    }

    #pragma unroll
    for (int i = 0; i < 8; i++) {
        int ml = (i < 4) ? (ty*4 + i) : (64 + ty*4 + i - 4);
        #pragma unroll
        for (int j = 0; j < 8; j++) {
            int nl = (j < 4) ? (tx*4 + j) : (64 + tx*4 + j - 4);
            C[(long)ml*ldc + nl] = acc[i][j];
        }
    }
}

// ---------------- q softmax over d_head ----------------
__global__ void qsoftmax_k(float* __restrict__ q)
{
    long base = (long)blockIdx.x * DH;
    int t = threadIdx.x;
    float v = q[base + t];
    __shared__ float sh[4];
    float m = v;
    #pragma unroll
    for (int o = 16; o > 0; o >>= 1) m = fmaxf(m, __shfl_xor_sync(0xffffffffu, m, o));
    if ((t & 31) == 0) sh[t >> 5] = m;
    __syncthreads();
    m = fmaxf(fmaxf(sh[0], sh[1]), fmaxf(sh[2], sh[3]));
    float e = __expf(v - m);
    float s = e;
    #pragma unroll
    for (int o = 16; o > 0; o >>= 1) s += __shfl_xor_sync(0xffffffffu, s, o);
    __syncthreads();
    if ((t & 31) == 0) sh[t >> 5] = s;
    __syncthreads();
    s = sh[0] + sh[1] + sh[2] + sh[3];
    q[base + t] = e / s;
}

// ---------------- k softmax over time ----------------
__global__ void ksm_pass1(const float* __restrict__ kq, float* __restrict__ gm,
                          float* __restrict__ gs)
{
    int d = blockIdx.x*256 + threadIdx.x;
    int b = blockIdx.y;
    int sp = blockIdx.z;
    const float* p = kq + (long)b*T_*D_ + (long)sp*(T_/KTS)*D_ + d;
    float m = -1e30f, s = 0.f;
    for (int t = 0; t < T_/KTS; t++) {
        float vv = p[(long)t*D_];
        float nm = fmaxf(m, vv);
        s = s*__expf(m - nm) + __expf(vv - nm);
        m = nm;
    }
    int idx = (sp*B_ + b)*D_ + d;
    gm[idx] = m; gs[idx] = s;
}

__global__ void ksm_pass2(const float* __restrict__ gm, const float* __restrict__ gs,
                          float* __restrict__ cm, float* __restrict__ cs)
{
    int i = blockIdx.x*256 + threadIdx.x;
    float M = -1e30f;
    #pragma unroll
    for (int sp = 0; sp < KTS; sp++) M = fmaxf(M, gm[sp*B_*D_ + i]);
    float S = 0.f;
    #pragma unroll
    for (int sp = 0; sp < KTS; sp++) S += gs[sp*B_*D_ + i]*__expf(gm[sp*B_*D_ + i] - M);
    cm[i] = M; cs[i] = 1.f/S;
}

__global__ void ksm_pass3(float* __restrict__ kq, const float* __restrict__ cm,
                          const float* __restrict__ cs)
{
    int d = blockIdx.x*256 + threadIdx.x;
    int b = blockIdx.y, sp = blockIdx.z;
    float M = cm[b*D_ + d], inv = cs[b*D_ + d];
    float* p = kq + (long)b*T_*D_ + (long)sp*(T_/KTS)*D_ + d;
    for (int t = 0; t < T_/KTS; t++)
        p[(long)t*D_] = __expf(p[(long)t*D_] - M) * inv;
}

// ---------------- att = K^T V per (b,h) ----------------
__global__ void __launch_bounds__(256)
attpart_k(const float* __restrict__ kq, const float* __restrict__ vq,
          float* __restrict__ part)
{
    int s  = blockIdx.x;
    int bh = blockIdx.y;
    int b = bh >> 3, h = bh & 7;
    int tid = threadIdx.x;
    long base = (long)b*T_*D_ + h*DH;
    int t0 = s * (T_/SPLITS);

    __shared__ float Ks[BK][DH+4];
    __shared__ float Vs[BK][DH+4];

    int r = tid >> 5, c = (tid & 31)*4;
    int tx = tid & 15, ty = tid >> 4;
    float acc[8][8];
    #pragma unroll
    for (int i = 0; i < 8; i++)
        #pragma unroll
        for (int j = 0; j < 8; j++) acc[i][j] = 0.f;

    for (int tt = t0; tt < t0 + T_/SPLITS; tt += BK) {
        float4 k4 = *(const float4*)&kq[base + (long)(tt + r)*D_ + c];
        float4 v4 = *(const float4*)&vq[base + (long)(tt + r)*D_ + c];
        __syncthreads();
        *(float4*)&Ks[r][c] = k4;
        *(float4*)&Vs[r][c] = v4;
        __syncthreads();
        #pragma unroll
        for (int kk = 0; kk < BK; kk++) {
            float ar[8], br[8];
            *(float4*)&ar[0] = *(const float4*)&Ks[kk][ty*4];
            *(float4*)&ar[4] = *(const float4*)&Ks[kk][64 + ty*4];
            *(float4*)&br[0] = *(const float4*)&Vs[kk][tx*4];
            *(float4*)&br[4] = *(const float4*)&Vs[kk][64 + tx*4];
            #pragma unroll
            for (int i = 0; i < 8; i++)
                #pragma unroll
                for (int j = 0; j < 8; j++)
                    acc[i][j] += ar[i]*br[j];
        }
    }
    float* P = part + ((long)s*(B_*H_) + bh)*(DH*DH);
    #pragma unroll
    for (int i = 0; i < 8; i++) {
        int ml = (i < 4) ? (ty*4 + i) : (64 + ty*4 + i - 4);
        #pragma unroll
        for (int j = 0; j < 8; j++) {
            int nl = (j < 4) ? (tx*4 + j) : (64 + tx*4 + j - 4);
            P[ml*DH + nl] = acc[i][j];
        }
    }
}

__global__ void attreduce_k(const float* __restrict__ part, float* __restrict__ att)
{
    int i = blockIdx.x*256 + threadIdx.x;
    float s = 0.f;
    #pragma unroll
    for (int sp = 0; sp < SPLITS; sp++)
        s += part[(long)sp*(B_*H_*DH*DH) + i];
    att[i] = s;
}

// ---------------- FiLM ----------------
__global__ void filmpart_k(const float* __restrict__ emb, const float* __restrict__ W,
                           float* __restrict__ part)
{
    int b = blockIdx.x;
    int colBase = blockIdx.y*256;
    int kz = blockIdx.z;
    __shared__ float se[256];
    int tid = threadIdx.x;
    float e = emb[(long)b*TE_ + kz*256 + tid];
    se[tid] = silu_f(e);
    __syncthreads();
    int col = colBase + tid;
    float acc = 0.f;
    const float* wp = W + (long)(kz*256)*D2 + col;
    #pragma unroll 8
    for (int k = 0; k < 256; k++) acc += se[k]*wp[(long)k*D2];
    part[((long)kz*B_ + b)*D2 + col] = acc;
}

__global__ void filmreduce_k(const float* __restrict__ part,
                             const float* __restrict__ b_emb,
                             float* __restrict__ film)
{
    int i = blockIdx.x*256 + threadIdx.x;
    int col = i & (D2-1);
    int b = i >> 11;
    float s = b_emb[col];
    #pragma unroll
    for (int kz = 0; kz < FKS; kz++)
        s += part[((long)kz*B_ + b)*D2 + col];
    film[i] = s;
}

// ---------------- launch ----------------
extern "C" void kernel_launch(void* const* d_in, const int* in_sizes, int n_in,
                              void* d_out, int out_size)
{
    const float* x     = (const float*)d_in[0];
    const float* emb   = (const float*)d_in[1];
    const float* mask  = (const float*)d_in[2];
    const float* ln_w  = (const float*)d_in[4];
    const float* ln_b  = (const float*)d_in[5];
    const float* Wq    = (const float*)d_in[6];
    const float* bq    = (const float*)d_in[7];
    const float* Wk    = (const float*)d_in[8];
    const float* bk    = (const float*)d_in[9];
    const float* Wv    = (const float*)d_in[10];
    const float* bv    = (const float*)d_in[11];
    const float* W_emb = (const float*)d_in[12];
    const float* b_emb = (const float*)d_in[13];
    const float* ln2_w = (const float*)d_in[14];
    const float* ln2_b = (const float*)d_in[15];
    const float* W_out = (const float*)d_in[16];
    const float* b_out = (const float*)d_in[17];
    float* out = (float*)d_out;

    float *q, *k, *v, *y, *attp, *att, *filmp, *film, *gm, *gs, *cm, *cs;
    __half *xh, *wh, *wl;
    cudaGetSymbolAddress((void**)&q,    g_q);
    cudaGetSymbolAddress((void**)&k,    g_k);
    cudaGetSymbolAddress((void**)&v,    g_v);
    cudaGetSymbolAddress((void**)&y,    g_y);
    cudaGetSymbolAddress((void**)&xh,   g_xh);
    cudaGetSymbolAddress((void**)&wh,   g_wh);
    cudaGetSymbolAddress((void**)&wl,   g_wl);
    cudaGetSymbolAddress((void**)&attp, g_attp);
    cudaGetSymbolAddress((void**)&att,  g_att);
    cudaGetSymbolAddress((void**)&filmp,g_filmp);
    cudaGetSymbolAddress((void**)&film, g_film);
    cudaGetSymbolAddress((void**)&gm,   g_gm);
    cudaGetSymbolAddress((void**)&gs,   g_gs);
    cudaGetSymbolAddress((void**)&cm,   g_cm);
    cudaGetSymbolAddress((void**)&cs,   g_cs);

    cudaFuncSetAttribute(hgemm_k<EPI_QKV>,   cudaFuncAttributeMaxDynamicSharedMemorySize, SMEM_HGEMM);
    cudaFuncSetAttribute(hgemm_k<EPI_RESID>, cudaFuncAttributeMaxDynamicSharedMemorySize, SMEM_HGEMM);

    dim3 wgrid(32, 32), wblk(32, 8);

    // 1) pre-norm -> fp16
    ln_k<<<NROWS, 256>>>(x, ln_w, ln_b, xh);

    // weights: transpose + fp16 hi/lo split into concat [3N, K]
    wconv_k<<<wgrid, wblk>>>(Wq, wh,            wl);
    wconv_k<<<wgrid, wblk>>>(Wk, wh + D_*D_,    wl + D_*D_);
    wconv_k<<<wgrid, wblk>>>(Wv, wh + 2*D_*D_,  wl + 2*D_*D_);

    // 2) fused Q/K/V projection (N=3072, per-block epilogue select)
    hgemm_k<EPI_QKV><<<dim3(24, NROWS/128), 256, SMEM_HGEMM>>>(
        xh, wh, wl, q, k, v, bq, bk, bv, mask, nullptr);

    // 3) feature-map softmaxes
    qsoftmax_k<<<NROWS*H_, 128>>>(q);
    ksm_pass1<<<dim3(D_/256, B_, KTS), 256>>>(k, gm, gs);
    ksm_pass2<<<(B_*D_)/256, 256>>>(gm, gs, cm, cs);
    ksm_pass3<<<dim3(D_/256, B_, KTS), 256>>>(k, cm, cs);

    // 4) att = K^T V per (b,h)
    attpart_k<<<dim3(SPLITS, B_*H_), 256>>>(k, v, attp);
    attreduce_k<<<(B_*H_*DH*DH)/256, 256>>>(attp, att);

    // 5) y = Q @ att per (b,h) (SIMT; small)
    sgemm_k<<<dim3(1, T_/BM, B_*H_), 256>>>(
        q, D_, (long)T_*D_, (long)DH,
        att, DH, (long)H_*DH*DH, (long)DH*DH,
        y, D_, (long)T_*D_, (long)DH,
        DH, H_);

    // 6) FiLM params
    filmpart_k<<<dim3(B_, D2/256, FKS), 256>>>(emb, W_emb, filmp);
    filmreduce_k<<<(B_*D2)/256, 256>>>(filmp, b_emb, film);

    // 7) LN2 + FiLM + SiLU -> fp16 (reuse xh)
    ln2film_k<<<NROWS, 256>>>(y, ln2_w, ln2_b, film, xh);

    // 8) out = x + hh @ W_out + b_out  (reuse wh/wl slice 0; stream-serialized)
    wconv_k<<<wgrid, wblk>>>(W_out, wh, wl);
    hgemm_k<EPI_RESID><<<dim3(8, NROWS/128), 256, SMEM_HGEMM>>>(
        xh, wh, wl, out, nullptr, nullptr, b_out, nullptr, nullptr, nullptr, x);
}

// round 7
// speedup vs baseline: 3.2781x; 1.3484x over previous
#include <cuda_runtime.h>
#include <cuda_bf16.h>
#include <cuda_fp16.h>
#include <cstdint>

// Problem constants
#define B_    4
#define T_    2048
#define D_    1024
#define H_    8
#define DH    128
#define TE_   2048
#define D2    2048
#define NROWS (B_*T_)         // 8192

// SIMT GEMM tiling (step 5 only)
#define BM 128
#define BN 128
#define BK 8

#define SPLITS 16
#define KTS    8
#define FKS    8

// HMMA GEMM config (fp16 single-term)
#define KC    32              // fp16 K per chunk
#define ROWB  80              // padded smem row bytes (64B data + pad; 5x16B -> conflict-free)
#define MATB  (128*ROWB)      // 10240 per matrix per stage
#define STGB  (2*MATB)        // A, B
#define SMEM_HGEMM (2*STGB)   // double buffer: 40960

// ---------------- scratch (device globals) ----------------
__device__ __align__(128) float g_q   [NROWS*D_];
__device__ __align__(128) float g_k   [NROWS*D_];
__device__ __align__(128) float g_v   [NROWS*D_];
__device__ __align__(128) float g_y   [NROWS*D_];
__device__ __align__(128) __half g_xh[NROWS*D_];
__device__ __align__(128) __half g_wh[3*D_*D_];
__device__ __align__(128) float g_attp[SPLITS*B_*H_*DH*DH];
__device__ __align__(128) float g_att [B_*H_*DH*DH];
__device__ __align__(128) float g_filmp[FKS*B_*D2];
__device__ __align__(128) float g_film[B_*D2];
__device__ __align__(128) float g_gm  [KTS*B_*D_];
__device__ __align__(128) float g_gs  [KTS*B_*D_];
__device__ __align__(128) float g_cm  [B_*D_];
__device__ __align__(128) float g_cs  [B_*D_];

// ---------------- PTX helpers (base-ISA only) ----------------
__device__ __forceinline__ uint32_t smem_u32(const void* p) {
    uint32_t a;
    asm("{ .reg .u64 t; cvta.to.shared.u64 t, %1; cvt.u32.u64 %0, t; }" : "=r"(a) : "l"(p));
    return a;
}
__device__ __forceinline__ void cp16(uint32_t sa, const void* g) {
    asm volatile("cp.async.cg.shared.global [%0], [%1], 16;" :: "r"(sa), "l"(__cvta_generic_to_global(g)));
}
__device__ __forceinline__ void cp_commit() { asm volatile("cp.async.commit_group;" ::: "memory"); }
template<int N> __device__ __forceinline__ void cp_wait() { asm volatile("cp.async.wait_group %0;" :: "n"(N) : "memory"); }

__device__ __forceinline__ void lds_x4(uint32_t a[4], uint32_t addr) {
    asm volatile("ldmatrix.sync.aligned.m8n8.x4.shared.b16 {%0,%1,%2,%3}, [%4];"
        : "=r"(a[0]), "=r"(a[1]), "=r"(a[2]), "=r"(a[3]) : "r"(addr));
}
__device__ __forceinline__ void lds_x2(uint32_t b[2], uint32_t addr) {
    asm volatile("ldmatrix.sync.aligned.m8n8.x2.shared.b16 {%0,%1}, [%2];"
        : "=r"(b[0]), "=r"(b[1]) : "r"(addr));
}
__device__ __forceinline__ void mma16816(float d[4], const uint32_t a[4], const uint32_t b[2]) {
    asm volatile("mma.sync.aligned.m16n8k16.row.col.f32.f16.f16.f32 "
        "{%0,%1,%2,%3}, {%4,%5,%6,%7}, {%8,%9}, {%0,%1,%2,%3};"
        : "+f"(d[0]), "+f"(d[1]), "+f"(d[2]), "+f"(d[3])
        : "r"(a[0]), "r"(a[1]), "r"(a[2]), "r"(a[3]), "r"(b[0]), "r"(b[1]));
}

// ---------------- misc helpers ----------------
__device__ __forceinline__ void blockReduce2(float& a, float& b) {
    __shared__ float sa[8], sb[8];
    #pragma unroll
    for (int o = 16; o > 0; o >>= 1) {
        a += __shfl_xor_sync(0xffffffffu, a, o);
        b += __shfl_xor_sync(0xffffffffu, b, o);
    }
    int w = threadIdx.x >> 5, l = threadIdx.x & 31;
    if (l == 0) { sa[w] = a; sb[w] = b; }
    __syncthreads();
    if (threadIdx.x < 32) {
        a = (l < 8) ? sa[l] : 0.f;
        b = (l < 8) ? sb[l] : 0.f;
        #pragma unroll
        for (int o = 4; o > 0; o >>= 1) {
            a += __shfl_xor_sync(0xffffffffu, a, o);
            b += __shfl_xor_sync(0xffffffffu, b, o);
        }
        if (l == 0) { sa[0] = a; sb[0] = b; }
    }
    __syncthreads();
    a = sa[0]; b = sb[0];
}
__device__ __forceinline__ float silu_f(float x) { return x / (1.f + __expf(-x)); }

// ---------------- LayerNorm (pre-norm) -> fp16 ----------------
__global__ void ln_k(const float* __restrict__ x, const float* __restrict__ w,
                     const float* __restrict__ bb, __half* __restrict__ oh)
{
    long base = (long)blockIdx.x * D_;
    int t = threadIdx.x;
    float4 v = *(const float4*)&x[base + t*4];
    float s  = v.x + v.y + v.z + v.w;
    float ss = v.x*v.x + v.y*v.y + v.z*v.z + v.w*v.w;
    blockReduce2(s, ss);
    float mean = s * (1.f/D_);
    float var  = ss * (1.f/D_) - mean*mean;
    float rs   = rsqrtf(var + 1e-5f);
    float4 w4 = *(const float4*)&w[t*4];
    float4 b4 = *(const float4*)&bb[t*4];
    long o = base + t*4;
    oh[o+0] = __float2half((v.x-mean)*rs*w4.x + b4.x);
    oh[o+1] = __float2half((v.y-mean)*rs*w4.y + b4.y);
    oh[o+2] = __float2half((v.z-mean)*rs*w4.z + b4.z);
    oh[o+3] = __float2half((v.w-mean)*rs*w4.w + b4.w);
}

// ---------------- LayerNorm2 + FiLM + SiLU -> fp16 ----------------
__global__ void ln2film_k(const float* __restrict__ y, const float* __restrict__ w,
                          const float* __restrict__ bb, const float* __restrict__ film,
                          __half* __restrict__ oh)
{
    long base = (long)blockIdx.x * D_;
    int b = blockIdx.x >> 11;
    int t = threadIdx.x;
    float4 v = *(const float4*)&y[base + t*4];
    float s  = v.x + v.y + v.z + v.w;
    float ss = v.x*v.x + v.y*v.y + v.z*v.z + v.w*v.w;
    blockReduce2(s, ss);
    float mean = s * (1.f/D_);
    float var  = ss * (1.f/D_) - mean*mean;
    float rs   = rsqrtf(var + 1e-5f);
    float4 w4 = *(const float4*)&w[t*4];
    float4 b4 = *(const float4*)&bb[t*4];
    float4 sc = *(const float4*)&film[(long)b*D2 + t*4];
    float4 sf = *(const float4*)&film[(long)b*D2 + D_ + t*4];
    long o = base + t*4;
    oh[o+0] = __float2half(silu_f(((v.x-mean)*rs*w4.x + b4.x)*(1.f+sc.x) + sf.x));
    oh[o+1] = __float2half(silu_f(((v.y-mean)*rs*w4.y + b4.y)*(1.f+sc.y) + sf.y));
    oh[o+2] = __float2half(silu_f(((v.z-mean)*rs*w4.z + b4.z)*(1.f+sc.z) + sf.z));
    oh[o+3] = __float2half(silu_f(((v.w-mean)*rs*w4.w + b4.w)*(1.f+sc.w) + sf.w));
}

// ---------------- weight transpose -> fp16: W[K,N] -> Wt[N,K] ---------
__global__ void wconv_k(const float* __restrict__ W, __half* __restrict__ th)
{
    __shared__ float tile[32][33];
    int n0 = blockIdx.x*32, k0 = blockIdx.y*32;
    int tx = threadIdx.x, ty0 = threadIdx.y;   // 32 x 8
    #pragma unroll
    for (int i = 0; i < 4; i++) {
        int ty = ty0 + i*8;
        tile[ty][tx] = W[(long)(k0+ty)*D_ + n0+tx];
    }
    __syncthreads();
    #pragma unroll
    for (int i = 0; i < 4; i++) {
        int ty = ty0 + i*8;
        th[(long)(n0+ty)*D_ + k0+tx] = __float2half(tile[tx][ty]);
    }
}

// ---------------- HMMA fp16 GEMM: C = A @ B^T ------------------
// A: [M,K] fp16 row-major. B: [N,K] fp16 row-major (N up to 3072).
static constexpr int EPI_QKV   = 0;   // grid.x=24: sel 0=bias, 1=bias+kmask, 2=(..+bias)*mask
static constexpr int EPI_RESID = 1;   // grid.x=8:  + bias + residual

template<int EPI>
__global__ void __launch_bounds__(256, 2)
hgemm_k(const __half* __restrict__ A, const __half* __restrict__ Bm,
        float* __restrict__ C0, float* __restrict__ C1, float* __restrict__ C2,
        const float* __restrict__ b0, const float* __restrict__ b1,
        const float* __restrict__ b2,
        const float* __restrict__ msk, const float* __restrict__ resid)
{
    extern __shared__ char smem[];
    uint32_t sb = smem_u32(smem);
    int tid = threadIdx.x, lane = tid & 31, wid = tid >> 5;
    int m0 = blockIdx.y * 128;
    int nblk = blockIdx.x;
    int n0g = nblk * 128;              // row offset into B (global N)
    int n0  = (nblk & 7) * 128;        // column offset into the selected C
    int sel = nblk >> 3;
    int wm0 = (wid >> 2) * 64;
    int wn0 = (wid & 3) * 32;
    const long Kd = D_;

    float acc[4][4][4];
    #pragma unroll
    for (int i = 0; i < 4; i++)
        #pragma unroll
        for (int j = 0; j < 4; j++)
            #pragma unroll
            for (int r = 0; r < 4; r++) acc[i][j][r] = 0.f;

    auto load_stage = [&](int s, int kc) {
        uint32_t st = sb + s * STGB;
        const __half* gp[2] = {
            A  + (long)m0  * Kd + kc,
            Bm + (long)n0g * Kd + kc };
        #pragma unroll
        for (int t = 0; t < 2; t++) {
            #pragma unroll
            for (int i = 0; i < 2; i++) {
                int g = tid + i * 256;
                int r = g >> 2, c = g & 3;
                cp16(st + t*MATB + r*ROWB + c*16,
                     (const char*)gp[t] + (long)r * Kd * 2 + c*16);
            }
        }
        cp_commit();
    };

    load_stage(0, 0);
    load_stage(1, KC);
    int nk = Kd / KC;                  // 32

    for (int ch = 0; ch < nk; ch++) {
        if (ch == nk - 1) cp_wait<0>(); else cp_wait<1>();
        __syncthreads();
        uint32_t st = sb + (ch & 1) * STGB;

        #pragma unroll
        for (int ks = 0; ks < 2; ks++) {
            uint32_t bh[4][2];
            #pragma unroll
            for (int ni = 0; ni < 4; ni++) {
                int rB = wn0 + ni*8 + (lane & 7);
                int cB = ks*16 + ((lane >> 3) & 1) * 8;
                lds_x2(bh[ni], st + MATB + (uint32_t)(rB*ROWB + cB*2));
            }
            #pragma unroll
            for (int mi = 0; mi < 4; mi++) {
                int rA = wm0 + mi*16 + (lane & 15);
                int cA = ks*16 + (lane >> 4) * 8;
                uint32_t ah[4];
                lds_x4(ah, st + (uint32_t)(rA*ROWB + cA*2));
                #pragma unroll
                for (int ni = 0; ni < 4; ni++)
                    mma16816(acc[mi][ni], ah, bh[ni]);
            }
        }
        __syncthreads();
        if (ch + 2 < nk) load_stage(ch & 1, (ch + 2) * KC);
    }

    float* C = C0; const float* bias = b0;
    if (EPI == EPI_QKV) {
        if (sel == 1) { C = C1; bias = b1; }
        else if (sel == 2) { C = C2; bias = b2; }
    }
    bool do_kadd = (EPI == EPI_QKV) && (sel == 1);
    bool do_vmul = (EPI == EPI_QKV) && (sel == 2);

    int gq = lane >> 2, tq = lane & 3;
    #pragma unroll
    for (int mi = 0; mi < 4; mi++) {
        #pragma unroll
        for (int half = 0; half < 2; half++) {
            int mg = m0 + wm0 + mi*16 + gq + half*8;
            float kadd = 0.f, vmul = 1.f;
            if (do_kadd) kadd = (1.0f - msk[mg]) * -1000000.0f;
            if (do_vmul) vmul = msk[mg];
            #pragma unroll
            for (int ni = 0; ni < 4; ni++) {
                int ng = n0 + wn0 + ni*8 + tq*2;
                #pragma unroll
                for (int e = 0; e < 2; e++) {
                    float val = acc[mi][ni][half*2 + e];
                    int ngc = ng + e;
                    val += bias[ngc];
                    if (do_kadd) val += kadd;
                    if (do_vmul) val *= vmul;
                    if (EPI == EPI_RESID) val += resid[(long)mg*D_ + ngc];
                    C[(long)mg*D_ + ngc] = val;
                }
            }
        }
    }
}

// ---------------- SIMT SGEMM (step 5: y = Q @ att) ----------------
__global__ void __launch_bounds__(256, 2)
sgemm_k(const float* __restrict__ A0, int lda, long sAb, long sAh,
        const float* __restrict__ B0, int ldb, long sBb, long sBh,
        float* __restrict__ C0, int ldc, long sCb, long sCh,
        int K, int zH)
{
    __shared__ float As[2][BK][BM+4];
    __shared__ float Bs[2][BK][BN+4];

    int tid = threadIdx.x;
    int bz = blockIdx.z;
    int zb = bz / zH, zh = bz - zb*zH;

    const float* A  = A0 + (long)zb*sAb + (long)zh*sAh + (long)blockIdx.y*BM*lda;
    const float* Bp = B0 + (long)zb*sBb + (long)zh*sBh + blockIdx.x*BN;
    float*       C  = C0 + (long)zb*sCb + (long)zh*sCh + (long)blockIdx.y*BM*ldc + blockIdx.x*BN;

    int arow = tid >> 1;
    int acol = (tid & 1) * 4;
    int brow = tid >> 5;
    int bcol = (tid & 31) * 4;
    int tx = tid & 15;
    int ty = tid >> 4;

    float acc[8][8];
    #pragma unroll
    for (int i = 0; i < 8; i++)
        #pragma unroll
        for (int j = 0; j < 8; j++) acc[i][j] = 0.f;

    float4 a4 = *(const float4*)&A[(long)arow*lda + acol];
    float4 b4 = *(const float4*)&Bp[(long)brow*ldb + bcol];
    As[0][acol+0][arow] = a4.x; As[0][acol+1][arow] = a4.y;
    As[0][acol+2][arow] = a4.z; As[0][acol+3][arow] = a4.w;
    *(float4*)&Bs[0][brow][bcol] = b4;
    __syncthreads();

    int nk = K / BK;
    for (int kt = 0; kt < nk; kt++) {
        int buf = kt & 1;
        float4 na, nb;
        if (kt + 1 < nk) {
            na = *(const float4*)&A[(long)arow*lda + (kt+1)*BK + acol];
            nb = *(const float4*)&Bp[(long)((kt+1)*BK + brow)*ldb + bcol];
        }
        #pragma unroll
        for (int kk = 0; kk < BK; kk++) {
            float ar[8], br[8];
            *(float4*)&ar[0] = *(const float4*)&As[buf][kk][ty*4];
            *(float4*)&ar[4] = *(const float4*)&As[buf][kk][64 + ty*4];
            *(float4*)&br[0] = *(const float4*)&Bs[buf][kk][tx*4];
            *(float4*)&br[4] = *(const float4*)&Bs[buf][kk][64 + tx*4];
            #pragma unroll
            for (int i = 0; i < 8; i++)
                #pragma unroll
                for (int j = 0; j < 8; j++)
                    acc[i][j] += ar[i]*br[j];
        }
        if (kt + 1 < nk) {
            int nbuf = buf ^ 1;
            As[nbuf][acol+0][arow] = na.x; As[nbuf][acol+1][arow] = na.y;
            As[nbuf][acol+2][arow] = na.z; As[nbuf][acol+3][arow] = na.w;
            *(float4*)&Bs[nbuf][brow][bcol] = nb;
            __syncthreads();
        }
    }

    #pragma unroll
    for (int i = 0; i < 8; i++) {
        int ml = (i < 4) ? (ty*4 + i) : (64 + ty*4 + i - 4);
        #pragma unroll
        for (int j = 0; j < 8; j++) {
            int nl = (j < 4) ? (tx*4 + j) : (64 + tx*4 + j - 4);
            C[(long)ml*ldc + nl] = acc[i][j];
        }
    }
}

// ---------------- q softmax over d_head ----------------
__global__ void qsoftmax_k(float* __restrict__ q)
{
    long base = (long)blockIdx.x * DH;
    int t = threadIdx.x;
    float v = q[base + t];
    __shared__ float sh[4];
    float m = v;
    #pragma unroll
    for (int o = 16; o > 0; o >>= 1) m = fmaxf(m, __shfl_xor_sync(0xffffffffu, m, o));
    if ((t & 31) == 0) sh[t >> 5] = m;
    __syncthreads();
    m = fmaxf(fmaxf(sh[0], sh[1]), fmaxf(sh[2], sh[3]));
    float e = __expf(v - m);
    float s = e;
    #pragma unroll
    for (int o = 16; o > 0; o >>= 1) s += __shfl_xor_sync(0xffffffffu, s, o);
    __syncthreads();
    if ((t & 31) == 0) sh[t >> 5] = s;
    __syncthreads();
    s = sh[0] + sh[1] + sh[2] + sh[3];
    q[base + t] = e / s;
}

// ---------------- k softmax stats over time (2 passes; normalization fused into attpart)
__global__ void ksm_pass1(const float* __restrict__ kq, float* __restrict__ gm,
                          float* __restrict__ gs)
{
    int d = blockIdx.x*256 + threadIdx.x;
    int b = blockIdx.y;
    int sp = blockIdx.z;
    const float* p = kq + (long)b*T_*D_ + (long)sp*(T_/KTS)*D_ + d;
    float m = -1e30f, s = 0.f;
    for (int t = 0; t < T_/KTS; t++) {
        float vv = p[(long)t*D_];
        float nm = fmaxf(m, vv);
        s = s*__expf(m - nm) + __expf(vv - nm);
        m = nm;
    }
    int idx = (sp*B_ + b)*D_ + d;
    gm[idx] = m; gs[idx] = s;
}

__global__ void ksm_pass2(const float* __restrict__ gm, const float* __restrict__ gs,
                          float* __restrict__ cm, float* __restrict__ cs)
{
    int i = blockIdx.x*256 + threadIdx.x;
    float M = -1e30f;
    #pragma unroll
    for (int sp = 0; sp < KTS; sp++) M = fmaxf(M, gm[sp*B_*D_ + i]);
    float S = 0.f;
    #pragma unroll
    for (int sp = 0; sp < KTS; sp++) S += gs[sp*B_*D_ + i]*__expf(gm[sp*B_*D_ + i] - M);
    cm[i] = M; cs[i] = 1.f/S;
}

// ---------------- att = softmax(K)^T V per (b,h), normalization fused ------
__global__ void __launch_bounds__(256)
attpart_k(const float* __restrict__ kq, const float* __restrict__ vq,
          const float* __restrict__ cm, const float* __restrict__ cs,
          float* __restrict__ part)
{
    int s  = blockIdx.x;
    int bh = blockIdx.y;
    int b = bh >> 3, h = bh & 7;
    int tid = threadIdx.x;
    long base = (long)b*T_*D_ + h*DH;
    int t0 = s * (T_/SPLITS);

    __shared__ float Ks[BK][DH+4];
    __shared__ float Vs[BK][DH+4];

    int r = tid >> 5, c = (tid & 31)*4;
    int tx = tid & 15, ty = tid >> 4;

    // per-thread softmax constants for columns c..c+3 of this head
    float4 M4 = *(const float4*)&cm[b*D_ + h*DH + c];
    float4 I4 = *(const float4*)&cs[b*D_ + h*DH + c];

    float acc[8][8];
    #pragma unroll
    for (int i = 0; i < 8; i++)
        #pragma unroll
        for (int j = 0; j < 8; j++) acc[i][j] = 0.f;

    for (int tt = t0; tt < t0 + T_/SPLITS; tt += BK) {
        float4 k4 = *(const float4*)&kq[base + (long)(tt + r)*D_ + c];
        float4 v4 = *(const float4*)&vq[base + (long)(tt + r)*D_ + c];
        k4.x = __expf(k4.x - M4.x) * I4.x;
        k4.y = __expf(k4.y - M4.y) * I4.y;
        k4.z = __expf(k4.z - M4.z) * I4.z;
        k4.w = __expf(k4.w - M4.w) * I4.w;
        __syncthreads();
        *(float4*)&Ks[r][c] = k4;
        *(float4*)&Vs[r][c] = v4;
        __syncthreads();
        #pragma unroll
        for (int kk = 0; kk < BK; kk++) {
            float ar[8], br[8];
            *(float4*)&ar[0] = *(const float4*)&Ks[kk][ty*4];
            *(float4*)&ar[4] = *(const float4*)&Ks[kk][64 + ty*4];
            *(float4*)&br[0] = *(const float4*)&Vs[kk][tx*4];
            *(float4*)&br[4] = *(const float4*)&Vs[kk][64 + tx*4];
            #pragma unroll
            for (int i = 0; i < 8; i++)
                #pragma unroll
                for (int j = 0; j < 8; j++)
                    acc[i][j] += ar[i]*br[j];
        }
    }
    float* P = part + ((long)s*(B_*H_) + bh)*(DH*DH);
    #pragma unroll
    for (int i = 0; i < 8; i++) {
        int ml = (i < 4) ? (ty*4 + i) : (64 + ty*4 + i - 4);
        #pragma unroll
        for (int j = 0; j < 8; j++) {
            int nl = (j < 4) ? (tx*4 + j) : (64 + tx*4 + j - 4);
            P[ml*DH + nl] = acc[i][j];
        }
    }
}

__global__ void attreduce_k(const float* __restrict__ part, float* __restrict__ att)
{
    int i = blockIdx.x*256 + threadIdx.x;
    float s = 0.f;
    #pragma unroll
    for (int sp = 0; sp < SPLITS; sp++)
        s += part[(long)sp*(B_*H_*DH*DH) + i];
    att[i] = s;
}

// ---------------- FiLM ----------------
__global__ void filmpart_k(const float* __restrict__ emb, const float* __restrict__ W,
                           float* __restrict__ part)
{
    int b = blockIdx.x;
    int colBase = blockIdx.y*256;
    int kz = blockIdx.z;
    __shared__ float se[256];
    int tid = threadIdx.x;
    float e = emb[(long)b*TE_ + kz*256 + tid];
    se[tid] = silu_f(e);
    __syncthreads();
    int col = colBase + tid;
    float acc = 0.f;
    const float* wp = W + (long)(kz*256)*D2 + col;
    #pragma unroll 8
    for (int k = 0; k < 256; k++) acc += se[k]*wp[(long)k*D2];
    part[((long)kz*B_ + b)*D2 + col] = acc;
}

__global__ void filmreduce_k(const float* __restrict__ part,
                             const float* __restrict__ b_emb,
                             float* __restrict__ film)
{
    int i = blockIdx.x*256 + threadIdx.x;
    int col = i & (D2-1);
    int b = i >> 11;
    float s = b_emb[col];
    #pragma unroll
    for (int kz = 0; kz < FKS; kz++)
        s += part[((long)kz*B_ + b)*D2 + col];
    film[i] = s;
}

// ---------------- launch ----------------
extern "C" void kernel_launch(void* const* d_in, const int* in_sizes, int n_in,
                              void* d_out, int out_size)
{
    const float* x     = (const float*)d_in[0];
    const float* emb   = (const float*)d_in[1];
    const float* mask  = (const float*)d_in[2];
    const float* ln_w  = (const float*)d_in[4];
    const float* ln_b  = (const float*)d_in[5];
    const float* Wq    = (const float*)d_in[6];
    const float* bq    = (const float*)d_in[7];
    const float* Wk    = (const float*)d_in[8];
    const float* bk    = (const float*)d_in[9];
    const float* Wv    = (const float*)d_in[10];
    const float* bv    = (const float*)d_in[11];
    const float* W_emb = (const float*)d_in[12];
    const float* b_emb = (const float*)d_in[13];
    const float* ln2_w = (const float*)d_in[14];
    const float* ln2_b = (const float*)d_in[15];
    const float* W_out = (const float*)d_in[16];
    const float* b_out = (const float*)d_in[17];
    float* out = (float*)d_out;

    float *q, *k, *v, *y, *attp, *att, *filmp, *film, *gm, *gs, *cm, *cs;
    __half *xh, *wh;
    cudaGetSymbolAddress((void**)&q,    g_q);
    cudaGetSymbolAddress((void**)&k,    g_k);
    cudaGetSymbolAddress((void**)&v,    g_v);
    cudaGetSymbolAddress((void**)&y,    g_y);
    cudaGetSymbolAddress((void**)&xh,   g_xh);
    cudaGetSymbolAddress((void**)&wh,   g_wh);
    cudaGetSymbolAddress((void**)&attp, g_attp);
    cudaGetSymbolAddress((void**)&att,  g_att);
    cudaGetSymbolAddress((void**)&filmp,g_filmp);
    cudaGetSymbolAddress((void**)&film, g_film);
    cudaGetSymbolAddress((void**)&gm,   g_gm);
    cudaGetSymbolAddress((void**)&gs,   g_gs);
    cudaGetSymbolAddress((void**)&cm,   g_cm);
    cudaGetSymbolAddress((void**)&cs,   g_cs);

    cudaFuncSetAttribute(hgemm_k<EPI_QKV>,   cudaFuncAttributeMaxDynamicSharedMemorySize, SMEM_HGEMM);
    cudaFuncSetAttribute(hgemm_k<EPI_RESID>, cudaFuncAttributeMaxDynamicSharedMemorySize, SMEM_HGEMM);

    dim3 wgrid(32, 32), wblk(32, 8);

    // 1) pre-norm -> fp16
    ln_k<<<NROWS, 256>>>(x, ln_w, ln_b, xh);

    // weights: transpose -> fp16 concat [3N, K]
    wconv_k<<<wgrid, wblk>>>(Wq, wh);
    wconv_k<<<wgrid, wblk>>>(Wk, wh + D_*D_);
    wconv_k<<<wgrid, wblk>>>(Wv, wh + 2*D_*D_);

    // 2) fused Q/K/V projection (N=3072, per-block epilogue select)
    hgemm_k<EPI_QKV><<<dim3(24, NROWS/128), 256, SMEM_HGEMM>>>(
        xh, wh, q, k, v, bq, bk, bv, mask, nullptr);

    // 3) feature-map softmaxes (k: stats only; normalization fused into attpart)
    qsoftmax_k<<<NROWS*H_, 128>>>(q);
    ksm_pass1<<<dim3(D_/256, B_, KTS), 256>>>(k, gm, gs);
    ksm_pass2<<<(B_*D_)/256, 256>>>(gm, gs, cm, cs);

    // 4) att = softmax(K)^T V per (b,h)
    attpart_k<<<dim3(SPLITS, B_*H_), 256>>>(k, v, cm, cs, attp);
    attreduce_k<<<(B_*H_*DH*DH)/256, 256>>>(attp, att);

    // 5) y = Q @ att per (b,h) (SIMT; small)
    sgemm_k<<<dim3(1, T_/BM, B_*H_), 256>>>(
        q, D_, (long)T_*D_, (long)DH,
        att, DH, (long)H_*DH*DH, (long)DH*DH,
        y, D_, (long)T_*D_, (long)DH,
        DH, H_);

    // 6) FiLM params
    filmpart_k<<<dim3(B_, D2/256, FKS), 256>>>(emb, W_emb, filmp);
    filmreduce_k<<<(B_*D2)/256, 256>>>(filmp, b_emb, film);

    // 7) LN2 + FiLM + SiLU -> fp16 (reuse xh)
    ln2film_k<<<NROWS, 256>>>(y, ln2_w, ln2_b, film, xh);

    // 8) out = x + hh @ W_out + b_out
    wconv_k<<<wgrid, wblk>>>(W_out, wh);
    hgemm_k<EPI_RESID><<<dim3(8, NROWS/128), 256, SMEM_HGEMM>>>(
        xh, wh, out, nullptr, nullptr, b_out, nullptr, nullptr, nullptr, x);
}

// round 9
// speedup vs baseline: 3.6663x; 1.1184x over previous
#include <cuda_runtime.h>
#include <cuda_bf16.h>
#include <cuda_fp16.h>
#include <cstdint>

// Problem constants
#define B_    4
#define T_    2048
#define D_    1024
#define H_    8
#define DH    128
#define TE_   2048
#define D2    2048
#define NROWS (B_*T_)         // 8192

#define SPLITS 16
#define KTS    8
#define FKS    8

// HMMA GEMM config (fp16 single-term)
#define KC    32              // fp16 K per chunk
#define ROWB  80              // padded smem row bytes
#define MATB  (128*ROWB)      // 10240 per matrix per stage
#define STGB  (2*MATB)        // A, B
#define SMEM_HGEMM (2*STGB)   // 40960

// ---------------- scratch (device globals) ----------------
__device__ __align__(128) __half g_qh [NROWS*D_];
__device__ __align__(128) float g_k   [NROWS*D_];
__device__ __align__(128) float g_v   [NROWS*D_];
__device__ __align__(128) float g_y   [NROWS*D_];
__device__ __align__(128) __half g_xh[NROWS*D_];
__device__ __align__(128) __half g_wh[3*D_*D_];
__device__ __align__(128) float g_attp[SPLITS*B_*H_*DH*DH];
__device__ __align__(128) __half g_attT[B_*H_*DH*DH];
__device__ __align__(128) float g_filmp[FKS*B_*D2];
__device__ __align__(128) float g_film[B_*D2];
__device__ __align__(128) float g_gm  [KTS*B_*D_];
__device__ __align__(128) float g_gs  [KTS*B_*D_];
__device__ __align__(128) float g_cm  [B_*D_];
__device__ __align__(128) float g_cs  [B_*D_];

// ---------------- PTX helpers (base-ISA only) ----------------
__device__ __forceinline__ uint32_t smem_u32(const void* p) {
    uint32_t a;
    asm("{ .reg .u64 t; cvta.to.shared.u64 t, %1; cvt.u32.u64 %0, t; }" : "=r"(a) : "l"(p));
    return a;
}
__device__ __forceinline__ void cp16(uint32_t sa, const void* g) {
    asm volatile("cp.async.cg.shared.global [%0], [%1], 16;" :: "r"(sa), "l"(__cvta_generic_to_global(g)));
}
__device__ __forceinline__ void cp_commit() { asm volatile("cp.async.commit_group;" ::: "memory"); }
template<int N> __device__ __forceinline__ void cp_wait() { asm volatile("cp.async.wait_group %0;" :: "n"(N) : "memory"); }

__device__ __forceinline__ void lds_x4(uint32_t a[4], uint32_t addr) {
    asm volatile("ldmatrix.sync.aligned.m8n8.x4.shared.b16 {%0,%1,%2,%3}, [%4];"
        : "=r"(a[0]), "=r"(a[1]), "=r"(a[2]), "=r"(a[3]) : "r"(addr));
}
__device__ __forceinline__ void lds_x2(uint32_t b[2], uint32_t addr) {
    asm volatile("ldmatrix.sync.aligned.m8n8.x2.shared.b16 {%0,%1}, [%2];"
        : "=r"(b[0]), "=r"(b[1]) : "r"(addr));
}
__device__ __forceinline__ void mma16816(float d[4], const uint32_t a[4], const uint32_t b[2]) {
    asm volatile("mma.sync.aligned.m16n8k16.row.col.f32.f16.f16.f32 "
        "{%0,%1,%2,%3}, {%4,%5,%6,%7}, {%8,%9}, {%0,%1,%2,%3};"
        : "+f"(d[0]), "+f"(d[1]), "+f"(d[2]), "+f"(d[3])
        : "r"(a[0]), "r"(a[1]), "r"(a[2]), "r"(a[3]), "r"(b[0]), "r"(b[1]));
}

// ---------------- misc helpers ----------------
__device__ __forceinline__ void blockReduce2(float& a, float& b) {
    __shared__ float sa[8], sb[8];
    #pragma unroll
    for (int o = 16; o > 0; o >>= 1) {
        a += __shfl_xor_sync(0xffffffffu, a, o);
        b += __shfl_xor_sync(0xffffffffu, b, o);
    }
    int w = threadIdx.x >> 5, l = threadIdx.x & 31;
    if (l == 0) { sa[w] = a; sb[w] = b; }
    __syncthreads();
    if (threadIdx.x < 32) {
        a = (l < 8) ? sa[l] : 0.f;
        b = (l < 8) ? sb[l] : 0.f;
        #pragma unroll
        for (int o = 4; o > 0; o >>= 1) {
            a += __shfl_xor_sync(0xffffffffu, a, o);
            b += __shfl_xor_sync(0xffffffffu, b, o);
        }
        if (l == 0) { sa[0] = a; sb[0] = b; }
    }
    __syncthreads();
    a = sa[0]; b = sb[0];
}
__device__ __forceinline__ float silu_f(float x) { return x / (1.f + __expf(-x)); }

// ---------------- LayerNorm (pre-norm) -> fp16 ----------------
__global__ void ln_k(const float* __restrict__ x, const float* __restrict__ w,
                     const float* __restrict__ bb, __half* __restrict__ oh)
{
    long base = (long)blockIdx.x * D_;
    int t = threadIdx.x;
    float4 v = *(const float4*)&x[base + t*4];
    float s  = v.x + v.y + v.z + v.w;
    float ss = v.x*v.x + v.y*v.y + v.z*v.z + v.w*v.w;
    blockReduce2(s, ss);
    float mean = s * (1.f/D_);
    float var  = ss * (1.f/D_) - mean*mean;
    float rs   = rsqrtf(var + 1e-5f);
    float4 w4 = *(const float4*)&w[t*4];
    float4 b4 = *(const float4*)&bb[t*4];
    long o = base + t*4;
    oh[o+0] = __float2half((v.x-mean)*rs*w4.x + b4.x);
    oh[o+1] = __float2half((v.y-mean)*rs*w4.y + b4.y);
    oh[o+2] = __float2half((v.z-mean)*rs*w4.z + b4.z);
    oh[o+3] = __float2half((v.w-mean)*rs*w4.w + b4.w);
}

// ---------------- LayerNorm2 + FiLM + SiLU -> fp16 ----------------
__global__ void ln2film_k(const float* __restrict__ y, const float* __restrict__ w,
                          const float* __restrict__ bb, const float* __restrict__ film,
                          __half* __restrict__ oh)
{
    long base = (long)blockIdx.x * D_;
    int b = blockIdx.x >> 11;
    int t = threadIdx.x;
    float4 v = *(const float4*)&y[base + t*4];
    float s  = v.x + v.y + v.z + v.w;
    float ss = v.x*v.x + v.y*v.y + v.z*v.z + v.w*v.w;
    blockReduce2(s, ss);
    float mean = s * (1.f/D_);
    float var  = ss * (1.f/D_) - mean*mean;
    float rs   = rsqrtf(var + 1e-5f);
    float4 w4 = *(const float4*)&w[t*4];
    float4 b4 = *(const float4*)&bb[t*4];
    float4 sc = *(const float4*)&film[(long)b*D2 + t*4];
    float4 sf = *(const float4*)&film[(long)b*D2 + D_ + t*4];
    long o = base + t*4;
    oh[o+0] = __float2half(silu_f(((v.x-mean)*rs*w4.x + b4.x)*(1.f+sc.x) + sf.x));
    oh[o+1] = __float2half(silu_f(((v.y-mean)*rs*w4.y + b4.y)*(1.f+sc.y) + sf.y));
    oh[o+2] = __float2half(silu_f(((v.z-mean)*rs*w4.z + b4.z)*(1.f+sc.z) + sf.z));
    oh[o+3] = __float2half(silu_f(((v.w-mean)*rs*w4.w + b4.w)*(1.f+sc.w) + sf.w));
}

// ---------------- weight transpose -> fp16: W[K,N] -> Wt[N,K] ---------
__global__ void wconv_k(const float* __restrict__ W, __half* __restrict__ th)
{
    __shared__ float tile[32][33];
    int n0 = blockIdx.x*32, k0 = blockIdx.y*32;
    int tx = threadIdx.x, ty0 = threadIdx.y;   // 32 x 8
    #pragma unroll
    for (int i = 0; i < 4; i++) {
        int ty = ty0 + i*8;
        tile[ty][tx] = W[(long)(k0+ty)*D_ + n0+tx];
    }
    __syncthreads();
    #pragma unroll
    for (int i = 0; i < 4; i++) {
        int ty = ty0 + i*8;
        th[(long)(n0+ty)*D_ + k0+tx] = __float2half(tile[tx][ty]);
    }
}

// ---------------- HMMA fp16 GEMM: C = A @ B^T ------------------
static constexpr int EPI_QKV   = 0;   // sel 0: bias+softmax(dh)->fp16 q; 1: bias+kmask; 2: (..+bias)*mask
static constexpr int EPI_RESID = 1;   // + bias + residual

template<int EPI>
__global__ void __launch_bounds__(256, 2)
hgemm_k(const __half* __restrict__ A, const __half* __restrict__ Bm,
        __half* __restrict__ Cq,
        float* __restrict__ C1, float* __restrict__ C2,
        const float* __restrict__ b0, const float* __restrict__ b1,
        const float* __restrict__ b2,
        const float* __restrict__ msk, const float* __restrict__ resid,
        float* __restrict__ Cf)
{
    extern __shared__ char smem[];
    uint32_t sb = smem_u32(smem);
    int tid = threadIdx.x, lane = tid & 31, wid = tid >> 5;
    int m0 = blockIdx.y * 128;
    int nblk = blockIdx.x;
    int n0g = nblk * 128;
    int n0  = (nblk & 7) * 128;
    int sel = nblk >> 3;
    int wm0 = (wid >> 2) * 64;
    int wn0 = (wid & 3) * 32;
    const long Kd = D_;

    float acc[4][4][4];
    #pragma unroll
    for (int i = 0; i < 4; i++)
        #pragma unroll
        for (int j = 0; j < 4; j++)
            #pragma unroll
            for (int r = 0; r < 4; r++) acc[i][j][r] = 0.f;

    auto load_stage = [&](int s, int kc) {
        uint32_t st = sb + s * STGB;
        const __half* gp[2] = {
            A  + (long)m0  * Kd + kc,
            Bm + (long)n0g * Kd + kc };
        #pragma unroll
        for (int t = 0; t < 2; t++) {
            #pragma unroll
            for (int i = 0; i < 2; i++) {
                int g = tid + i * 256;
                int r = g >> 2, c = g & 3;
                cp16(st + t*MATB + r*ROWB + c*16,
                     (const char*)gp[t] + (long)r * Kd * 2 + c*16);
            }
        }
        cp_commit();
    };

    load_stage(0, 0);
    load_stage(1, KC);
    int nk = Kd / KC;

    for (int ch = 0; ch < nk; ch++) {
        if (ch == nk - 1) cp_wait<0>(); else cp_wait<1>();
        __syncthreads();
        uint32_t st = sb + (ch & 1) * STGB;

        #pragma unroll
        for (int ks = 0; ks < 2; ks++) {
            uint32_t bh[4][2];
            #pragma unroll
            for (int ni = 0; ni < 4; ni++) {
                int rB = wn0 + ni*8 + (lane & 7);
                int cB = ks*16 + ((lane >> 3) & 1) * 8;
                lds_x2(bh[ni], st + MATB + (uint32_t)(rB*ROWB + cB*2));
            }
            #pragma unroll
            for (int mi = 0; mi < 4; mi++) {
                int rA = wm0 + mi*16 + (lane & 15);
                int cA = ks*16 + (lane >> 4) * 8;
                uint32_t ah[4];
                lds_x4(ah, st + (uint32_t)(rA*ROWB + cA*2));
                #pragma unroll
                for (int ni = 0; ni < 4; ni++)
                    mma16816(acc[mi][ni], ah, bh[ni]);
            }
        }
        __syncthreads();
        if (ch + 2 < nk) load_stage(ch & 1, (ch + 2) * KC);
    }

    int gq = lane >> 2, tq = lane & 3;

    if (EPI == EPI_QKV && sel == 0) {
        // ---- fused per-head softmax over the 128 columns of this tile ----
        float* redmax = (float*)smem;            // [128][4]
        float* redsum = (float*)(smem + 2048);   // [128][4]
        int w4 = wid & 3;
        // bias + row max
        #pragma unroll
        for (int mi = 0; mi < 4; mi++)
            #pragma unroll
            for (int half = 0; half < 2; half++) {
                int rloc = wm0 + mi*16 + gq + half*8;
                float pm = -1e30f;
                #pragma unroll
                for (int ni = 0; ni < 4; ni++)
                    #pragma unroll
                    for (int e = 0; e < 2; e++) {
                        int ngc = n0 + wn0 + ni*8 + tq*2 + e;
                        float val = acc[mi][ni][half*2 + e] + b0[ngc];
                        acc[mi][ni][half*2 + e] = val;
                        pm = fmaxf(pm, val);
                    }
                pm = fmaxf(pm, __shfl_xor_sync(0xffffffffu, pm, 1));
                pm = fmaxf(pm, __shfl_xor_sync(0xffffffffu, pm, 2));
                if (tq == 0) redmax[rloc*4 + w4] = pm;
            }
        __syncthreads();
        // exp + row sum
        #pragma unroll
        for (int mi = 0; mi < 4; mi++)
            #pragma unroll
            for (int half = 0; half < 2; half++) {
                int rloc = wm0 + mi*16 + gq + half*8;
                float rm = fmaxf(fmaxf(redmax[rloc*4+0], redmax[rloc*4+1]),
                                 fmaxf(redmax[rloc*4+2], redmax[rloc*4+3]));
                float ps = 0.f;
                #pragma unroll
                for (int ni = 0; ni < 4; ni++)
                    #pragma unroll
                    for (int e = 0; e < 2; e++) {
                        float v = __expf(acc[mi][ni][half*2 + e] - rm);
                        acc[mi][ni][half*2 + e] = v;
                        ps += v;
                    }
                ps += __shfl_xor_sync(0xffffffffu, ps, 1);
                ps += __shfl_xor_sync(0xffffffffu, ps, 2);
                if (tq == 0) redsum[rloc*4 + w4] = ps;
            }
        __syncthreads();
        // normalize + write fp16
        #pragma unroll
        for (int mi = 0; mi < 4; mi++)
            #pragma unroll
            for (int half = 0; half < 2; half++) {
                int rloc = wm0 + mi*16 + gq + half*8;
                float inv = 1.f / (redsum[rloc*4+0] + redsum[rloc*4+1]
                                 + redsum[rloc*4+2] + redsum[rloc*4+3]);
                long mg = m0 + rloc;
                #pragma unroll
                for (int ni = 0; ni < 4; ni++)
                    #pragma unroll
                    for (int e = 0; e < 2; e++) {
                        int ngc = n0 + wn0 + ni*8 + tq*2 + e;
                        Cq[mg*D_ + ngc] = __float2half(acc[mi][ni][half*2 + e] * inv);
                    }
            }
        return;
    }

    float* C; const float* bias;
    if (EPI == EPI_RESID) { C = Cf; bias = b0; }
    else if (sel == 1)    { C = C1; bias = b1; }
    else                  { C = C2; bias = b2; }
    bool do_kadd = (EPI == EPI_QKV) && (sel == 1);
    bool do_vmul = (EPI == EPI_QKV) && (sel == 2);

    #pragma unroll
    for (int mi = 0; mi < 4; mi++) {
        #pragma unroll
        for (int half = 0; half < 2; half++) {
            int mg = m0 + wm0 + mi*16 + gq + half*8;
            float kadd = 0.f, vmul = 1.f;
            if (do_kadd) kadd = (1.0f - msk[mg]) * -1000000.0f;
            if (do_vmul) vmul = msk[mg];
            #pragma unroll
            for (int ni = 0; ni < 4; ni++) {
                int ng = n0 + wn0 + ni*8 + tq*2;
                #pragma unroll
                for (int e = 0; e < 2; e++) {
                    float val = acc[mi][ni][half*2 + e];
                    int ngc = ng + e;
                    val += bias[ngc];
                    if (do_kadd) val += kadd;
                    if (do_vmul) val *= vmul;
                    if (EPI == EPI_RESID) val += resid[(long)mg*D_ + ngc];
                    C[(long)mg*D_ + ngc] = val;
                }
            }
        }
    }
}

// ---------------- HMMA step 5: y = qh @ attT^T per (b,h) ----------------
__global__ void __launch_bounds__(256, 2)
attgemm_k(const __half* __restrict__ qh, const __half* __restrict__ attT,
          float* __restrict__ y)
{
    extern __shared__ char smem[];
    uint32_t sb = smem_u32(smem);
    int tid = threadIdx.x, lane = tid & 31, wid = tid >> 5;
    int m0 = blockIdx.x * 128;
    int bh = blockIdx.y;
    int b = bh >> 3, h = bh & 7;
    // FIX R8 bug: A must be offset by this CTA's row block m0
    const __half* A  = qh   + (long)b*T_*D_ + (long)m0*D_ + h*DH;
    const __half* Bm = attT + (long)bh*DH*DH;
    float*        C  = y    + (long)b*T_*D_ + h*DH;
    int wm0 = (wid >> 2) * 64;
    int wn0 = (wid & 3) * 32;

    float acc[4][4][4];
    #pragma unroll
    for (int i = 0; i < 4; i++)
        #pragma unroll
        for (int j = 0; j < 4; j++)
            #pragma unroll
            for (int r = 0; r < 4; r++) acc[i][j][r] = 0.f;

    auto load_stage = [&](int s, int kc) {
        uint32_t st = sb + s * STGB;
        #pragma unroll
        for (int i = 0; i < 2; i++) {
            int g = tid + i * 256;
            int r = g >> 2, c = g & 3;
            cp16(st + r*ROWB + c*16,
                 (const char*)(A + (long)r * D_ + kc) + c*16);
            cp16(st + MATB + r*ROWB + c*16,
                 (const char*)(Bm + r * DH + kc) + c*16);
        }
        cp_commit();
    };

    load_stage(0, 0);
    load_stage(1, KC);
    const int nk = DH / KC;   // 4

    for (int ch = 0; ch < nk; ch++) {
        if (ch == nk - 1) cp_wait<0>(); else cp_wait<1>();
        __syncthreads();
        uint32_t st = sb + (ch & 1) * STGB;
        #pragma unroll
        for (int ks = 0; ks < 2; ks++) {
            uint32_t bh2[4][2];
            #pragma unroll
            for (int ni = 0; ni < 4; ni++) {
                int rB = wn0 + ni*8 + (lane & 7);
                int cB = ks*16 + ((lane >> 3) & 1) * 8;
                lds_x2(bh2[ni], st + MATB + (uint32_t)(rB*ROWB + cB*2));
            }
            #pragma unroll
            for (int mi = 0; mi < 4; mi++) {
                int rA = wm0 + mi*16 + (lane & 15);
                int cA = ks*16 + (lane >> 4) * 8;
                uint32_t ah[4];
                lds_x4(ah, st + (uint32_t)(rA*ROWB + cA*2));
                #pragma unroll
                for (int ni = 0; ni < 4; ni++)
                    mma16816(acc[mi][ni], ah, bh2[ni]);
            }
        }
        __syncthreads();
        if (ch + 2 < nk) load_stage(ch & 1, (ch + 2) * KC);
    }

    int gq = lane >> 2, tq = lane & 3;
    #pragma unroll
    for (int mi = 0; mi < 4; mi++)
        #pragma unroll
        for (int half = 0; half < 2; half++) {
            long mg = m0 + wm0 + mi*16 + gq + half*8;
            #pragma unroll
            for (int ni = 0; ni < 4; ni++) {
                int ng = wn0 + ni*8 + tq*2;
                C[mg*D_ + ng]   = acc[mi][ni][half*2];
                C[mg*D_ + ng+1] = acc[mi][ni][half*2+1];
            }
        }
}

// ---------------- k softmax stats over time ----------------
__global__ void ksm_pass1(const float* __restrict__ kq, float* __restrict__ gm,
                          float* __restrict__ gs)
{
    int d = blockIdx.x*256 + threadIdx.x;
    int b = blockIdx.y;
    int sp = blockIdx.z;
    const float* p = kq + (long)b*T_*D_ + (long)sp*(T_/KTS)*D_ + d;
    float m = -1e30f, s = 0.f;
    for (int t = 0; t < T_/KTS; t++) {
        float vv = p[(long)t*D_];
        float nm = fmaxf(m, vv);
        s = s*__expf(m - nm) + __expf(vv - nm);
        m = nm;
    }
    int idx = (sp*B_ + b)*D_ + d;
    gm[idx] = m; gs[idx] = s;
}

__global__ void ksm_pass2(const float* __restrict__ gm, const float* __restrict__ gs,
                          float* __restrict__ cm, float* __restrict__ cs)
{
    int i = blockIdx.x*256 + threadIdx.x;
    float M = -1e30f;
    #pragma unroll
    for (int sp = 0; sp < KTS; sp++) M = fmaxf(M, gm[sp*B_*D_ + i]);
    float S = 0.f;
    #pragma unroll
    for (int sp = 0; sp < KTS; sp++) S += gs[sp*B_*D_ + i]*__expf(gm[sp*B_*D_ + i] - M);
    cm[i] = M; cs[i] = 1.f/S;
}

// ---------------- att = softmax(K)^T V per (b,h), normalization fused ------
#define ABK 8
__global__ void __launch_bounds__(256)
attpart_k(const float* __restrict__ kq, const float* __restrict__ vq,
          const float* __restrict__ cm, const float* __restrict__ cs,
          float* __restrict__ part)
{
    int s  = blockIdx.x;
    int bh = blockIdx.y;
    int b = bh >> 3, h = bh & 7;
    int tid = threadIdx.x;
    long base = (long)b*T_*D_ + h*DH;
    int t0 = s * (T_/SPLITS);

    __shared__ float Ks[ABK][DH+4];
    __shared__ float Vs[ABK][DH+4];

    int r = tid >> 5, c = (tid & 31)*4;
    int tx = tid & 15, ty = tid >> 4;

    float4 M4 = *(const float4*)&cm[b*D_ + h*DH + c];
    float4 I4 = *(const float4*)&cs[b*D_ + h*DH + c];

    float acc[8][8];
    #pragma unroll
    for (int i = 0; i < 8; i++)
        #pragma unroll
        for (int j = 0; j < 8; j++) acc[i][j] = 0.f;

    for (int tt = t0; tt < t0 + T_/SPLITS; tt += ABK) {
        float4 k4 = *(const float4*)&kq[base + (long)(tt + r)*D_ + c];
        float4 v4 = *(const float4*)&vq[base + (long)(tt + r)*D_ + c];
        k4.x = __expf(k4.x - M4.x) * I4.x;
        k4.y = __expf(k4.y - M4.y) * I4.y;
        k4.z = __expf(k4.z - M4.z) * I4.z;
        k4.w = __expf(k4.w - M4.w) * I4.w;
        __syncthreads();
        *(float4*)&Ks[r][c] = k4;
        *(float4*)&Vs[r][c] = v4;
        __syncthreads();
        #pragma unroll
        for (int kk = 0; kk < ABK; kk++) {
            float ar[8], br[8];
            *(float4*)&ar[0] = *(const float4*)&Ks[kk][ty*4];
            *(float4*)&ar[4] = *(const float4*)&Ks[kk][64 + ty*4];
            *(float4*)&br[0] = *(const float4*)&Vs[kk][tx*4];
            *(float4*)&br[4] = *(const float4*)&Vs[kk][64 + tx*4];
            #pragma unroll
            for (int i = 0; i < 8; i++)
                #pragma unroll
                for (int j = 0; j < 8; j++)
                    acc[i][j] += ar[i]*br[j];
        }
    }
    float* P = part + ((long)s*(B_*H_) + bh)*(DH*DH);
    #pragma unroll
    for (int i = 0; i < 8; i++) {
        int ml = (i < 4) ? (ty*4 + i) : (64 + ty*4 + i - 4);
        #pragma unroll
        for (int j = 0; j < 8; j++) {
            int nl = (j < 4) ? (tx*4 + j) : (64 + tx*4 + j - 4);
            P[ml*DH + nl] = acc[i][j];
        }
    }
}

// reduce partials -> transposed fp16 att
__global__ void attreduce_k(const float* __restrict__ part, __half* __restrict__ attT)
{
    int i = blockIdx.x*256 + threadIdx.x;
    float s = 0.f;
    #pragma unroll
    for (int sp = 0; sp < SPLITS; sp++)
        s += part[(long)sp*(B_*H_*DH*DH) + i];
    int bh = i >> 14;
    int rem = i & 16383;
    int d = rem >> 7, l = rem & 127;
    attT[((long)bh << 14) + l*DH + d] = __float2half(s);
}

// ---------------- FiLM ----------------
__global__ void filmpart_k(const float* __restrict__ emb, const float* __restrict__ W,
                           float* __restrict__ part)
{
    int b = blockIdx.x;
    int colBase = blockIdx.y*256;
    int kz = blockIdx.z;
    __shared__ float se[256];
    int tid = threadIdx.x;
    float e = emb[(long)b*TE_ + kz*256 + tid];
    se[tid] = silu_f(e);
    __syncthreads();
    int col = colBase + tid;
    float acc = 0.f;
    const float* wp = W + (long)(kz*256)*D2 + col;
    #pragma unroll 8
    for (int k = 0; k < 256; k++) acc += se[k]*wp[(long)k*D2];
    part[((long)kz*B_ + b)*D2 + col] = acc;
}

__global__ void filmreduce_k(const float* __restrict__ part,
                             const float* __restrict__ b_emb,
                             float* __restrict__ film)
{
    int i = blockIdx.x*256 + threadIdx.x;
    int col = i & (D2-1);
    int b = i >> 11;
    float s = b_emb[col];
    #pragma unroll
    for (int kz = 0; kz < FKS; kz++)
        s += part[((long)kz*B_ + b)*D2 + col];
    film[i] = s;
}

// ---------------- launch ----------------
extern "C" void kernel_launch(void* const* d_in, const int* in_sizes, int n_in,
                              void* d_out, int out_size)
{
    const float* x     = (const float*)d_in[0];
    const float* emb   = (const float*)d_in[1];
    const float* mask  = (const float*)d_in[2];
    const float* ln_w  = (const float*)d_in[4];
    const float* ln_b  = (const float*)d_in[5];
    const float* Wq    = (const float*)d_in[6];
    const float* bq    = (const float*)d_in[7];
    const float* Wk    = (const float*)d_in[8];
    const float* bk    = (const float*)d_in[9];
    const float* Wv    = (const float*)d_in[10];
    const float* bv    = (const float*)d_in[11];
    const float* W_emb = (const float*)d_in[12];
    const float* b_emb = (const float*)d_in[13];
    const float* ln2_w = (const float*)d_in[14];
    const float* ln2_b = (const float*)d_in[15];
    const float* W_out = (const float*)d_in[16];
    const float* b_out = (const float*)d_in[17];
    float* out = (float*)d_out;

    float *k, *v, *y, *attp, *filmp, *film, *gm, *gs, *cm, *cs;
    __half *qh, *xh, *wh, *attT;
    cudaGetSymbolAddress((void**)&qh,   g_qh);
    cudaGetSymbolAddress((void**)&k,    g_k);
    cudaGetSymbolAddress((void**)&v,    g_v);
    cudaGetSymbolAddress((void**)&y,    g_y);
    cudaGetSymbolAddress((void**)&xh,   g_xh);
    cudaGetSymbolAddress((void**)&wh,   g_wh);
    cudaGetSymbolAddress((void**)&attp, g_attp);
    cudaGetSymbolAddress((void**)&attT, g_attT);
    cudaGetSymbolAddress((void**)&filmp,g_filmp);
    cudaGetSymbolAddress((void**)&film, g_film);
    cudaGetSymbolAddress((void**)&gm,   g_gm);
    cudaGetSymbolAddress((void**)&gs,   g_gs);
    cudaGetSymbolAddress((void**)&cm,   g_cm);
    cudaGetSymbolAddress((void**)&cs,   g_cs);

    cudaFuncSetAttribute(hgemm_k<EPI_QKV>,   cudaFuncAttributeMaxDynamicSharedMemorySize, SMEM_HGEMM);
    cudaFuncSetAttribute(hgemm_k<EPI_RESID>, cudaFuncAttributeMaxDynamicSharedMemorySize, SMEM_HGEMM);
    cudaFuncSetAttribute(attgemm_k,          cudaFuncAttributeMaxDynamicSharedMemorySize, SMEM_HGEMM);

    dim3 wgrid(32, 32), wblk(32, 8);

    // 1) pre-norm -> fp16
    ln_k<<<NROWS, 256>>>(x, ln_w, ln_b, xh);

    // weights: transpose -> fp16 concat [3N, K]
    wconv_k<<<wgrid, wblk>>>(Wq, wh);
    wconv_k<<<wgrid, wblk>>>(Wk, wh + D_*D_);
    wconv_k<<<wgrid, wblk>>>(Wv, wh + 2*D_*D_);

    // 2) fused Q/K/V projection; q-softmax fused into epilogue, q written fp16
    hgemm_k<EPI_QKV><<<dim3(24, NROWS/128), 256, SMEM_HGEMM>>>(
        xh, wh, qh, k, v, bq, bk, bv, mask, nullptr, nullptr);

    // 3) k-softmax stats (normalization fused into attpart)
    ksm_pass1<<<dim3(D_/256, B_, KTS), 256>>>(k, gm, gs);
    ksm_pass2<<<(B_*D_)/256, 256>>>(gm, gs, cm, cs);

    // 4) att = softmax(K)^T V per (b,h); reduce -> transposed fp16
    attpart_k<<<dim3(SPLITS, B_*H_), 256>>>(k, v, cm, cs, attp);
    attreduce_k<<<(B_*H_*DH*DH)/256, 256>>>(attp, attT);

    // 5) y = q @ att per (b,h) on HMMA
    attgemm_k<<<dim3(T_/128, B_*H_), 256, SMEM_HGEMM>>>(qh, attT, y);

    // 6) FiLM params
    filmpart_k<<<dim3(B_, D2/256, FKS), 256>>>(emb, W_emb, filmp);
    filmreduce_k<<<(B_*D2)/256, 256>>>(filmp, b_emb, film);

    // 7) LN2 + FiLM + SiLU -> fp16 (reuse xh)
    ln2film_k<<<NROWS, 256>>>(y, ln2_w, ln2_b, film, xh);

    // 8) out = x + hh @ W_out + b_out
    wconv_k<<<wgrid, wblk>>>(W_out, wh);
    hgemm_k<EPI_RESID><<<dim3(8, NROWS/128), 256, SMEM_HGEMM>>>(
        xh, wh, nullptr, nullptr, nullptr, b_out, nullptr, nullptr, nullptr, x, out);
}

// round 11
// speedup vs baseline: 3.6673x; 1.0003x over previous
#include <cuda_runtime.h>
#include <cuda_bf16.h>
#include <cuda_fp16.h>
#include <cstdint>

// Problem constants
#define B_    4
#define T_    2048
#define D_    1024
#define H_    8
#define DH    128
#define TE_   2048
#define D2    2048
#define NROWS (B_*T_)         // 8192

#define SPLITS 8
#define KTS    8
#define FKS    8

// HMMA GEMM config (fp16 single-term)
#define KC    32              // fp16 K per chunk
#define ROWB  80              // padded smem row bytes
#define MATB  (128*ROWB)      // 10240 per matrix per stage
#define STGB  (2*MATB)        // A, B
#define NSTG  3
#define SMEM_HGEMM (NSTG*STGB)  // 61440
#define SMEM_ATTG  (2*STGB)     // 40960

// ---------------- scratch (device globals) ----------------
__device__ __align__(128) __half g_qh [NROWS*D_];
__device__ __align__(128) __half g_kh [NROWS*D_];
__device__ __align__(128) __half g_vh [NROWS*D_];
__device__ __align__(128) __half g_yh [NROWS*D_];
__device__ __align__(128) __half g_xh [NROWS*D_];
__device__ __align__(128) __half g_wh [3*D_*D_];
__device__ __align__(128) float g_attp[SPLITS*B_*H_*DH*DH];
__device__ __align__(128) __half g_attT[B_*H_*DH*DH];
__device__ __align__(128) float g_filmp[FKS*B_*D2];
__device__ __align__(128) float g_film[B_*D2];
__device__ __align__(128) float g_gm  [KTS*B_*D_];
__device__ __align__(128) float g_gs  [KTS*B_*D_];
__device__ __align__(128) float g_cm  [B_*D_];
__device__ __align__(128) float g_cs  [B_*D_];

// ---------------- PTX helpers (base-ISA only) ----------------
__device__ __forceinline__ uint32_t smem_u32(const void* p) {
    uint32_t a;
    asm("{ .reg .u64 t; cvta.to.shared.u64 t, %1; cvt.u32.u64 %0, t; }" : "=r"(a) : "l"(p));
    return a;
}
__device__ __forceinline__ void cp16(uint32_t sa, const void* g) {
    asm volatile("cp.async.cg.shared.global [%0], [%1], 16;" :: "r"(sa), "l"(__cvta_generic_to_global(g)));
}
__device__ __forceinline__ void cp_commit() { asm volatile("cp.async.commit_group;" ::: "memory"); }
template<int N> __device__ __forceinline__ void cp_wait() { asm volatile("cp.async.wait_group %0;" :: "n"(N) : "memory"); }

__device__ __forceinline__ void lds_x4(uint32_t a[4], uint32_t addr) {
    asm volatile("ldmatrix.sync.aligned.m8n8.x4.shared.b16 {%0,%1,%2,%3}, [%4];"
        : "=r"(a[0]), "=r"(a[1]), "=r"(a[2]), "=r"(a[3]) : "r"(addr));
}
__device__ __forceinline__ void lds_x2(uint32_t b[2], uint32_t addr) {
    asm volatile("ldmatrix.sync.aligned.m8n8.x2.shared.b16 {%0,%1}, [%2];"
        : "=r"(b[0]), "=r"(b[1]) : "r"(addr));
}
__device__ __forceinline__ void mma16816(float d[4], const uint32_t a[4], const uint32_t b[2]) {
    asm volatile("mma.sync.aligned.m16n8k16.row.col.f32.f16.f16.f32 "
        "{%0,%1,%2,%3}, {%4,%5,%6,%7}, {%8,%9}, {%0,%1,%2,%3};"
        : "+f"(d[0]), "+f"(d[1]), "+f"(d[2]), "+f"(d[3])
        : "r"(a[0]), "r"(a[1]), "r"(a[2]), "r"(a[3]), "r"(b[0]), "r"(b[1]));
}

// ---------------- misc helpers ----------------
__device__ __forceinline__ void blockReduce2(float& a, float& b) {
    __shared__ float sa[8], sb[8];
    #pragma unroll
    for (int o = 16; o > 0; o >>= 1) {
        a += __shfl_xor_sync(0xffffffffu, a, o);
        b += __shfl_xor_sync(0xffffffffu, b, o);
    }
    int w = threadIdx.x >> 5, l = threadIdx.x & 31;
    if (l == 0) { sa[w] = a; sb[w] = b; }
    __syncthreads();
    if (threadIdx.x < 32) {
        a = (l < 8) ? sa[l] : 0.f;
        b = (l < 8) ? sb[l] : 0.f;
        #pragma unroll
        for (int o = 4; o > 0; o >>= 1) {
            a += __shfl_xor_sync(0xffffffffu, a, o);
            b += __shfl_xor_sync(0xffffffffu, b, o);
        }
        if (l == 0) { sa[0] = a; sb[0] = b; }
    }
    __syncthreads();
    a = sa[0]; b = sb[0];
}
__device__ __forceinline__ float silu_f(float x) { return x / (1.f + __expf(-x)); }

// ---------------- LayerNorm (pre-norm) -> fp16 ----------------
__global__ void ln_k(const float* __restrict__ x, const float* __restrict__ w,
                     const float* __restrict__ bb, __half* __restrict__ oh)
{
    long base = (long)blockIdx.x * D_;
    int t = threadIdx.x;
    float4 v = *(const float4*)&x[base + t*4];
    float s  = v.x + v.y + v.z + v.w;
    float ss = v.x*v.x + v.y*v.y + v.z*v.z + v.w*v.w;
    blockReduce2(s, ss);
    float mean = s * (1.f/D_);
    float var  = ss * (1.f/D_) - mean*mean;
    float rs   = rsqrtf(var + 1e-5f);
    float4 w4 = *(const float4*)&w[t*4];
    float4 b4 = *(const float4*)&bb[t*4];
    long o = base + t*4;
    oh[o+0] = __float2half((v.x-mean)*rs*w4.x + b4.x);
    oh[o+1] = __float2half((v.y-mean)*rs*w4.y + b4.y);
    oh[o+2] = __float2half((v.z-mean)*rs*w4.z + b4.z);
    oh[o+3] = __float2half((v.w-mean)*rs*w4.w + b4.w);
}

// ---------------- LayerNorm2 + FiLM + SiLU: y(fp16) -> fp16 ----------------
__global__ void ln2film_k(const __half* __restrict__ y, const float* __restrict__ w,
                          const float* __restrict__ bb, const float* __restrict__ film,
                          __half* __restrict__ oh)
{
    long base = (long)blockIdx.x * D_;
    int b = blockIdx.x >> 11;
    int t = threadIdx.x;
    uint2 raw = *(const uint2*)&y[base + t*4];
    float2 v01 = __half22float2(*(__half2*)&raw.x);
    float2 v23 = __half22float2(*(__half2*)&raw.y);
    float s  = v01.x + v01.y + v23.x + v23.y;
    float ss = v01.x*v01.x + v01.y*v01.y + v23.x*v23.x + v23.y*v23.y;
    blockReduce2(s, ss);
    float mean = s * (1.f/D_);
    float var  = ss * (1.f/D_) - mean*mean;
    float rs   = rsqrtf(var + 1e-5f);
    float4 w4 = *(const float4*)&w[t*4];
    float4 b4 = *(const float4*)&bb[t*4];
    float4 sc = *(const float4*)&film[(long)b*D2 + t*4];
    float4 sf = *(const float4*)&film[(long)b*D2 + D_ + t*4];
    long o = base + t*4;
    oh[o+0] = __float2half(silu_f(((v01.x-mean)*rs*w4.x + b4.x)*(1.f+sc.x) + sf.x));
    oh[o+1] = __float2half(silu_f(((v01.y-mean)*rs*w4.y + b4.y)*(1.f+sc.y) + sf.y));
    oh[o+2] = __float2half(silu_f(((v23.x-mean)*rs*w4.z + b4.z)*(1.f+sc.z) + sf.z));
    oh[o+3] = __float2half(silu_f(((v23.y-mean)*rs*w4.w + b4.w)*(1.f+sc.w) + sf.w));
}

// ---------------- weight transpose -> fp16: W[K,N] -> Wt[N,K] ---------
__global__ void wconv_k(const float* __restrict__ W, __half* __restrict__ th)
{
    __shared__ float tile[32][33];
    int n0 = blockIdx.x*32, k0 = blockIdx.y*32;
    int tx = threadIdx.x, ty0 = threadIdx.y;   // 32 x 8
    #pragma unroll
    for (int i = 0; i < 4; i++) {
        int ty = ty0 + i*8;
        tile[ty][tx] = W[(long)(k0+ty)*D_ + n0+tx];
    }
    __syncthreads();
    #pragma unroll
    for (int i = 0; i < 4; i++) {
        int ty = ty0 + i*8;
        th[(long)(n0+ty)*D_ + k0+tx] = __float2half(tile[tx][ty]);
    }
}

// ---------------- HMMA fp16 GEMM: C = A @ B^T, 3-stage pipeline ------------
static constexpr int EPI_QKV   = 0;   // sel 0: bias+softmax->qh; 1: bias+kmask->kh; 2: (..)*mask->vh
static constexpr int EPI_RESID = 1;   // + bias + residual -> fp32 out

template<int EPI>
__global__ void __launch_bounds__(256, 2)
hgemm_k(const __half* __restrict__ A, const __half* __restrict__ Bm,
        __half* __restrict__ Cq,
        __half* __restrict__ C1, __half* __restrict__ C2,
        const float* __restrict__ b0, const float* __restrict__ b1,
        const float* __restrict__ b2,
        const float* __restrict__ msk, const float* __restrict__ resid,
        float* __restrict__ Cf)
{
    extern __shared__ char smem[];
    uint32_t sb = smem_u32(smem);
    int tid = threadIdx.x, lane = tid & 31, wid = tid >> 5;
    int m0 = blockIdx.y * 128;
    int nblk = blockIdx.x;
    int n0g = nblk * 128;
    int n0  = (nblk & 7) * 128;
    int sel = nblk >> 3;
    int wm0 = (wid >> 2) * 64;
    int wn0 = (wid & 3) * 32;
    const long Kd = D_;

    float acc[4][4][4];
    #pragma unroll
    for (int i = 0; i < 4; i++)
        #pragma unroll
        for (int j = 0; j < 4; j++)
            #pragma unroll
            for (int r = 0; r < 4; r++) acc[i][j][r] = 0.f;

    auto load_stage = [&](int s, int kc) {
        uint32_t st = sb + s * STGB;
        const __half* gp[2] = {
            A  + (long)m0  * Kd + kc,
            Bm + (long)n0g * Kd + kc };
        #pragma unroll
        for (int t = 0; t < 2; t++) {
            #pragma unroll
            for (int i = 0; i < 2; i++) {
                int g = tid + i * 256;
                int r = g >> 2, c = g & 3;
                cp16(st + t*MATB + r*ROWB + c*16,
                     (const char*)gp[t] + (long)r * Kd * 2 + c*16);
            }
        }
        cp_commit();
    };

    int nk = Kd / KC;                  // 32
    load_stage(0, 0);
    load_stage(1, KC);
    load_stage(2, 2*KC);

    for (int ch = 0; ch < nk; ch++) {
        cp_wait<2>();
        __syncthreads();
        uint32_t st = sb + (ch % NSTG) * STGB;

        #pragma unroll
        for (int ks = 0; ks < 2; ks++) {
            uint32_t bh[4][2];
            #pragma unroll
            for (int ni = 0; ni < 4; ni++) {
                int rB = wn0 + ni*8 + (lane & 7);
                int cB = ks*16 + ((lane >> 3) & 1) * 8;
                lds_x2(bh[ni], st + MATB + (uint32_t)(rB*ROWB + cB*2));
            }
            #pragma unroll
            for (int mi = 0; mi < 4; mi++) {
                int rA = wm0 + mi*16 + (lane & 15);
                int cA = ks*16 + (lane >> 4) * 8;
                uint32_t ah[4];
                lds_x4(ah, st + (uint32_t)(rA*ROWB + cA*2));
                #pragma unroll
                for (int ni = 0; ni < 4; ni++)
                    mma16816(acc[mi][ni], ah, bh[ni]);
            }
        }
        __syncthreads();
        if (ch + 3 < nk) load_stage((ch + 3) % NSTG, (ch + 3) * KC);
        else cp_commit();              // keep group count uniform for cp_wait<2>
    }

    int gq = lane >> 2, tq = lane & 3;

    if (EPI == EPI_QKV && sel == 0) {
        // ---- fused per-head softmax over the 128 columns of this tile ----
        float* redmax = (float*)smem;            // [128][4]
        float* redsum = (float*)(smem + 2048);   // [128][4]
        int w4 = wid & 3;
        #pragma unroll
        for (int mi = 0; mi < 4; mi++)
            #pragma unroll
            for (int half = 0; half < 2; half++) {
                int rloc = wm0 + mi*16 + gq + half*8;
                float pm = -1e30f;
                #pragma unroll
                for (int ni = 0; ni < 4; ni++)
                    #pragma unroll
                    for (int e = 0; e < 2; e++) {
                        int ngc = n0 + wn0 + ni*8 + tq*2 + e;
                        float val = acc[mi][ni][half*2 + e] + b0[ngc];
                        acc[mi][ni][half*2 + e] = val;
                        pm = fmaxf(pm, val);
                    }
                pm = fmaxf(pm, __shfl_xor_sync(0xffffffffu, pm, 1));
                pm = fmaxf(pm, __shfl_xor_sync(0xffffffffu, pm, 2));
                if (tq == 0) redmax[rloc*4 + w4] = pm;
            }
        __syncthreads();
        #pragma unroll
        for (int mi = 0; mi < 4; mi++)
            #pragma unroll
            for (int half = 0; half < 2; half++) {
                int rloc = wm0 + mi*16 + gq + half*8;
                float rm = fmaxf(fmaxf(redmax[rloc*4+0], redmax[rloc*4+1]),
                                 fmaxf(redmax[rloc*4+2], redmax[rloc*4+3]));
                float ps = 0.f;
                #pragma unroll
                for (int ni = 0; ni < 4; ni++)
                    #pragma unroll
                    for (int e = 0; e < 2; e++) {
                        float v = __expf(acc[mi][ni][half*2 + e] - rm);
                        acc[mi][ni][half*2 + e] = v;
                        ps += v;
                    }
                ps += __shfl_xor_sync(0xffffffffu, ps, 1);
                ps += __shfl_xor_sync(0xffffffffu, ps, 2);
                if (tq == 0) redsum[rloc*4 + w4] = ps;
            }
        __syncthreads();
        #pragma unroll
        for (int mi = 0; mi < 4; mi++)
            #pragma unroll
            for (int half = 0; half < 2; half++) {
                int rloc = wm0 + mi*16 + gq + half*8;
                float inv = 1.f / (redsum[rloc*4+0] + redsum[rloc*4+1]
                                 + redsum[rloc*4+2] + redsum[rloc*4+3]);
                long mg = m0 + rloc;
                #pragma unroll
                for (int ni = 0; ni < 4; ni++)
                    #pragma unroll
                    for (int e = 0; e < 2; e++) {
                        int ngc = n0 + wn0 + ni*8 + tq*2 + e;
                        Cq[mg*D_ + ngc] = __float2half(acc[mi][ni][half*2 + e] * inv);
                    }
            }
        return;
    }

    if (EPI == EPI_QKV) {
        // sel==1 -> k (fp16, bias+mask offset; -1e6 saturates to -inf: benign)
        // sel==2 -> v (fp16, (..+bias)*mask)
        __half* C = (sel == 1) ? C1 : C2;
        const float* bias = (sel == 1) ? b1 : b2;
        bool do_kadd = (sel == 1);
        #pragma unroll
        for (int mi = 0; mi < 4; mi++)
            #pragma unroll
            for (int half = 0; half < 2; half++) {
                int mg = m0 + wm0 + mi*16 + gq + half*8;
                float kadd = 0.f, vmul = 1.f;
                if (do_kadd) kadd = (1.0f - msk[mg]) * -1000000.0f;
                else         vmul = msk[mg];
                #pragma unroll
                for (int ni = 0; ni < 4; ni++) {
                    int ng = n0 + wn0 + ni*8 + tq*2;
                    #pragma unroll
                    for (int e = 0; e < 2; e++) {
                        float val = acc[mi][ni][half*2 + e] + bias[ng + e];
                        if (do_kadd) val += kadd; else val *= vmul;
                        C[(long)mg*D_ + ng + e] = __float2half(val);
                    }
                }
            }
        return;
    }

    // EPI_RESID: out = acc + bias + residual (fp32)
    #pragma unroll
    for (int mi = 0; mi < 4; mi++)
        #pragma unroll
        for (int half = 0; half < 2; half++) {
            int mg = m0 + wm0 + mi*16 + gq + half*8;
            #pragma unroll
            for (int ni = 0; ni < 4; ni++) {
                int ng = n0 + wn0 + ni*8 + tq*2;
                #pragma unroll
                for (int e = 0; e < 2; e++) {
                    float val = acc[mi][ni][half*2 + e] + b0[ng + e]
                              + resid[(long)mg*D_ + ng + e];
                    Cf[(long)mg*D_ + ng + e] = val;
                }
            }
        }
}

// ---------------- HMMA step 5: y = qh @ attT^T per (b,h), fp16 out ---------
__global__ void __launch_bounds__(256, 2)
attgemm_k(const __half* __restrict__ qh, const __half* __restrict__ attT,
          __half* __restrict__ y)
{
    extern __shared__ char smem[];
    uint32_t sb = smem_u32(smem);
    int tid = threadIdx.x, lane = tid & 31, wid = tid >> 5;
    int m0 = blockIdx.x * 128;
    int bh = blockIdx.y;
    int b = bh >> 3, h = bh & 7;
    const __half* A  = qh   + (long)b*T_*D_ + (long)m0*D_ + h*DH;
    const __half* Bm = attT + (long)bh*DH*DH;
    __half*       C  = y    + (long)b*T_*D_ + (long)m0*D_ + h*DH;
    int wm0 = (wid >> 2) * 64;
    int wn0 = (wid & 3) * 32;

    float acc[4][4][4];
    #pragma unroll
    for (int i = 0; i < 4; i++)
        #pragma unroll
        for (int j = 0; j < 4; j++)
            #pragma unroll
            for (int r = 0; r < 4; r++) acc[i][j][r] = 0.f;

    auto load_stage = [&](int s, int kc) {
        uint32_t st = sb + s * STGB;
        #pragma unroll
        for (int i = 0; i < 2; i++) {
            int g = tid + i * 256;
            int r = g >> 2, c = g & 3;
            cp16(st + r*ROWB + c*16,
                 (const char*)(A + (long)r * D_ + kc) + c*16);
            cp16(st + MATB + r*ROWB + c*16,
                 (const char*)(Bm + r * DH + kc) + c*16);
        }
        cp_commit();
    };

    load_stage(0, 0);
    load_stage(1, KC);
    const int nk = DH / KC;   // 4

    for (int ch = 0; ch < nk; ch++) {
        if (ch == nk - 1) cp_wait<0>(); else cp_wait<1>();
        __syncthreads();
        uint32_t st = sb + (ch & 1) * STGB;
        #pragma unroll
        for (int ks = 0; ks < 2; ks++) {
            uint32_t bh2[4][2];
            #pragma unroll
            for (int ni = 0; ni < 4; ni++) {
                int rB = wn0 + ni*8 + (lane & 7);
                int cB = ks*16 + ((lane >> 3) & 1) * 8;
                lds_x2(bh2[ni], st + MATB + (uint32_t)(rB*ROWB + cB*2));
            }
            #pragma unroll
            for (int mi = 0; mi < 4; mi++) {
                int rA = wm0 + mi*16 + (lane & 15);
                int cA = ks*16 + (lane >> 4) * 8;
                uint32_t ah[4];
                lds_x4(ah, st + (uint32_t)(rA*ROWB + cA*2));
                #pragma unroll
                for (int ni = 0; ni < 4; ni++)
                    mma16816(acc[mi][ni], ah, bh2[ni]);
            }
        }
        __syncthreads();
        if (ch + 2 < nk) load_stage(ch & 1, (ch + 2) * KC);
    }

    int gq = lane >> 2, tq = lane & 3;
    #pragma unroll
    for (int mi = 0; mi < 4; mi++)
        #pragma unroll
        for (int half = 0; half < 2; half++) {
            long mg = wm0 + mi*16 + gq + half*8;
            #pragma unroll
            for (int ni = 0; ni < 4; ni++) {
                int ng = wn0 + ni*8 + tq*2;
                __half2 hv = __floats2half2_rn(acc[mi][ni][half*2], acc[mi][ni][half*2+1]);
                *(__half2*)&C[mg*D_ + ng] = hv;
            }
        }
}

// ---------------- k softmax stats over time (k fp16) ----------------
__global__ void ksm_pass1(const __half* __restrict__ kq, float* __restrict__ gm,
                          float* __restrict__ gs)
{
    int d = blockIdx.x*256 + threadIdx.x;
    int b = blockIdx.y;
    int sp = blockIdx.z;
    const __half* p = kq + (long)b*T_*D_ + (long)sp*(T_/KTS)*D_ + d;
    float m = -1e30f, s = 0.f;
    for (int t = 0; t < T_/KTS; t++) {
        float vv = __half2float(p[(long)t*D_]);
        float nm = fmaxf(m, vv);
        s = s*__expf(m - nm) + __expf(vv - nm);
        m = nm;
    }
    int idx = (sp*B_ + b)*D_ + d;
    gm[idx] = m; gs[idx] = s;
}

__global__ void ksm_pass2(const float* __restrict__ gm, const float* __restrict__ gs,
                          float* __restrict__ cm, float* __restrict__ cs)
{
    int i = blockIdx.x*256 + threadIdx.x;
    float M = -1e30f;
    #pragma unroll
    for (int sp = 0; sp < KTS; sp++) M = fmaxf(M, gm[sp*B_*D_ + i]);
    float S = 0.f;
    #pragma unroll
    for (int sp = 0; sp < KTS; sp++) S += gs[sp*B_*D_ + i]*__expf(gm[sp*B_*D_ + i] - M);
    cm[i] = M; cs[i] = 1.f/S;
}

// ---------------- att = softmax(K)^T V per (b,h), k/v fp16 ------
#define ABK 8
__global__ void __launch_bounds__(256)
attpart_k(const __half* __restrict__ kq, const __half* __restrict__ vq,
          const float* __restrict__ cm, const float* __restrict__ cs,
          float* __restrict__ part)
{
    int s  = blockIdx.x;
    int bh = blockIdx.y;
    int b = bh >> 3, h = bh & 7;
    int tid = threadIdx.x;
    long base = (long)b*T_*D_ + h*DH;
    int t0 = s * (T_/SPLITS);

    __shared__ float Ks[ABK][DH+4];
    __shared__ float Vs[ABK][DH+4];

    int r = tid >> 5, c = (tid & 31)*4;
    int tx = tid & 15, ty = tid >> 4;

    float4 M4 = *(const float4*)&cm[b*D_ + h*DH + c];
    float4 I4 = *(const float4*)&cs[b*D_ + h*DH + c];

    float acc[8][8];
    #pragma unroll
    for (int i = 0; i < 8; i++)
        #pragma unroll
        for (int j = 0; j < 8; j++) acc[i][j] = 0.f;

    for (int tt = t0; tt < t0 + T_/SPLITS; tt += ABK) {
        uint2 kraw = *(const uint2*)&kq[base + (long)(tt + r)*D_ + c];
        uint2 vraw = *(const uint2*)&vq[base + (long)(tt + r)*D_ + c];
        float2 k01 = __half22float2(*(__half2*)&kraw.x);
        float2 k23 = __half22float2(*(__half2*)&kraw.y);
        float2 v01 = __half22float2(*(__half2*)&vraw.x);
        float2 v23 = __half22float2(*(__half2*)&vraw.y);
        float4 k4, v4;
        k4.x = __expf(k01.x - M4.x) * I4.x;
        k4.y = __expf(k01.y - M4.y) * I4.y;
        k4.z = __expf(k23.x - M4.z) * I4.z;
        k4.w = __expf(k23.y - M4.w) * I4.w;
        v4.x = v01.x; v4.y = v01.y; v4.z = v23.x; v4.w = v23.y;
        __syncthreads();
        *(float4*)&Ks[r][c] = k4;
        *(float4*)&Vs[r][c] = v4;
        __syncthreads();
        #pragma unroll
        for (int kk = 0; kk < ABK; kk++) {
            float ar[8], br[8];
            *(float4*)&ar[0] = *(const float4*)&Ks[kk][ty*4];
            *(float4*)&ar[4] = *(const float4*)&Ks[kk][64 + ty*4];
            *(float4*)&br[0] = *(const float4*)&Vs[kk][tx*4];
            *(float4*)&br[4] = *(const float4*)&Vs[kk][64 + tx*4];
            #pragma unroll
            for (int i = 0; i < 8; i++)
                #pragma unroll
                for (int j = 0; j < 8; j++)
                    acc[i][j] += ar[i]*br[j];
        }
    }
    float* P = part + ((long)s*(B_*H_) + bh)*(DH*DH);
    #pragma unroll
    for (int i = 0; i < 8; i++) {
        int ml = (i < 4) ? (ty*4 + i) : (64 + ty*4 + i - 4);
        #pragma unroll
        for (int j = 0; j < 8; j++) {
            int nl = (j < 4) ? (tx*4 + j) : (64 + tx*4 + j - 4);
            P[ml*DH + nl] = acc[i][j];
        }
    }
}

// reduce partials -> transposed fp16 att
__global__ void attreduce_k(const float* __restrict__ part, __half* __restrict__ attT)
{
    int i = blockIdx.x*256 + threadIdx.x;
    float s = 0.f;
    #pragma unroll
    for (int sp = 0; sp < SPLITS; sp++)
        s += part[(long)sp*(B_*H_*DH*DH) + i];
    int bh = i >> 14;
    int rem = i & 16383;
    int d = rem >> 7, l = rem & 127;
    attT[((long)bh << 14) + l*DH + d] = __float2half(s);
}

// ---------------- FiLM ----------------
__global__ void filmpart_k(const float* __restrict__ emb, const float* __restrict__ W,
                           float* __restrict__ part)
{
    int b = blockIdx.x;
    int colBase = blockIdx.y*256;
    int kz = blockIdx.z;
    __shared__ float se[256];
    int tid = threadIdx.x;
    float e = emb[(long)b*TE_ + kz*256 + tid];
    se[tid] = silu_f(e);
    __syncthreads();
    int col = colBase + tid;
    float acc = 0.f;
    const float* wp = W + (long)(kz*256)*D2 + col;
    #pragma unroll 8
    for (int k = 0; k < 256; k++) acc += se[k]*wp[(long)k*D2];
    part[((long)kz*B_ + b)*D2 + col] = acc;
}

__global__ void filmreduce_k(const float* __restrict__ part,
                             const float* __restrict__ b_emb,
                             float* __restrict__ film)
{
    int i = blockIdx.x*256 + threadIdx.x;
    int col = i & (D2-1);
    int b = i >> 11;
    float s = b_emb[col];
    #pragma unroll
    for (int kz = 0; kz < FKS; kz++)
        s += part[((long)kz*B_ + b)*D2 + col];
    film[i] = s;
}

// ---------------- launch ----------------
extern "C" void kernel_launch(void* const* d_in, const int* in_sizes, int n_in,
                              void* d_out, int out_size)
{
    const float* x     = (const float*)d_in[0];
    const float* emb   = (const float*)d_in[1];
    const float* mask  = (const float*)d_in[2];
    const float* ln_w  = (const float*)d_in[4];
    const float* ln_b  = (const float*)d_in[5];
    const float* Wq    = (const float*)d_in[6];
    const float* bq    = (const float*)d_in[7];
    const float* Wk    = (const float*)d_in[8];
    const float* bk    = (const float*)d_in[9];
    const float* Wv    = (const float*)d_in[10];
    const float* bv    = (const float*)d_in[11];
    const float* W_emb = (const float*)d_in[12];
    const float* b_emb = (const float*)d_in[13];
    const float* ln2_w = (const float*)d_in[14];
    const float* ln2_b = (const float*)d_in[15];
    const float* W_out = (const float*)d_in[16];
    const float* b_out = (const float*)d_in[17];
    float* out = (float*)d_out;

    float *attp, *filmp, *film, *gm, *gs, *cm, *cs;
    __half *qh, *kh, *vh, *yh, *xh, *wh, *attT;
    cudaGetSymbolAddress((void**)&qh,   g_qh);
    cudaGetSymbolAddress((void**)&kh,   g_kh);
    cudaGetSymbolAddress((void**)&vh,   g_vh);
    cudaGetSymbolAddress((void**)&yh,   g_yh);
    cudaGetSymbolAddress((void**)&xh,   g_xh);
    cudaGetSymbolAddress((void**)&wh,   g_wh);
    cudaGetSymbolAddress((void**)&attp, g_attp);
    cudaGetSymbolAddress((void**)&attT, g_attT);
    cudaGetSymbolAddress((void**)&filmp,g_filmp);
    cudaGetSymbolAddress((void**)&film, g_film);
    cudaGetSymbolAddress((void**)&gm,   g_gm);
    cudaGetSymbolAddress((void**)&gs,   g_gs);
    cudaGetSymbolAddress((void**)&cm,   g_cm);
    cudaGetSymbolAddress((void**)&cs,   g_cs);

    cudaFuncSetAttribute(hgemm_k<EPI_QKV>,   cudaFuncAttributeMaxDynamicSharedMemorySize, SMEM_HGEMM);
    cudaFuncSetAttribute(hgemm_k<EPI_RESID>, cudaFuncAttributeMaxDynamicSharedMemorySize, SMEM_HGEMM);
    cudaFuncSetAttribute(attgemm_k,          cudaFuncAttributeMaxDynamicSharedMemorySize, SMEM_ATTG);

    dim3 wgrid(32, 32), wblk(32, 8);

    // 1) pre-norm -> fp16
    ln_k<<<NROWS, 256>>>(x, ln_w, ln_b, xh);

    // weights: transpose -> fp16 concat [3N, K]
    wconv_k<<<wgrid, wblk>>>(Wq, wh);
    wconv_k<<<wgrid, wblk>>>(Wk, wh + D_*D_);
    wconv_k<<<wgrid, wblk>>>(Wv, wh + 2*D_*D_);

    // 2) fused Q/K/V projection; q-softmax fused, all outputs fp16
    hgemm_k<EPI_QKV><<<dim3(24, NROWS/128), 256, SMEM_HGEMM>>>(
        xh, wh, qh, kh, vh, bq, bk, bv, mask, nullptr, nullptr);

    // 3) k-softmax stats (normalization fused into attpart)
    ksm_pass1<<<dim3(D_/256, B_, KTS), 256>>>(kh, gm, gs);
    ksm_pass2<<<(B_*D_)/256, 256>>>(gm, gs, cm, cs);

    // 4) att = softmax(K)^T V per (b,h); reduce -> transposed fp16
    attpart_k<<<dim3(SPLITS, B_*H_), 256>>>(kh, vh, cm, cs, attp);
    attreduce_k<<<(B_*H_*DH*DH)/256, 256>>>(attp, attT);

    // 5) y = q @ att per (b,h) on HMMA, fp16 out
    attgemm_k<<<dim3(T_/128, B_*H_), 256, SMEM_ATTG>>>(qh, attT, yh);

    // 6) FiLM params
    filmpart_k<<<dim3(B_, D2/256, FKS), 256>>>(emb, W_emb, filmp);
    filmreduce_k<<<(B_*D2)/256, 256>>>(filmp, b_emb, film);

    // 7) LN2 + FiLM + SiLU -> fp16 (reuse xh)
    ln2film_k<<<NROWS, 256>>>(yh, ln2_w, ln2_b, film, xh);

    // 8) out = x + hh @ W_out + b_out
    wconv_k<<<wgrid, wblk>>>(W_out, wh);
    hgemm_k<EPI_RESID><<<dim3(8, NROWS/128), 256, SMEM_HGEMM>>>(
        xh, wh, nullptr, nullptr, nullptr, b_out, nullptr, nullptr, nullptr, x, out);
}

// round 15
// speedup vs baseline: 4.0779x; 1.1120x over previous
#include <cuda_runtime.h>
#include <cuda_bf16.h>
#include <cuda_fp16.h>
#include <cstdint>

// Problem constants
#define B_    4
#define T_    2048
#define D_    1024
#define H_    8
#define DH    128
#define TE_   2048
#define D2    2048
#define NROWS (B_*T_)         // 8192

#define SPLITS 8
#define KTS    8
#define FKS    8

// HMMA GEMM config (fp16 single-term)
#define KC    32              // fp16 K per chunk
#define ROWB  80              // padded smem row bytes
#define MATB  (128*ROWB)      // 10240 per matrix per stage
#define STGB  (2*MATB)        // A, B
#define NSTG  3
#define SMEM_HGEMM (NSTG*STGB)  // 61440
#define SMEM_ATTG  (2*STGB)     // 40960

// ---------------- scratch (device globals) ----------------
__device__ __align__(128) __half g_qh [NROWS*D_];
__device__ __align__(128) __half g_kh [NROWS*D_];
__device__ __align__(128) __half g_vh [NROWS*D_];
__device__ __align__(128) __half g_yh [NROWS*D_];
__device__ __align__(128) __half g_xh [NROWS*D_];
__device__ __align__(128) __half g_wh [4*D_*D_];
__device__ __align__(128) float g_attp[SPLITS*B_*H_*DH*DH];
__device__ __align__(128) __half g_attT[B_*H_*DH*DH];
__device__ __align__(128) float g_filmp[FKS*B_*D2];
__device__ __align__(128) float g_film[B_*D2];
__device__ __align__(128) float g_gm  [KTS*B_*D_];
__device__ __align__(128) float g_gs  [KTS*B_*D_];
__device__ __align__(128) float g_cm  [B_*D_];
__device__ __align__(128) float g_cs  [B_*D_];

// ---------------- PTX helpers (base-ISA only) ----------------
__device__ __forceinline__ uint32_t smem_u32(const void* p) {
    uint32_t a;
    asm("{ .reg .u64 t; cvta.to.shared.u64 t, %1; cvt.u32.u64 %0, t; }" : "=r"(a) : "l"(p));
    return a;
}
__device__ __forceinline__ void cp16(uint32_t sa, const void* g) {
    asm volatile("cp.async.cg.shared.global [%0], [%1], 16;" :: "r"(sa), "l"(__cvta_generic_to_global(g)));
}
__device__ __forceinline__ void cp_commit() { asm volatile("cp.async.commit_group;" ::: "memory"); }
template<int N> __device__ __forceinline__ void cp_wait() { asm volatile("cp.async.wait_group %0;" :: "n"(N) : "memory"); }

__device__ __forceinline__ void lds_x4(uint32_t a[4], uint32_t addr) {
    asm volatile("ldmatrix.sync.aligned.m8n8.x4.shared.b16 {%0,%1,%2,%3}, [%4];"
        : "=r"(a[0]), "=r"(a[1]), "=r"(a[2]), "=r"(a[3]) : "r"(addr));
}
__device__ __forceinline__ void lds_x2(uint32_t b[2], uint32_t addr) {
    asm volatile("ldmatrix.sync.aligned.m8n8.x2.shared.b16 {%0,%1}, [%2];"
        : "=r"(b[0]), "=r"(b[1]) : "r"(addr));
}
__device__ __forceinline__ void mma16816(float d[4], const uint32_t a[4], const uint32_t b[2]) {
    asm volatile("mma.sync.aligned.m16n8k16.row.col.f32.f16.f16.f32 "
        "{%0,%1,%2,%3}, {%4,%5,%6,%7}, {%8,%9}, {%0,%1,%2,%3};"
        : "+f"(d[0]), "+f"(d[1]), "+f"(d[2]), "+f"(d[3])
        : "r"(a[0]), "r"(a[1]), "r"(a[2]), "r"(a[3]), "r"(b[0]), "r"(b[1]));
}

// ---------------- misc helpers ----------------
__device__ __forceinline__ void blockReduce2(float& a, float& b) {
    __shared__ float sa[8], sb[8];
    #pragma unroll
    for (int o = 16; o > 0; o >>= 1) {
        a += __shfl_xor_sync(0xffffffffu, a, o);
        b += __shfl_xor_sync(0xffffffffu, b, o);
    }
    int w = threadIdx.x >> 5, l = threadIdx.x & 31;
    if (l == 0) { sa[w] = a; sb[w] = b; }
    __syncthreads();
    if (threadIdx.x < 32) {
        a = (l < 8) ? sa[l] : 0.f;
        b = (l < 8) ? sb[l] : 0.f;
        #pragma unroll
        for (int o = 4; o > 0; o >>= 1) {
            a += __shfl_xor_sync(0xffffffffu, a, o);
            b += __shfl_xor_sync(0xffffffffu, b, o);
        }
        if (l == 0) { sa[0] = a; sb[0] = b; }
    }
    __syncthreads();
    a = sa[0]; b = sb[0];
}
__device__ __forceinline__ float silu_f(float x) { return x / (1.f + __expf(-x)); }

// ---------------- LayerNorm (pre-norm) -> fp16 ----------------
__global__ void ln_k(const float* __restrict__ x, const float* __restrict__ w,
                     const float* __restrict__ bb, __half* __restrict__ oh)
{
    long base = (long)blockIdx.x * D_;
    int t = threadIdx.x;
    float4 v = *(const float4*)&x[base + t*4];
    float s  = v.x + v.y + v.z + v.w;
    float ss = v.x*v.x + v.y*v.y + v.z*v.z + v.w*v.w;
    blockReduce2(s, ss);
    float mean = s * (1.f/D_);
    float var  = ss * (1.f/D_) - mean*mean;
    float rs   = rsqrtf(var + 1e-5f);
    float4 w4 = *(const float4*)&w[t*4];
    float4 b4 = *(const float4*)&bb[t*4];
    long o = base + t*4;
    oh[o+0] = __float2half((v.x-mean)*rs*w4.x + b4.x);
    oh[o+1] = __float2half((v.y-mean)*rs*w4.y + b4.y);
    oh[o+2] = __float2half((v.z-mean)*rs*w4.z + b4.z);
    oh[o+3] = __float2half((v.w-mean)*rs*w4.w + b4.w);
}

// ---------------- LayerNorm2 + FiLM + SiLU: y(fp16) -> fp16 ----------------
__global__ void ln2film_k(const __half* __restrict__ y, const float* __restrict__ w,
                          const float* __restrict__ bb, const float* __restrict__ film,
                          __half* __restrict__ oh)
{
    long base = (long)blockIdx.x * D_;
    int b = blockIdx.x >> 11;
    int t = threadIdx.x;
    uint2 raw = *(const uint2*)&y[base + t*4];
    float2 v01 = __half22float2(*(__half2*)&raw.x);
    float2 v23 = __half22float2(*(__half2*)&raw.y);
    float s  = v01.x + v01.y + v23.x + v23.y;
    float ss = v01.x*v01.x + v01.y*v01.y + v23.x*v23.x + v23.y*v23.y;
    blockReduce2(s, ss);
    float mean = s * (1.f/D_);
    float var  = ss * (1.f/D_) - mean*mean;
    float rs   = rsqrtf(var + 1e-5f);
    float4 w4 = *(const float4*)&w[t*4];
    float4 b4 = *(const float4*)&bb[t*4];
    float4 sc = *(const float4*)&film[(long)b*D2 + t*4];
    float4 sf = *(const float4*)&film[(long)b*D2 + D_ + t*4];
    long o = base + t*4;
    oh[o+0] = __float2half(silu_f(((v01.x-mean)*rs*w4.x + b4.x)*(1.f+sc.x) + sf.x));
    oh[o+1] = __float2half(silu_f(((v01.y-mean)*rs*w4.y + b4.y)*(1.f+sc.y) + sf.y));
    oh[o+2] = __float2half(silu_f(((v23.x-mean)*rs*w4.z + b4.z)*(1.f+sc.z) + sf.z));
    oh[o+3] = __float2half(silu_f(((v23.y-mean)*rs*w4.w + b4.w)*(1.f+sc.w) + sf.w));
}

// ---------------- 4-way weight transpose -> fp16: W[K,N] -> Wt[N,K] --------
__global__ void wconv4_k(const float* __restrict__ W0, const float* __restrict__ W1,
                         const float* __restrict__ W2, const float* __restrict__ W3,
                         __half* __restrict__ th)
{
    __shared__ float tile[32][33];
    int slot = blockIdx.z;
    const float* W = (slot == 0) ? W0 : (slot == 1) ? W1 : (slot == 2) ? W2 : W3;
    __half* out = th + (long)slot * D_ * D_;
    int n0 = blockIdx.x*32, k0 = blockIdx.y*32;
    int tx = threadIdx.x, ty0 = threadIdx.y;   // 32 x 8
    #pragma unroll
    for (int i = 0; i < 4; i++) {
        int ty = ty0 + i*8;
        tile[ty][tx] = W[(long)(k0+ty)*D_ + n0+tx];
    }
    __syncthreads();
    #pragma unroll
    for (int i = 0; i < 4; i++) {
        int ty = ty0 + i*8;
        out[(long)(n0+ty)*D_ + k0+tx] = __float2half(tile[tx][ty]);
    }
}

// ---------------- HMMA fp16 GEMM: C = A @ B^T, 3-stage pipeline ------------
static constexpr int EPI_QKV   = 0;
static constexpr int EPI_RESID = 1;

template<int EPI>
__global__ void __launch_bounds__(256, 2)
hgemm_k(const __half* __restrict__ A, const __half* __restrict__ Bm,
        __half* __restrict__ Cq,
        __half* __restrict__ C1, __half* __restrict__ C2,
        const float* __restrict__ b0, const float* __restrict__ b1,
        const float* __restrict__ b2,
        const float* __restrict__ msk, const float* __restrict__ resid,
        float* __restrict__ Cf)
{
    extern __shared__ char smem[];
    uint32_t sb = smem_u32(smem);
    int tid = threadIdx.x, lane = tid & 31, wid = tid >> 5;
    int m0 = blockIdx.y * 128;
    int nblk = blockIdx.x;
    int n0g = nblk * 128;
    int n0  = (nblk & 7) * 128;
    int sel = nblk >> 3;
    int wm0 = (wid >> 2) * 64;
    int wn0 = (wid & 3) * 32;
    const long Kd = D_;

    float acc[4][4][4];
    #pragma unroll
    for (int i = 0; i < 4; i++)
        #pragma unroll
        for (int j = 0; j < 4; j++)
            #pragma unroll
            for (int r = 0; r < 4; r++) acc[i][j][r] = 0.f;

    auto load_stage = [&](int s, int kc) {
        uint32_t st = sb + s * STGB;
        const __half* gp[2] = {
            A  + (long)m0  * Kd + kc,
            Bm + (long)n0g * Kd + kc };
        #pragma unroll
        for (int t = 0; t < 2; t++) {
            #pragma unroll
            for (int i = 0; i < 2; i++) {
                int g = tid + i * 256;
                int r = g >> 2, c = g & 3;
                cp16(st + t*MATB + r*ROWB + c*16,
                     (const char*)gp[t] + (long)r * Kd * 2 + c*16);
            }
        }
        cp_commit();
    };

    int nk = Kd / KC;                  // 32
    load_stage(0, 0);
    load_stage(1, KC);
    load_stage(2, 2*KC);

    for (int ch = 0; ch < nk; ch++) {
        cp_wait<2>();
        __syncthreads();
        uint32_t st = sb + (ch % NSTG) * STGB;

        #pragma unroll
        for (int ks = 0; ks < 2; ks++) {
            uint32_t bh[4][2];
            #pragma unroll
            for (int ni = 0; ni < 4; ni++) {
                int rB = wn0 + ni*8 + (lane & 7);
                int cB = ks*16 + ((lane >> 3) & 1) * 8;
                lds_x2(bh[ni], st + MATB + (uint32_t)(rB*ROWB + cB*2));
            }
            #pragma unroll
            for (int mi = 0; mi < 4; mi++) {
                int rA = wm0 + mi*16 + (lane & 15);
                int cA = ks*16 + (lane >> 4) * 8;
                uint32_t ah[4];
                lds_x4(ah, st + (uint32_t)(rA*ROWB + cA*2));
                #pragma unroll
                for (int ni = 0; ni < 4; ni++)
                    mma16816(acc[mi][ni], ah, bh[ni]);
            }
        }
        __syncthreads();
        if (ch + 3 < nk) load_stage((ch + 3) % NSTG, (ch + 3) * KC);
        else cp_commit();
    }

    int gq = lane >> 2, tq = lane & 3;

    if (EPI == EPI_QKV && sel == 0) {
        float* redmax = (float*)smem;            // [128][4]
        float* redsum = (float*)(smem + 2048);   // [128][4]
        int w4 = wid & 3;
        #pragma unroll
        for (int mi = 0; mi < 4; mi++)
            #pragma unroll
            for (int half = 0; half < 2; half++) {
                int rloc = wm0 + mi*16 + gq + half*8;
                float pm = -1e30f;
                #pragma unroll
                for (int ni = 0; ni < 4; ni++)
                    #pragma unroll
                    for (int e = 0; e < 2; e++) {
                        int ngc = n0 + wn0 + ni*8 + tq*2 + e;
                        float val = acc[mi][ni][half*2 + e] + b0[ngc];
                        acc[mi][ni][half*2 + e] = val;
                        pm = fmaxf(pm, val);
                    }
                pm = fmaxf(pm, __shfl_xor_sync(0xffffffffu, pm, 1));
                pm = fmaxf(pm, __shfl_xor_sync(0xffffffffu, pm, 2));
                if (tq == 0) redmax[rloc*4 + w4] = pm;
            }
        __syncthreads();
        #pragma unroll
        for (int mi = 0; mi < 4; mi++)
            #pragma unroll
            for (int half = 0; half < 2; half++) {
                int rloc = wm0 + mi*16 + gq + half*8;
                float rm = fmaxf(fmaxf(redmax[rloc*4+0], redmax[rloc*4+1]),
                                 fmaxf(redmax[rloc*4+2], redmax[rloc*4+3]));
                float ps = 0.f;
                #pragma unroll
                for (int ni = 0; ni < 4; ni++)
                    #pragma unroll
                    for (int e = 0; e < 2; e++) {
                        float v = __expf(acc[mi][ni][half*2 + e] - rm);
                        acc[mi][ni][half*2 + e] = v;
                        ps += v;
                    }
                ps += __shfl_xor_sync(0xffffffffu, ps, 1);
                ps += __shfl_xor_sync(0xffffffffu, ps, 2);
                if (tq == 0) redsum[rloc*4 + w4] = ps;
            }
        __syncthreads();
        #pragma unroll
        for (int mi = 0; mi < 4; mi++)
            #pragma unroll
            for (int half = 0; half < 2; half++) {
                int rloc = wm0 + mi*16 + gq + half*8;
                float inv = 1.f / (redsum[rloc*4+0] + redsum[rloc*4+1]
                                 + redsum[rloc*4+2] + redsum[rloc*4+3]);
                long mg = m0 + rloc;
                #pragma unroll
                for (int ni = 0; ni < 4; ni++)
                    #pragma unroll
                    for (int e = 0; e < 2; e++) {
                        int ngc = n0 + wn0 + ni*8 + tq*2 + e;
                        Cq[mg*D_ + ngc] = __float2half(acc[mi][ni][half*2 + e] * inv);
                    }
            }
        return;
    }

    if (EPI == EPI_QKV) {
        __half* C = (sel == 1) ? C1 : C2;
        const float* bias = (sel == 1) ? b1 : b2;
        bool do_kadd = (sel == 1);
        #pragma unroll
        for (int mi = 0; mi < 4; mi++)
            #pragma unroll
            for (int half = 0; half < 2; half++) {
                int mg = m0 + wm0 + mi*16 + gq + half*8;
                float kadd = 0.f, vmul = 1.f;
                if (do_kadd) kadd = (1.0f - msk[mg]) * -1000000.0f;
                else         vmul = msk[mg];
                #pragma unroll
                for (int ni = 0; ni < 4; ni++) {
                    int ng = n0 + wn0 + ni*8 + tq*2;
                    #pragma unroll
                    for (int e = 0; e < 2; e++) {
                        float val = acc[mi][ni][half*2 + e] + bias[ng + e];
                        if (do_kadd) val += kadd; else val *= vmul;
                        C[(long)mg*D_ + ng + e] = __float2half(val);
                    }
                }
            }
        return;
    }

    #pragma unroll
    for (int mi = 0; mi < 4; mi++)
        #pragma unroll
        for (int half = 0; half < 2; half++) {
            int mg = m0 + wm0 + mi*16 + gq + half*8;
            #pragma unroll
            for (int ni = 0; ni < 4; ni++) {
                int ng = n0 + wn0 + ni*8 + tq*2;
                #pragma unroll
                for (int e = 0; e < 2; e++) {
                    float val = acc[mi][ni][half*2 + e] + b0[ng + e]
                              + resid[(long)mg*D_ + ng + e];
                    Cf[(long)mg*D_ + ng + e] = val;
                }
            }
        }
}

// ---------------- HMMA step 5: y = qh @ attT^T per (b,h), fp16 out ---------
__global__ void __launch_bounds__(256, 2)
attgemm_k(const __half* __restrict__ qh, const __half* __restrict__ attT,
          __half* __restrict__ y)
{
    extern __shared__ char smem[];
    uint32_t sb = smem_u32(smem);
    int tid = threadIdx.x, lane = tid & 31, wid = tid >> 5;
    int m0 = blockIdx.x * 128;
    int bh = blockIdx.y;
    int b = bh >> 3, h = bh & 7;
    const __half* A  = qh   + (long)b*T_*D_ + (long)m0*D_ + h*DH;
    const __half* Bm = attT + (long)bh*DH*DH;
    __half*       C  = y    + (long)b*T_*D_ + (long)m0*D_ + h*DH;
    int wm0 = (wid >> 2) * 64;
    int wn0 = (wid & 3) * 32;

    float acc[4][4][4];
    #pragma unroll
    for (int i = 0; i < 4; i++)
        #pragma unroll
        for (int j = 0; j < 4; j++)
            #pragma unroll
            for (int r = 0; r < 4; r++) acc[i][j][r] = 0.f;

    auto load_stage = [&](int s, int kc) {
        uint32_t st = sb + s * STGB;
        #pragma unroll
        for (int i = 0; i < 2; i++) {
            int g = tid + i * 256;
            int r = g >> 2, c = g & 3;
            cp16(st + r*ROWB + c*16,
                 (const char*)(A + (long)r * D_ + kc) + c*16);
            cp16(st + MATB + r*ROWB + c*16,
                 (const char*)(Bm + r * DH + kc) + c*16);
        }
        cp_commit();
    };

    load_stage(0, 0);
    load_stage(1, KC);
    const int nk = DH / KC;   // 4

    for (int ch = 0; ch < nk; ch++) {
        if (ch == nk - 1) cp_wait<0>(); else cp_wait<1>();
        __syncthreads();
        uint32_t st = sb + (ch & 1) * STGB;
        #pragma unroll
        for (int ks = 0; ks < 2; ks++) {
            uint32_t bh2[4][2];
            #pragma unroll
            for (int ni = 0; ni < 4; ni++) {
                int rB = wn0 + ni*8 + (lane & 7);
                int cB = ks*16 + ((lane >> 3) & 1) * 8;
                lds_x2(bh2[ni], st + MATB + (uint32_t)(rB*ROWB + cB*2));
            }
            #pragma unroll
            for (int mi = 0; mi < 4; mi++) {
                int rA = wm0 + mi*16 + (lane & 15);
                int cA = ks*16 + (lane >> 4) * 8;
                uint32_t ah[4];
                lds_x4(ah, st + (uint32_t)(rA*ROWB + cA*2));
                #pragma unroll
                for (int ni = 0; ni < 4; ni++)
                    mma16816(acc[mi][ni], ah, bh2[ni]);
            }
        }
        __syncthreads();
        if (ch + 2 < nk) load_stage(ch & 1, (ch + 2) * KC);
    }

    int gq = lane >> 2, tq = lane & 3;
    #pragma unroll
    for (int mi = 0; mi < 4; mi++)
        #pragma unroll
        for (int half = 0; half < 2; half++) {
            long mg = wm0 + mi*16 + gq + half*8;
            #pragma unroll
            for (int ni = 0; ni < 4; ni++) {
                int ng = wn0 + ni*8 + tq*2;
                __half2 hv = __floats2half2_rn(acc[mi][ni][half*2], acc[mi][ni][half*2+1]);
                *(__half2*)&C[mg*D_ + ng] = hv;
            }
        }
}

// ---------------- k softmax stats over time (k fp16) ----------------
__global__ void ksm_pass1(const __half* __restrict__ kq, float* __restrict__ gm,
                          float* __restrict__ gs)
{
    int d = blockIdx.x*256 + threadIdx.x;
    int b = blockIdx.y;
    int sp = blockIdx.z;
    const __half* p = kq + (long)b*T_*D_ + (long)sp*(T_/KTS)*D_ + d;
    float m = -1e30f, s = 0.f;
    for (int t = 0; t < T_/KTS; t++) {
        float vv = __half2float(p[(long)t*D_]);
        float nm = fmaxf(m, vv);
        s = s*__expf(m - nm) + __expf(vv - nm);
        m = nm;
    }
    int idx = (sp*B_ + b)*D_ + d;
    gm[idx] = m; gs[idx] = s;
}

__global__ void ksm_pass2(const float* __restrict__ gm, const float* __restrict__ gs,
                          float* __restrict__ cm, float* __restrict__ cs)
{
    int i = blockIdx.x*256 + threadIdx.x;
    float M = -1e30f;
    #pragma unroll
    for (int sp = 0; sp < KTS; sp++) M = fmaxf(M, gm[sp*B_*D_ + i]);
    float S = 0.f;
    #pragma unroll
    for (int sp = 0; sp < KTS; sp++) S += gs[sp*B_*D_ + i]*__expf(gm[sp*B_*D_ + i] - M);
    cm[i] = M; cs[i] = 1.f/S;
}

// ---------------- att = softmax(K)^T V per (b,h) on HMMA -------------------
// Stages kT [dk][t] (exp-normalized) and vT [dv][t] into smem (fp16, ROWB
// layout), then runs the standard m16n8k16 loop: A=kT, B=vT, K-dim = time.
#define ATBK 32
__global__ void __launch_bounds__(256, 2)
attpart_k(const __half* __restrict__ kq, const __half* __restrict__ vq,
          const float* __restrict__ cm, const float* __restrict__ cs,
          float* __restrict__ part)
{
    extern __shared__ char smem[];
    uint32_t sb = smem_u32(smem);
    int s  = blockIdx.x;
    int bh = blockIdx.y;
    int b = bh >> 3, h = bh & 7;
    int tid = threadIdx.x, lane = tid & 31, wid = tid >> 5;
    long base = (long)b*T_*D_ + h*DH;
    int t0 = s * (T_/SPLITS);
    int wm0 = (wid >> 2) * 64;
    int wn0 = (wid & 3) * 32;

    int d  = tid & 127;          // feature column handled by this thread
    int th = tid >> 7;           // 0/1: which 16-t half of the chunk

    float Md = cm[b*D_ + h*DH + d];
    float Id = cs[b*D_ + h*DH + d];

    __half kreg[16], vreg[16];
    auto load_regs = [&](int tt) {
        #pragma unroll
        for (int j = 0; j < 16; j++) {
            int t = th*16 + j;
            float kf = __half2float(kq[base + (long)(tt + t)*D_ + d]);
            kreg[j] = __float2half(__expf(kf - Md) * Id);
            vreg[j] = vq[base + (long)(tt + t)*D_ + d];
        }
    };
    auto store_smem = [&](int sidx) {
        char* st = smem + sidx*STGB;
        *(uint4*)(st + d*ROWB + th*32)        = *(uint4*)&kreg[0];
        *(uint4*)(st + d*ROWB + th*32 + 16)   = *(uint4*)&kreg[8];
        *(uint4*)(st + MATB + d*ROWB + th*32)      = *(uint4*)&vreg[0];
        *(uint4*)(st + MATB + d*ROWB + th*32 + 16) = *(uint4*)&vreg[8];
    };

    float acc[4][4][4];
    #pragma unroll
    for (int i = 0; i < 4; i++)
        #pragma unroll
        for (int j = 0; j < 4; j++)
            #pragma unroll
            for (int r = 0; r < 4; r++) acc[i][j][r] = 0.f;

    const int nch = (T_/SPLITS) / ATBK;    // 8
    load_regs(t0);
    store_smem(0);

    for (int ch = 0; ch < nch; ch++) {
        if (ch + 1 < nch) load_regs(t0 + (ch + 1)*ATBK);
        __syncthreads();                    // staging of buf ch&1 visible
        uint32_t st = sb + (ch & 1)*STGB;
        #pragma unroll
        for (int ks = 0; ks < 2; ks++) {
            uint32_t bh2[4][2];
            #pragma unroll
            for (int ni = 0; ni < 4; ni++) {
                int rB = wn0 + ni*8 + (lane & 7);
                int cB = ks*16 + ((lane >> 3) & 1) * 8;
                lds_x2(bh2[ni], st + MATB + (uint32_t)(rB*ROWB + cB*2));
            }
            #pragma unroll
            for (int mi = 0; mi < 4; mi++) {
                int rA = wm0 + mi*16 + (lane & 15);
                int cA = ks*16 + (lane >> 4) * 8;
                uint32_t ah[4];
                lds_x4(ah, st + (uint32_t)(rA*ROWB + cA*2));
                #pragma unroll
                for (int ni = 0; ni < 4; ni++)
                    mma16816(acc[mi][ni], ah, bh2[ni]);
            }
        }
        if (ch + 1 < nch) store_smem((ch + 1) & 1);   // other buffer; prior readers done pre-sync
    }

    float* P = part + ((long)s*(B_*H_) + bh)*(DH*DH);
    int gq = lane >> 2, tq = lane & 3;
    #pragma unroll
    for (int mi = 0; mi < 4; mi++)
        #pragma unroll
        for (int half = 0; half < 2; half++) {
            int ml = wm0 + mi*16 + gq + half*8;     // dk
            #pragma unroll
            for (int ni = 0; ni < 4; ni++) {
                int nl = wn0 + ni*8 + tq*2;         // dv
                P[ml*DH + nl]   = acc[mi][ni][half*2];
                P[ml*DH + nl+1] = acc[mi][ni][half*2+1];
            }
        }
}

// reduce partials -> transposed fp16 att
__global__ void attreduce_k(const float* __restrict__ part, __half* __restrict__ attT)
{
    int i = blockIdx.x*256 + threadIdx.x;
    float s = 0.f;
    #pragma unroll
    for (int sp = 0; sp < SPLITS; sp++)
        s += part[(long)sp*(B_*H_*DH*DH) + i];
    int bh = i >> 14;
    int rem = i & 16383;
    int d = rem >> 7, l = rem & 127;
    attT[((long)bh << 14) + l*DH + d] = __float2half(s);
}

// ---------------- FiLM ----------------
__global__ void filmpart_k(const float* __restrict__ emb, const float* __restrict__ W,
                           float* __restrict__ part)
{
    int b = blockIdx.x;
    int colBase = blockIdx.y*256;
    int kz = blockIdx.z;
    __shared__ float se[256];
    int tid = threadIdx.x;
    float e = emb[(long)b*TE_ + kz*256 + tid];
    se[tid] = silu_f(e);
    __syncthreads();
    int col = colBase + tid;
    float acc = 0.f;
    const float* wp = W + (long)(kz*256)*D2 + col;
    #pragma unroll 8
    for (int k = 0; k < 256; k++) acc += se[k]*wp[(long)k*D2];
    part[((long)kz*B_ + b)*D2 + col] = acc;
}

__global__ void filmreduce_k(const float* __restrict__ part,
                             const float* __restrict__ b_emb,
                             float* __restrict__ film)
{
    int i = blockIdx.x*256 + threadIdx.x;
    int col = i & (D2-1);
    int b = i >> 11;
    float s = b_emb[col];
    #pragma unroll
    for (int kz = 0; kz < FKS; kz++)
        s += part[((long)kz*B_ + b)*D2 + col];
    film[i] = s;
}

// ---------------- launch ----------------
extern "C" void kernel_launch(void* const* d_in, const int* in_sizes, int n_in,
                              void* d_out, int out_size)
{
    const float* x     = (const float*)d_in[0];
    const float* emb   = (const float*)d_in[1];
    const float* mask  = (const float*)d_in[2];
    const float* ln_w  = (const float*)d_in[4];
    const float* ln_b  = (const float*)d_in[5];
    const float* Wq    = (const float*)d_in[6];
    const float* bq    = (const float*)d_in[7];
    const float* Wk    = (const float*)d_in[8];
    const float* bk    = (const float*)d_in[9];
    const float* Wv    = (const float*)d_in[10];
    const float* bv    = (const float*)d_in[11];
    const float* W_emb = (const float*)d_in[12];
    const float* b_emb = (const float*)d_in[13];
    const float* ln2_w = (const float*)d_in[14];
    const float* ln2_b = (const float*)d_in[15];
    const float* W_out = (const float*)d_in[16];
    const float* b_out = (const float*)d_in[17];
    float* out = (float*)d_out;

    float *attp, *filmp, *film, *gm, *gs, *cm, *cs;
    __half *qh, *kh, *vh, *yh, *xh, *wh, *attT;
    cudaGetSymbolAddress((void**)&qh,   g_qh);
    cudaGetSymbolAddress((void**)&kh,   g_kh);
    cudaGetSymbolAddress((void**)&vh,   g_vh);
    cudaGetSymbolAddress((void**)&yh,   g_yh);
    cudaGetSymbolAddress((void**)&xh,   g_xh);
    cudaGetSymbolAddress((void**)&wh,   g_wh);
    cudaGetSymbolAddress((void**)&attp, g_attp);
    cudaGetSymbolAddress((void**)&attT, g_attT);
    cudaGetSymbolAddress((void**)&filmp,g_filmp);
    cudaGetSymbolAddress((void**)&film, g_film);
    cudaGetSymbolAddress((void**)&gm,   g_gm);
    cudaGetSymbolAddress((void**)&gs,   g_gs);
    cudaGetSymbolAddress((void**)&cm,   g_cm);
    cudaGetSymbolAddress((void**)&cs,   g_cs);

    cudaFuncSetAttribute(hgemm_k<EPI_QKV>,   cudaFuncAttributeMaxDynamicSharedMemorySize, SMEM_HGEMM);
    cudaFuncSetAttribute(hgemm_k<EPI_RESID>, cudaFuncAttributeMaxDynamicSharedMemorySize, SMEM_HGEMM);
    cudaFuncSetAttribute(attgemm_k,          cudaFuncAttributeMaxDynamicSharedMemorySize, SMEM_ATTG);
    cudaFuncSetAttribute(attpart_k,          cudaFuncAttributeMaxDynamicSharedMemorySize, SMEM_ATTG);

    // 1) pre-norm -> fp16
    ln_k<<<NROWS, 256>>>(x, ln_w, ln_b, xh);

    // weights: transpose -> fp16 concat [4N, K] in ONE launch (W_out hoisted)
    wconv4_k<<<dim3(32, 32, 4), dim3(32, 8)>>>(Wq, Wk, Wv, W_out, wh);

    // 2) fused Q/K/V projection; q-softmax fused, all outputs fp16
    hgemm_k<EPI_QKV><<<dim3(24, NROWS/128), 256, SMEM_HGEMM>>>(
        xh, wh, qh, kh, vh, bq, bk, bv, mask, nullptr, nullptr);

    // 3) k-softmax stats (normalization fused into attpart)
    ksm_pass1<<<dim3(D_/256, B_, KTS), 256>>>(kh, gm, gs);
    ksm_pass2<<<(B_*D_)/256, 256>>>(gm, gs, cm, cs);

    // 4) att = softmax(K)^T V per (b,h) on HMMA; reduce -> transposed fp16
    attpart_k<<<dim3(SPLITS, B_*H_), 256, SMEM_ATTG>>>(kh, vh, cm, cs, attp);
    attreduce_k<<<(B_*H_*DH*DH)/256, 256>>>(attp, attT);

    // 5) y = q @ att per (b,h) on HMMA, fp16 out
    attgemm_k<<<dim3(T_/128, B_*H_), 256, SMEM_ATTG>>>(qh, attT, yh);

    // 6) FiLM params
    filmpart_k<<<dim3(B_, D2/256, FKS), 256>>>(emb, W_emb, filmp);
    filmreduce_k<<<(B_*D2)/256, 256>>>(filmp, b_emb, film);

    // 7) LN2 + FiLM + SiLU -> fp16 (reuse xh)
    ln2film_k<<<NROWS, 256>>>(yh, ln2_w, ln2_b, film, xh);

    // 8) out = x + hh @ W_out + b_out  (weight slice 3, pre-converted)
    hgemm_k<EPI_RESID><<<dim3(8, NROWS/128), 256, SMEM_HGEMM>>>(
        xh, wh + (long)3*D_*D_, nullptr, nullptr, nullptr, b_out,
        nullptr, nullptr, nullptr, x, out);
}